// round 1
// baseline (speedup 1.0000x reference)
#include <cuda_runtime.h>
#include <cstdint>

#define SEQ 4096
#define HID 2048
#define NHEADS 16
#define HD 128

// ---------------- scratch (static device arrays; no allocation) ----------------
static __device__ float g_Xr[SEQ * HID];
static __device__ float g_Wqr[HID * HID];
static __device__ float g_Wkr[HID * HID];
static __device__ float g_Wvr[HID * HID];
static __device__ float g_Wor[HID * HID];
static __device__ float g_Q[SEQ * HID];
static __device__ float g_K[SEQ * HID];
static __device__ float g_V[SEQ * HID];
static __device__ float g_ctx[SEQ * HID];
static __device__ float g_cos[SEQ * 64];
static __device__ float g_sin[SEQ * 64];

// ---------------- helpers ----------------
__device__ __forceinline__ uint32_t f2tf(float x) {
    uint32_t r;
    asm("cvt.rna.tf32.f32 %0, %1;" : "=r"(r) : "f"(x));
    return r;
}
__device__ __forceinline__ float rtf(float x) { return __uint_as_float(f2tf(x)); }

__device__ __forceinline__ void mma_tf32(float* c, const uint32_t* a, uint32_t b0, uint32_t b1) {
    asm volatile(
        "mma.sync.aligned.m16n8k8.row.col.f32.tf32.tf32.f32 "
        "{%0,%1,%2,%3}, {%4,%5,%6,%7}, {%8,%9}, {%0,%1,%2,%3};"
        : "+f"(c[0]), "+f"(c[1]), "+f"(c[2]), "+f"(c[3])
        : "r"(a[0]), "r"(a[1]), "r"(a[2]), "r"(a[3]), "r"(b0), "r"(b1));
}

// ---------------- prep: tf32-round inputs into scratch ----------------
__global__ void round_kernel(const float* __restrict__ in, int sel, int n4) {
    int i = blockIdx.x * blockDim.x + threadIdx.x;
    if (i >= n4) return;
    float* dst = (sel == 0) ? g_Xr : (sel == 1) ? g_Wqr : (sel == 2) ? g_Wkr
               : (sel == 3) ? g_Wvr : g_Wor;
    float4 v = reinterpret_cast<const float4*>(in)[i];
    float4 o;
    o.x = rtf(v.x); o.y = rtf(v.y); o.z = rtf(v.z); o.w = rtf(v.w);
    reinterpret_cast<float4*>(dst)[i] = o;
}

// ---------------- RoPE tables (double precision of the fp32-rounded angle,
// matching the reference's fp32 pos*inv_freq argument) ----------------
__global__ void rope_table() {
    int idx = blockIdx.x * blockDim.x + threadIdx.x;
    if (idx >= SEQ * 64) return;
    int s = idx >> 6, j = idx & 63;
    double invf = exp(-(double)j * (9.210340371976184 / 64.0));  // 10000^(-j/64)
    float freq = (float)s * (float)invf;                          // fp32, like the ref
    g_cos[idx] = (float)cos((double)freq);
    g_sin[idx] = (float)sin((double)freq);
}

__global__ void rope_apply() {
    int idx = blockIdx.x * blockDim.x + threadIdx.x;
    if (idx >= SEQ * NHEADS * 64) return;
    int s = idx >> 10;
    int h = (idx >> 6) & (NHEADS - 1);
    int i = idx & 63;
    float c = g_cos[(s << 6) + i], sn = g_sin[(s << 6) + i];
    int base = s * HID + h * HD + i;
    float q1 = g_Q[base], q2 = g_Q[base + 64];
    g_Q[base]      = rtf(q1 * c - q2 * sn);
    g_Q[base + 64] = rtf(q2 * c + q1 * sn);
    float k1 = g_K[base], k2 = g_K[base + 64];
    g_K[base]      = rtf(k1 * c - k2 * sn);
    g_K[base + 64] = rtf(k2 * c + k1 * sn);
}

// ---------------- GEMM: C[M,N] = A[M,K] @ B[N,K]^T (both K-major), tf32 mma ----
#define GBM 128
#define GBN 128
#define GBK 16

__global__ void __launch_bounds__(256) gemm_tn(int sel, float* __restrict__ extC) {
    const float* A; const float* B; float* C; int roundOut = 0;
    const int M = SEQ, N = HID, K = HID;
    if (sel == 0)      { A = g_Xr;  B = g_Wqr; C = g_Q; }
    else if (sel == 1) { A = g_Xr;  B = g_Wkr; C = g_K; }
    else if (sel == 2) { A = g_Xr;  B = g_Wvr; C = g_V; roundOut = 1; }
    else               { A = g_ctx; B = g_Wor; C = extC; }
    (void)M;

    __shared__ float As[2][GBM][GBK + 4];
    __shared__ float Bs[2][GBN][GBK + 4];

    int tid = threadIdx.x;
    int lane = tid & 31, wid = tid >> 5;
    int wm = wid & 3, wn = wid >> 2;
    int bm = blockIdx.y * GBM, bn = blockIdx.x * GBN;

    float c[2][8][4];
#pragma unroll
    for (int im = 0; im < 2; im++)
#pragma unroll
        for (int jn = 0; jn < 8; jn++)
#pragma unroll
            for (int q = 0; q < 4; q++) c[im][jn][q] = 0.f;

    const float* Abase = A + (size_t)bm * K;
    const float* Bbase = B + (size_t)bn * K;

    // each thread loads two float4 for A tile and two for B tile
    int ar0 = tid >> 2,        ac0 = (tid & 3) << 2;
    int ar1 = (tid + 256) >> 2, ac1 = ((tid + 256) & 3) << 2;

    auto load_tile = [&](int buf, int kt) {
        int koff = kt * GBK;
        uint32_t s0 = (uint32_t)__cvta_generic_to_shared(&As[buf][ar0][ac0]);
        asm volatile("cp.async.ca.shared.global [%0], [%1], 16;" :: "r"(s0),
                     "l"(Abase + (size_t)ar0 * K + koff + ac0));
        uint32_t s1 = (uint32_t)__cvta_generic_to_shared(&As[buf][ar1][ac1]);
        asm volatile("cp.async.ca.shared.global [%0], [%1], 16;" :: "r"(s1),
                     "l"(Abase + (size_t)ar1 * K + koff + ac1));
        uint32_t s2 = (uint32_t)__cvta_generic_to_shared(&Bs[buf][ar0][ac0]);
        asm volatile("cp.async.ca.shared.global [%0], [%1], 16;" :: "r"(s2),
                     "l"(Bbase + (size_t)ar0 * K + koff + ac0));
        uint32_t s3 = (uint32_t)__cvta_generic_to_shared(&Bs[buf][ar1][ac1]);
        asm volatile("cp.async.ca.shared.global [%0], [%1], 16;" :: "r"(s3),
                     "l"(Bbase + (size_t)ar1 * K + koff + ac1));
    };

    load_tile(0, 0);
    asm volatile("cp.async.commit_group;");
    const int NT = K / GBK;

    int g = lane >> 2, t = lane & 3;

    for (int kt = 0; kt < NT; kt++) {
        asm volatile("cp.async.wait_group 0;" ::: "memory");
        __syncthreads();
        int buf = kt & 1;
        if (kt + 1 < NT) {
            load_tile(buf ^ 1, kt + 1);
            asm volatile("cp.async.commit_group;");
        }
#pragma unroll
        for (int ks = 0; ks < 2; ks++) {
            int k0 = ks * 8;
            uint32_t a[2][4], b[8][2];
#pragma unroll
            for (int im = 0; im < 2; im++) {
                int r = wm * 32 + im * 16 + g;
                a[im][0] = __float_as_uint(As[buf][r][k0 + t]);
                a[im][1] = __float_as_uint(As[buf][r + 8][k0 + t]);
                a[im][2] = __float_as_uint(As[buf][r][k0 + t + 4]);
                a[im][3] = __float_as_uint(As[buf][r + 8][k0 + t + 4]);
            }
#pragma unroll
            for (int jn = 0; jn < 8; jn++) {
                int cc = wn * 64 + jn * 8 + g;
                b[jn][0] = __float_as_uint(Bs[buf][cc][k0 + t]);
                b[jn][1] = __float_as_uint(Bs[buf][cc][k0 + t + 4]);
            }
#pragma unroll
            for (int im = 0; im < 2; im++)
#pragma unroll
                for (int jn = 0; jn < 8; jn++)
                    mma_tf32(c[im][jn], a[im], b[jn][0], b[jn][1]);
        }
    }

#pragma unroll
    for (int im = 0; im < 2; im++) {
#pragma unroll
        for (int jn = 0; jn < 8; jn++) {
            int r = bm + wm * 32 + im * 16 + g;
            int col = bn + wn * 64 + jn * 8 + 2 * t;
            float v0 = c[im][jn][0], v1 = c[im][jn][1];
            float v2 = c[im][jn][2], v3 = c[im][jn][3];
            if (roundOut) { v0 = rtf(v0); v1 = rtf(v1); v2 = rtf(v2); v3 = rtf(v3); }
            *reinterpret_cast<float2*>(&C[(size_t)r * N + col])       = make_float2(v0, v1);
            *reinterpret_cast<float2*>(&C[(size_t)(r + 8) * N + col]) = make_float2(v2, v3);
        }
    }
}

// ---------------- flash attention (causal), tf32 mma ----------------
#define ABM 64
#define ABN 32

__global__ void __launch_bounds__(128) attn_kernel(float scale) {
    __shared__ float KVs[ABN][136];  // K tile then V tile, [key][dim]
    __shared__ float Ps[ABM][36];    // probs tile, [row][key_local]

    int tid = threadIdx.x, lane = tid & 31, wid = tid >> 5;
    int g = lane >> 2, t = lane & 3;
    int qt = blockIdx.x, h = blockIdx.y;
    int hoff = h * HD;
    int qrow = qt * ABM + wid * 16;
    int row0 = qrow + g, row1 = row0 + 8;
    int rl0 = wid * 16 + g, rl1 = rl0 + 8;

    // Q A-fragments in registers (pre-rounded tf32 from rope_apply)
    uint32_t qf[16][4];
#pragma unroll
    for (int k8 = 0; k8 < 16; k8++) {
        int cb = hoff + k8 * 8 + t;
        qf[k8][0] = __float_as_uint(g_Q[row0 * HID + cb]);
        qf[k8][1] = __float_as_uint(g_Q[row1 * HID + cb]);
        qf[k8][2] = __float_as_uint(g_Q[row0 * HID + cb + 4]);
        qf[k8][3] = __float_as_uint(g_Q[row1 * HID + cb + 4]);
    }

    float of[16][4];
#pragma unroll
    for (int j = 0; j < 16; j++) { of[j][0] = 0.f; of[j][1] = 0.f; of[j][2] = 0.f; of[j][3] = 0.f; }
    float m0 = -1e30f, m1 = -1e30f, l0 = 0.f, l1 = 0.f;

    int ktmax = 2 * qt + 1;
    for (int kt = 0; kt <= ktmax; kt++) {
        __syncthreads();
        {   // load K tile
            const float* Kg = g_K + (size_t)(kt * ABN) * HID + hoff;
            for (int i = tid; i < ABN * 32; i += 128) {
                int rr = i >> 5, c4 = (i & 31) << 2;
                *reinterpret_cast<float4*>(&KVs[rr][c4]) =
                    *reinterpret_cast<const float4*>(Kg + (size_t)rr * HID + c4);
            }
        }
        __syncthreads();

        // scores: Q (64x128) @ K^T (128x32), per-warp 16x32
        float sf[4][4];
#pragma unroll
        for (int j = 0; j < 4; j++) { sf[j][0] = 0.f; sf[j][1] = 0.f; sf[j][2] = 0.f; sf[j][3] = 0.f; }
#pragma unroll
        for (int k8 = 0; k8 < 16; k8++) {
#pragma unroll
            for (int j = 0; j < 4; j++) {
                uint32_t b0 = __float_as_uint(KVs[j * 8 + g][k8 * 8 + t]);
                uint32_t b1 = __float_as_uint(KVs[j * 8 + g][k8 * 8 + t + 4]);
                mma_tf32(sf[j], qf[k8], b0, b1);
            }
        }

        // scale + causal mask + row max
        float mx0 = -1e30f, mx1 = -1e30f;
#pragma unroll
        for (int j = 0; j < 4; j++) {
            int cg = kt * ABN + j * 8 + 2 * t;
            sf[j][0] = (cg     <= row0) ? sf[j][0] * scale : -1e30f;
            sf[j][1] = (cg + 1 <= row0) ? sf[j][1] * scale : -1e30f;
            sf[j][2] = (cg     <= row1) ? sf[j][2] * scale : -1e30f;
            sf[j][3] = (cg + 1 <= row1) ? sf[j][3] * scale : -1e30f;
            mx0 = fmaxf(mx0, fmaxf(sf[j][0], sf[j][1]));
            mx1 = fmaxf(mx1, fmaxf(sf[j][2], sf[j][3]));
        }
        mx0 = fmaxf(mx0, __shfl_xor_sync(0xffffffffu, mx0, 1));
        mx0 = fmaxf(mx0, __shfl_xor_sync(0xffffffffu, mx0, 2));
        mx1 = fmaxf(mx1, __shfl_xor_sync(0xffffffffu, mx1, 1));
        mx1 = fmaxf(mx1, __shfl_xor_sync(0xffffffffu, mx1, 2));

        float mn0 = fmaxf(m0, mx0), mn1 = fmaxf(m1, mx1);
        float al0 = __expf(m0 - mn0), al1 = __expf(m1 - mn1);

        float rs0 = 0.f, rs1 = 0.f;
#pragma unroll
        for (int j = 0; j < 4; j++) {
            float p0 = __expf(sf[j][0] - mn0);
            float p1 = __expf(sf[j][1] - mn0);
            float p2 = __expf(sf[j][2] - mn1);
            float p3 = __expf(sf[j][3] - mn1);
            rs0 += p0 + p1; rs1 += p2 + p3;
            int cl = j * 8 + 2 * t;
            *reinterpret_cast<float2*>(&Ps[rl0][cl]) = make_float2(rtf(p0), rtf(p1));
            *reinterpret_cast<float2*>(&Ps[rl1][cl]) = make_float2(rtf(p2), rtf(p3));
        }
        rs0 += __shfl_xor_sync(0xffffffffu, rs0, 1);
        rs0 += __shfl_xor_sync(0xffffffffu, rs0, 2);
        rs1 += __shfl_xor_sync(0xffffffffu, rs1, 1);
        rs1 += __shfl_xor_sync(0xffffffffu, rs1, 2);
        l0 = l0 * al0 + rs0;
        l1 = l1 * al1 + rs1;
        m0 = mn0; m1 = mn1;
#pragma unroll
        for (int j = 0; j < 16; j++) {
            of[j][0] *= al0; of[j][1] *= al0; of[j][2] *= al1; of[j][3] *= al1;
        }

        __syncthreads();  // all warps done reading K tile
        {   // load V tile into the same buffer
            const float* Vg = g_V + (size_t)(kt * ABN) * HID + hoff;
            for (int i = tid; i < ABN * 32; i += 128) {
                int rr = i >> 5, c4 = (i & 31) << 2;
                *reinterpret_cast<float4*>(&KVs[rr][c4]) =
                    *reinterpret_cast<const float4*>(Vg + (size_t)rr * HID + c4);
            }
        }
        __syncthreads();

        // PV: P (64x32) @ V (32x128)
#pragma unroll
        for (int k8 = 0; k8 < 4; k8++) {
            uint32_t a[4];
            a[0] = __float_as_uint(Ps[rl0][k8 * 8 + t]);
            a[1] = __float_as_uint(Ps[rl1][k8 * 8 + t]);
            a[2] = __float_as_uint(Ps[rl0][k8 * 8 + t + 4]);
            a[3] = __float_as_uint(Ps[rl1][k8 * 8 + t + 4]);
#pragma unroll
            for (int j = 0; j < 16; j++) {
                uint32_t b0 = __float_as_uint(KVs[k8 * 8 + t][j * 8 + g]);
                uint32_t b1 = __float_as_uint(KVs[k8 * 8 + t + 4][j * 8 + g]);
                mma_tf32(of[j], a, b0, b1);
            }
        }
    }

    float inv0 = 1.f / l0, inv1 = 1.f / l1;
#pragma unroll
    for (int j = 0; j < 16; j++) {
        int col = hoff + j * 8 + 2 * t;
        *reinterpret_cast<float2*>(&g_ctx[(size_t)row0 * HID + col]) =
            make_float2(rtf(of[j][0] * inv0), rtf(of[j][1] * inv0));
        *reinterpret_cast<float2*>(&g_ctx[(size_t)row1 * HID + col]) =
            make_float2(rtf(of[j][2] * inv1), rtf(of[j][3] * inv1));
    }
}

// ---------------- launch ----------------
extern "C" void kernel_launch(void* const* d_in, const int* in_sizes, int n_in,
                              void* d_out, int out_size) {
    const float* X  = (const float*)d_in[0];
    const float* Wq = (const float*)d_in[1];
    const float* Wk = (const float*)d_in[2];
    const float* Wv = (const float*)d_in[3];
    const float* Wo = (const float*)d_in[4];
    float* out = (float*)d_out;

    round_kernel<<<(SEQ * HID / 4) / 256, 256>>>(X, 0, SEQ * HID / 4);
    round_kernel<<<(HID * HID / 4) / 256, 256>>>(Wq, 1, HID * HID / 4);
    round_kernel<<<(HID * HID / 4) / 256, 256>>>(Wk, 2, HID * HID / 4);
    round_kernel<<<(HID * HID / 4) / 256, 256>>>(Wv, 3, HID * HID / 4);
    round_kernel<<<(HID * HID / 4) / 256, 256>>>(Wo, 4, HID * HID / 4);
    rope_table<<<(SEQ * 64) / 256, 256>>>();

    dim3 gg(HID / GBN, SEQ / GBM);
    gemm_tn<<<gg, 256>>>(0, nullptr);  // Q = Xr @ Wq^T
    gemm_tn<<<gg, 256>>>(1, nullptr);  // K = Xr @ Wk^T
    gemm_tn<<<gg, 256>>>(2, nullptr);  // V = Xr @ Wv^T (tf32-rounded)
    rope_apply<<<(SEQ * NHEADS * 64) / 256, 256>>>();

    attn_kernel<<<dim3(SEQ / ABM, NHEADS), 128>>>(0.08838834764831845f);

    gemm_tn<<<gg, 256>>>(3, out);      // out = ctx @ Wo^T
}

// round 3
// speedup vs baseline: 1.2298x; 1.2298x over previous
#include <cuda_runtime.h>
#include <cstdint>

#define SEQ 4096
#define HID 2048
#define NHEADS 16
#define HD 128

// ---------------- scratch (static device arrays; no allocation) ----------------
static __device__ float g_Xr[SEQ * HID];
static __device__ float g_Wqr[HID * HID];
static __device__ float g_Wkr[HID * HID];
static __device__ float g_Wvr[HID * HID];
static __device__ float g_Wor[HID * HID];
static __device__ float g_Q[SEQ * HID];
static __device__ float g_K[SEQ * HID];
static __device__ float g_V[SEQ * HID];
static __device__ float g_ctx[SEQ * HID];
static __device__ float g_cos[SEQ * 64];
static __device__ float g_sin[SEQ * 64];

// ---------------- helpers ----------------
__device__ __forceinline__ uint32_t f2tf(float x) {
    uint32_t r;
    asm("cvt.rna.tf32.f32 %0, %1;" : "=r"(r) : "f"(x));
    return r;
}
__device__ __forceinline__ float rtf(float x) { return __uint_as_float(f2tf(x)); }

__device__ __forceinline__ void mma_tf32(float* c, const uint32_t* a, uint32_t b0, uint32_t b1) {
    asm volatile(
        "mma.sync.aligned.m16n8k8.row.col.f32.tf32.tf32.f32 "
        "{%0,%1,%2,%3}, {%4,%5,%6,%7}, {%8,%9}, {%0,%1,%2,%3};"
        : "+f"(c[0]), "+f"(c[1]), "+f"(c[2]), "+f"(c[3])
        : "r"(a[0]), "r"(a[1]), "r"(a[2]), "r"(a[3]), "r"(b0), "r"(b1));
}

__device__ __forceinline__ void cpasync16(uint32_t dst, const void* src) {
    asm volatile("cp.async.cg.shared.global [%0], [%1], 16;" :: "r"(dst), "l"(src));
}
__device__ __forceinline__ void cpcommit() { asm volatile("cp.async.commit_group;"); }

// ---------------- prep: tf32-round inputs into scratch ----------------
__global__ void round_kernel(const float* __restrict__ in, int sel, int n4) {
    int i = blockIdx.x * blockDim.x + threadIdx.x;
    if (i >= n4) return;
    float* dst = (sel == 0) ? g_Xr : (sel == 1) ? g_Wqr : (sel == 2) ? g_Wkr
               : (sel == 3) ? g_Wvr : g_Wor;
    float4 v = reinterpret_cast<const float4*>(in)[i];
    float4 o;
    o.x = rtf(v.x); o.y = rtf(v.y); o.z = rtf(v.z); o.w = rtf(v.w);
    reinterpret_cast<float4*>(dst)[i] = o;
}

// ---------------- RoPE ----------------
__global__ void rope_table() {
    int idx = blockIdx.x * blockDim.x + threadIdx.x;
    if (idx >= SEQ * 64) return;
    int s = idx >> 6, j = idx & 63;
    double invf = exp(-(double)j * (9.210340371976184 / 64.0));  // 10000^(-j/64)
    float freq = (float)s * (float)invf;                          // fp32, like the ref
    g_cos[idx] = (float)cos((double)freq);
    g_sin[idx] = (float)sin((double)freq);
}

__global__ void rope_apply() {
    int idx = blockIdx.x * blockDim.x + threadIdx.x;
    if (idx >= SEQ * NHEADS * 64) return;
    int s = idx >> 10;
    int h = (idx >> 6) & (NHEADS - 1);
    int i = idx & 63;
    float c = g_cos[(s << 6) + i], sn = g_sin[(s << 6) + i];
    int base = s * HID + h * HD + i;
    float q1 = g_Q[base], q2 = g_Q[base + 64];
    g_Q[base]      = rtf(q1 * c - q2 * sn);
    g_Q[base + 64] = rtf(q2 * c + q1 * sn);
    float k1 = g_K[base], k2 = g_K[base + 64];
    g_K[base]      = rtf(k1 * c - k2 * sn);
    g_K[base + 64] = rtf(k2 * c + k1 * sn);
}

// ---------------- GEMM: C[M,N] = A[M,K] @ B[N,K]^T, 4-stage cp.async ----------
#define GBM 128
#define GBN 128
#define GBK 16
#define GST 4
#define APITCH 20
#define AS_FLOATS (GBM * APITCH)        // 2560
#define STG_FLOATS (2 * AS_FLOATS)      // 5120
#define GEMM_SMEM (GST * STG_FLOATS * 4)  // 81920 B

__global__ void __launch_bounds__(256, 1) gemm_tn(int sel, float* __restrict__ extC) {
    extern __shared__ float sm[];
    const float* A; const float* B; float* C; int roundOut = 0;
    const int N = HID, K = HID;
    if (sel == 0)      { A = g_Xr;  B = g_Wqr; C = g_Q; }
    else if (sel == 1) { A = g_Xr;  B = g_Wkr; C = g_K; }
    else if (sel == 2) { A = g_Xr;  B = g_Wvr; C = g_V; roundOut = 1; }
    else               { A = g_ctx; B = g_Wor; C = extC; }

    int tid = threadIdx.x;
    int lane = tid & 31, wid = tid >> 5;
    int wm = wid & 3, wn = wid >> 2;
    int bm = blockIdx.y * GBM, bn = blockIdx.x * GBN;

    float c[2][8][4];
#pragma unroll
    for (int im = 0; im < 2; im++)
#pragma unroll
        for (int jn = 0; jn < 8; jn++)
#pragma unroll
            for (int q = 0; q < 4; q++) c[im][jn][q] = 0.f;

    const float* Abase = A + (size_t)bm * K;
    const float* Bbase = B + (size_t)bn * K;

    uint32_t smb = (uint32_t)__cvta_generic_to_shared(sm);

    // per-thread load coords: two float4 for A, two for B
    int ar0 = tid >> 2,        ac0 = (tid & 3) << 2;
    int ar1 = ar0 + 64,        ac1 = ac0;

    auto load_tile = [&](int s, int kt) {
        int koff = kt * GBK;
        uint32_t sa = smb + (uint32_t)(s * STG_FLOATS) * 4;
        uint32_t sb = sa + AS_FLOATS * 4;
        cpasync16(sa + (uint32_t)(ar0 * APITCH + ac0) * 4, Abase + (size_t)ar0 * K + koff + ac0);
        cpasync16(sa + (uint32_t)(ar1 * APITCH + ac1) * 4, Abase + (size_t)ar1 * K + koff + ac1);
        cpasync16(sb + (uint32_t)(ar0 * APITCH + ac0) * 4, Bbase + (size_t)ar0 * K + koff + ac0);
        cpasync16(sb + (uint32_t)(ar1 * APITCH + ac1) * 4, Bbase + (size_t)ar1 * K + koff + ac1);
    };

    const int NT = K / GBK;  // 128
#pragma unroll
    for (int s = 0; s < GST - 1; s++) { load_tile(s, s); cpcommit(); }

    int g = lane >> 2, t = lane & 3;

    for (int kt = 0; kt < NT; kt++) {
        if (kt + GST - 1 < NT) {
            __syncthreads();  // all warps done with stage (kt-1)%GST == (kt+3)%GST
            load_tile((kt + GST - 1) & (GST - 1), kt + GST - 1);
            cpcommit();
            asm volatile("cp.async.wait_group %0;" :: "n"(GST - 1) : "memory");
        } else {
            asm volatile("cp.async.wait_group 0;" ::: "memory");
        }
        __syncthreads();

        const float* As = sm + (kt & (GST - 1)) * STG_FLOATS;
        const float* Bs = As + AS_FLOATS;
#pragma unroll
        for (int ks = 0; ks < 2; ks++) {
            int k0 = ks * 8;
            uint32_t a[2][4], b[8][2];
#pragma unroll
            for (int im = 0; im < 2; im++) {
                int r = wm * 32 + im * 16 + g;
                a[im][0] = __float_as_uint(As[r * APITCH + k0 + t]);
                a[im][1] = __float_as_uint(As[(r + 8) * APITCH + k0 + t]);
                a[im][2] = __float_as_uint(As[r * APITCH + k0 + t + 4]);
                a[im][3] = __float_as_uint(As[(r + 8) * APITCH + k0 + t + 4]);
            }
#pragma unroll
            for (int jn = 0; jn < 8; jn++) {
                int cc = wn * 64 + jn * 8 + g;
                b[jn][0] = __float_as_uint(Bs[cc * APITCH + k0 + t]);
                b[jn][1] = __float_as_uint(Bs[cc * APITCH + k0 + t + 4]);
            }
#pragma unroll
            for (int im = 0; im < 2; im++)
#pragma unroll
                for (int jn = 0; jn < 8; jn++)
                    mma_tf32(c[im][jn], a[im], b[jn][0], b[jn][1]);
        }
    }

#pragma unroll
    for (int im = 0; im < 2; im++) {
#pragma unroll
        for (int jn = 0; jn < 8; jn++) {
            int r = bm + wm * 32 + im * 16 + g;
            int col = bn + wn * 64 + jn * 8 + 2 * t;
            float v0 = c[im][jn][0], v1 = c[im][jn][1];
            float v2 = c[im][jn][2], v3 = c[im][jn][3];
            if (roundOut) { v0 = rtf(v0); v1 = rtf(v1); v2 = rtf(v2); v3 = rtf(v3); }
            *reinterpret_cast<float2*>(&C[(size_t)r * N + col])       = make_float2(v0, v1);
            *reinterpret_cast<float2*>(&C[(size_t)(r + 8) * N + col]) = make_float2(v2, v3);
        }
    }
}

// ---------------- flash attention (causal), double-buffered cp.async ----------
#define ABM 64
#define ABN 32
#define KVPITCH 136
#define KVSTG (ABN * KVPITCH)            // 4352 floats per stage
#define ATT_SMEM (4 * KVSTG * 4)         // K[2] + V[2] = 69632 B dynamic

__global__ void __launch_bounds__(128) attn_kernel(float scale) {
    extern __shared__ float kvdyn[];     // [K0, K1, V0, V1]
    __shared__ float Ps[ABM][36];        // probs, warp-local rows

    int tid = threadIdx.x, lane = tid & 31, wid = tid >> 5;
    int g = lane >> 2, t = lane & 3;
    int qt = blockIdx.x, h = blockIdx.y;
    int hoff = h * HD;
    int qrow = qt * ABM + wid * 16;
    int row0 = qrow + g, row1 = row0 + 8;
    int rl0 = wid * 16 + g, rl1 = rl0 + 8;

    uint32_t dynb = (uint32_t)__cvta_generic_to_shared(kvdyn);

    // Q A-fragments in registers (pre-rounded tf32 from rope_apply)
    uint32_t qf[16][4];
#pragma unroll
    for (int k8 = 0; k8 < 16; k8++) {
        int cb = hoff + k8 * 8 + t;
        qf[k8][0] = __float_as_uint(g_Q[row0 * HID + cb]);
        qf[k8][1] = __float_as_uint(g_Q[row1 * HID + cb]);
        qf[k8][2] = __float_as_uint(g_Q[row0 * HID + cb + 4]);
        qf[k8][3] = __float_as_uint(g_Q[row1 * HID + cb + 4]);
    }

    float of[16][4];
#pragma unroll
    for (int j = 0; j < 16; j++) { of[j][0] = 0.f; of[j][1] = 0.f; of[j][2] = 0.f; of[j][3] = 0.f; }
    float m0 = -1e30f, m1 = -1e30f, l0 = 0.f, l1 = 0.f;

    // one group = K tile + V tile for one kt
    auto loadKV = [&](int b, int kt) {
        const float* Kg = g_K + (size_t)(kt * ABN) * HID + hoff;
        const float* Vg = g_V + (size_t)(kt * ABN) * HID + hoff;
        uint32_t kb = dynb + (uint32_t)(b * KVSTG) * 4;
        uint32_t vb = dynb + (uint32_t)((2 + b) * KVSTG) * 4;
#pragma unroll
        for (int j = 0; j < 8; j++) {
            int cidx = tid + 128 * j;          // 0..1023
            int rr = cidx >> 5, c16 = cidx & 31;
            uint32_t off = (uint32_t)(rr * KVPITCH * 4 + c16 * 16);
            cpasync16(kb + off, Kg + (size_t)rr * HID + c16 * 4);
            cpasync16(vb + off, Vg + (size_t)rr * HID + c16 * 4);
        }
    };

    int ktmax = 2 * qt + 1;
    loadKV(0, 0);
    cpcommit();
    int buf = 0;

    for (int kt = 0; kt <= ktmax; kt++) {
        if (kt < ktmax) {
            if (kt > 0) __syncthreads();       // buffer buf^1 free?
            loadKV(buf ^ 1, kt + 1);
            cpcommit();
            asm volatile("cp.async.wait_group 1;" ::: "memory");
        } else {
            if (kt > 0) __syncthreads();
            asm volatile("cp.async.wait_group 0;" ::: "memory");
        }
        __syncthreads();

        const float* Kb = kvdyn + buf * KVSTG;
        const float* Vb = kvdyn + (2 + buf) * KVSTG;

        // scores: Q (64x128) @ K^T (128x32), per-warp 16x32
        float sf[4][4];
#pragma unroll
        for (int j = 0; j < 4; j++) { sf[j][0] = 0.f; sf[j][1] = 0.f; sf[j][2] = 0.f; sf[j][3] = 0.f; }
#pragma unroll
        for (int k8 = 0; k8 < 16; k8++) {
#pragma unroll
            for (int j = 0; j < 4; j++) {
                uint32_t b0 = __float_as_uint(Kb[(j * 8 + g) * KVPITCH + k8 * 8 + t]);
                uint32_t b1 = __float_as_uint(Kb[(j * 8 + g) * KVPITCH + k8 * 8 + t + 4]);
                mma_tf32(sf[j], qf[k8], b0, b1);
            }
        }

        // scale + causal mask + row max
        float mx0 = -1e30f, mx1 = -1e30f;
#pragma unroll
        for (int j = 0; j < 4; j++) {
            int cg = kt * ABN + j * 8 + 2 * t;
            sf[j][0] = (cg     <= row0) ? sf[j][0] * scale : -1e30f;
            sf[j][1] = (cg + 1 <= row0) ? sf[j][1] * scale : -1e30f;
            sf[j][2] = (cg     <= row1) ? sf[j][2] * scale : -1e30f;
            sf[j][3] = (cg + 1 <= row1) ? sf[j][3] * scale : -1e30f;
            mx0 = fmaxf(mx0, fmaxf(sf[j][0], sf[j][1]));
            mx1 = fmaxf(mx1, fmaxf(sf[j][2], sf[j][3]));
        }
        mx0 = fmaxf(mx0, __shfl_xor_sync(0xffffffffu, mx0, 1));
        mx0 = fmaxf(mx0, __shfl_xor_sync(0xffffffffu, mx0, 2));
        mx1 = fmaxf(mx1, __shfl_xor_sync(0xffffffffu, mx1, 1));
        mx1 = fmaxf(mx1, __shfl_xor_sync(0xffffffffu, mx1, 2));

        float mn0 = fmaxf(m0, mx0), mn1 = fmaxf(m1, mx1);
        float al0 = __expf(m0 - mn0), al1 = __expf(m1 - mn1);

        float rs0 = 0.f, rs1 = 0.f;
#pragma unroll
        for (int j = 0; j < 4; j++) {
            float p0 = __expf(sf[j][0] - mn0);
            float p1 = __expf(sf[j][1] - mn0);
            float p2 = __expf(sf[j][2] - mn1);
            float p3 = __expf(sf[j][3] - mn1);
            rs0 += p0 + p1; rs1 += p2 + p3;
            int cl = j * 8 + 2 * t;
            *reinterpret_cast<float2*>(&Ps[rl0][cl]) = make_float2(rtf(p0), rtf(p1));
            *reinterpret_cast<float2*>(&Ps[rl1][cl]) = make_float2(rtf(p2), rtf(p3));
        }
        rs0 += __shfl_xor_sync(0xffffffffu, rs0, 1);
        rs0 += __shfl_xor_sync(0xffffffffu, rs0, 2);
        rs1 += __shfl_xor_sync(0xffffffffu, rs1, 1);
        rs1 += __shfl_xor_sync(0xffffffffu, rs1, 2);
        l0 = l0 * al0 + rs0;
        l1 = l1 * al1 + rs1;
        m0 = mn0; m1 = mn1;
#pragma unroll
        for (int j = 0; j < 16; j++) {
            of[j][0] *= al0; of[j][1] *= al0; of[j][2] *= al1; of[j][3] *= al1;
        }

        // PV: P (64x32) @ V (32x128); Ps rows are warp-local, no sync needed
#pragma unroll
        for (int k8 = 0; k8 < 4; k8++) {
            uint32_t a[4];
            a[0] = __float_as_uint(Ps[rl0][k8 * 8 + t]);
            a[1] = __float_as_uint(Ps[rl1][k8 * 8 + t]);
            a[2] = __float_as_uint(Ps[rl0][k8 * 8 + t + 4]);
            a[3] = __float_as_uint(Ps[rl1][k8 * 8 + t + 4]);
#pragma unroll
            for (int j = 0; j < 16; j++) {
                uint32_t b0 = __float_as_uint(Vb[(k8 * 8 + t) * KVPITCH + j * 8 + g]);
                uint32_t b1 = __float_as_uint(Vb[(k8 * 8 + t + 4) * KVPITCH + j * 8 + g]);
                mma_tf32(of[j], a, b0, b1);
            }
        }
        buf ^= 1;
    }

    float inv0 = 1.f / l0, inv1 = 1.f / l1;
#pragma unroll
    for (int j = 0; j < 16; j++) {
        int col = hoff + j * 8 + 2 * t;
        *reinterpret_cast<float2*>(&g_ctx[(size_t)row0 * HID + col]) =
            make_float2(rtf(of[j][0] * inv0), rtf(of[j][1] * inv0));
        *reinterpret_cast<float2*>(&g_ctx[(size_t)row1 * HID + col]) =
            make_float2(rtf(of[j][2] * inv1), rtf(of[j][3] * inv1));
    }
}

// ---------------- launch ----------------
extern "C" void kernel_launch(void* const* d_in, const int* in_sizes, int n_in,
                              void* d_out, int out_size) {
    const float* X  = (const float*)d_in[0];
    const float* Wq = (const float*)d_in[1];
    const float* Wk = (const float*)d_in[2];
    const float* Wv = (const float*)d_in[3];
    const float* Wo = (const float*)d_in[4];
    float* out = (float*)d_out;

    static int inited = 0;
    if (!inited) {
        cudaFuncSetAttribute(gemm_tn, cudaFuncAttributeMaxDynamicSharedMemorySize, GEMM_SMEM);
        cudaFuncSetAttribute(attn_kernel, cudaFuncAttributeMaxDynamicSharedMemorySize, ATT_SMEM);
        inited = 1;
    }

    round_kernel<<<(SEQ * HID / 4) / 256, 256>>>(X, 0, SEQ * HID / 4);
    round_kernel<<<(HID * HID / 4) / 256, 256>>>(Wq, 1, HID * HID / 4);
    round_kernel<<<(HID * HID / 4) / 256, 256>>>(Wk, 2, HID * HID / 4);
    round_kernel<<<(HID * HID / 4) / 256, 256>>>(Wv, 3, HID * HID / 4);
    round_kernel<<<(HID * HID / 4) / 256, 256>>>(Wo, 4, HID * HID / 4);
    rope_table<<<(SEQ * 64) / 256, 256>>>();

    dim3 gg(HID / GBN, SEQ / GBM);  // (16, 32)
    gemm_tn<<<gg, 256, GEMM_SMEM>>>(0, nullptr);  // Q = Xr @ Wq^T
    gemm_tn<<<gg, 256, GEMM_SMEM>>>(1, nullptr);  // K = Xr @ Wk^T
    gemm_tn<<<gg, 256, GEMM_SMEM>>>(2, nullptr);  // V = Xr @ Wv^T (tf32-rounded)
    rope_apply<<<(SEQ * NHEADS * 64) / 256, 256>>>();

    attn_kernel<<<dim3(SEQ / ABM, NHEADS), 128, ATT_SMEM>>>(0.08838834764831845f);

    gemm_tn<<<gg, 256, GEMM_SMEM>>>(3, out);      // out = ctx @ Wo^T
}

// round 4
// speedup vs baseline: 1.3085x; 1.0640x over previous
#include <cuda_runtime.h>
#include <cstdint>

#define SEQ 4096
#define HID 2048
#define NHEADS 16
#define HD 128

// ---------------- scratch (static device arrays; no allocation) ----------------
static __device__ float g_Xr[SEQ * HID];
static __device__ float g_Wqr[HID * HID];
static __device__ float g_Wkr[HID * HID];
static __device__ float g_Wvr[HID * HID];
static __device__ float g_Wor[HID * HID];
static __device__ float g_Q[SEQ * HID];
static __device__ float g_K[SEQ * HID];
static __device__ float g_V[SEQ * HID];
static __device__ float g_ctx[SEQ * HID];
static __device__ float g_cos[SEQ * 64];
static __device__ float g_sin[SEQ * 64];

// ---------------- helpers ----------------
__device__ __forceinline__ uint32_t f2tf(float x) {
    uint32_t r;
    asm("cvt.rna.tf32.f32 %0, %1;" : "=r"(r) : "f"(x));
    return r;
}
__device__ __forceinline__ float rtf(float x) { return __uint_as_float(f2tf(x)); }

__device__ __forceinline__ void mma_tf32(float* c, const uint32_t* a, uint32_t b0, uint32_t b1) {
    asm volatile(
        "mma.sync.aligned.m16n8k8.row.col.f32.tf32.tf32.f32 "
        "{%0,%1,%2,%3}, {%4,%5,%6,%7}, {%8,%9}, {%0,%1,%2,%3};"
        : "+f"(c[0]), "+f"(c[1]), "+f"(c[2]), "+f"(c[3])
        : "r"(a[0]), "r"(a[1]), "r"(a[2]), "r"(a[3]), "r"(b0), "r"(b1));
}

__device__ __forceinline__ void cpasync16(uint32_t dst, const void* src) {
    asm volatile("cp.async.cg.shared.global [%0], [%1], 16;" :: "r"(dst), "l"(src));
}
__device__ __forceinline__ void cpcommit() { asm volatile("cp.async.commit_group;"); }

// ---------------- prep: tf32-round inputs into scratch ----------------
__global__ void round_kernel(const float* __restrict__ in, int sel, int n4) {
    int i = blockIdx.x * blockDim.x + threadIdx.x;
    if (i >= n4) return;
    float* dst = (sel == 0) ? g_Xr : (sel == 1) ? g_Wqr : (sel == 2) ? g_Wkr
               : (sel == 3) ? g_Wvr : g_Wor;
    float4 v = reinterpret_cast<const float4*>(in)[i];
    float4 o;
    o.x = rtf(v.x); o.y = rtf(v.y); o.z = rtf(v.z); o.w = rtf(v.w);
    reinterpret_cast<float4*>(dst)[i] = o;
}

// ---------------- RoPE ----------------
__global__ void rope_table() {
    int idx = blockIdx.x * blockDim.x + threadIdx.x;
    if (idx >= SEQ * 64) return;
    int s = idx >> 6, j = idx & 63;
    double invf = exp(-(double)j * (9.210340371976184 / 64.0));  // 10000^(-j/64)
    float freq = (float)s * (float)invf;                          // fp32, like the ref
    g_cos[idx] = (float)cos((double)freq);
    g_sin[idx] = (float)sin((double)freq);
}

__global__ void rope_apply() {
    int idx = blockIdx.x * blockDim.x + threadIdx.x;
    if (idx >= SEQ * NHEADS * 64) return;
    int s = idx >> 10;
    int h = (idx >> 6) & (NHEADS - 1);
    int i = idx & 63;
    float c = g_cos[(s << 6) + i], sn = g_sin[(s << 6) + i];
    int base = s * HID + h * HD + i;
    float q1 = g_Q[base], q2 = g_Q[base + 64];
    g_Q[base]      = rtf(q1 * c - q2 * sn);
    g_Q[base + 64] = rtf(q2 * c + q1 * sn);
    float k1 = g_K[base], k2 = g_K[base + 64];
    g_K[base]      = rtf(k1 * c - k2 * sn);
    g_K[base + 64] = rtf(k2 * c + k1 * sn);
}

// ---------------- GEMM: C[M,N] = A[M,K] @ B[N,K]^T, GBK=32, 3-stage ----------
#define GBM 128
#define GBN 128
#define GBK 32
#define GST 3
#define APITCH 36
#define AS_FLOATS (GBM * APITCH)          // 4608
#define STG_FLOATS (2 * AS_FLOATS)        // 9216
#define GEMM_SMEM (GST * STG_FLOATS * 4)  // 110592 B

// sel: 0..2 = fused QKV (blockIdx.z picks weight), 3 = output proj
__global__ void __launch_bounds__(256, 1) gemm_tn(int fused, float* __restrict__ extC) {
    extern __shared__ float sm[];
    const float* A; const float* B; float* C; int roundOut = 0;
    const int N = HID, K = HID;
    int sel = fused ? (int)blockIdx.z : 3;
    if (sel == 0)      { A = g_Xr;  B = g_Wqr; C = g_Q; }
    else if (sel == 1) { A = g_Xr;  B = g_Wkr; C = g_K; }
    else if (sel == 2) { A = g_Xr;  B = g_Wvr; C = g_V; roundOut = 1; }
    else               { A = g_ctx; B = g_Wor; C = extC; }

    int tid = threadIdx.x;
    int lane = tid & 31, wid = tid >> 5;
    int wm = wid & 3, wn = wid >> 2;
    int bm = blockIdx.y * GBM, bn = blockIdx.x * GBN;

    float c[2][8][4];
#pragma unroll
    for (int im = 0; im < 2; im++)
#pragma unroll
        for (int jn = 0; jn < 8; jn++)
#pragma unroll
            for (int q = 0; q < 4; q++) c[im][jn][q] = 0.f;

    const float* Abase = A + (size_t)bm * K;
    const float* Bbase = B + (size_t)bn * K;

    uint32_t smb = (uint32_t)__cvta_generic_to_shared(sm);

    // per-thread: 4 float4 per operand tile; rows r = (tid>>3) + 32*i, col (tid&7)*4
    int lr = tid >> 3, lc = (tid & 7) << 2;

    auto load_tile = [&](int s, int kt) {
        int koff = kt * GBK + lc;
        uint32_t sa = smb + (uint32_t)(s * STG_FLOATS) * 4;
        uint32_t sb = sa + AS_FLOATS * 4;
#pragma unroll
        for (int i = 0; i < 4; i++) {
            int r = lr + 32 * i;
            cpasync16(sa + (uint32_t)(r * APITCH + lc) * 4, Abase + (size_t)r * K + koff);
            cpasync16(sb + (uint32_t)(r * APITCH + lc) * 4, Bbase + (size_t)r * K + koff);
        }
    };

    const int NT = K / GBK;  // 64
    load_tile(0, 0); cpcommit();
    load_tile(1, 1); cpcommit();

    int g = lane >> 2, t = lane & 3;
    int stg = 0;

    for (int kt = 0; kt < NT; kt++) {
        if (kt + 2 < NT) {
            if (kt > 0) __syncthreads();   // stage being overwritten was consumed at kt-1
            int ns = stg + 2; if (ns >= GST) ns -= GST;
            load_tile(ns, kt + 2);
            cpcommit();
            asm volatile("cp.async.wait_group 2;" ::: "memory");
        } else {
            if (kt > 0) __syncthreads();
            asm volatile("cp.async.wait_group 0;" ::: "memory");
        }
        __syncthreads();

        const float* As = sm + stg * STG_FLOATS;
        const float* Bs = As + AS_FLOATS;
#pragma unroll
        for (int ks = 0; ks < 4; ks++) {
            int k0 = ks * 8;
            uint32_t a[2][4], b[8][2];
#pragma unroll
            for (int im = 0; im < 2; im++) {
                int r = wm * 32 + im * 16 + g;
                a[im][0] = __float_as_uint(As[r * APITCH + k0 + t]);
                a[im][1] = __float_as_uint(As[(r + 8) * APITCH + k0 + t]);
                a[im][2] = __float_as_uint(As[r * APITCH + k0 + t + 4]);
                a[im][3] = __float_as_uint(As[(r + 8) * APITCH + k0 + t + 4]);
            }
#pragma unroll
            for (int jn = 0; jn < 8; jn++) {
                int cc = wn * 64 + jn * 8 + g;
                b[jn][0] = __float_as_uint(Bs[cc * APITCH + k0 + t]);
                b[jn][1] = __float_as_uint(Bs[cc * APITCH + k0 + t + 4]);
            }
#pragma unroll
            for (int im = 0; im < 2; im++)
#pragma unroll
                for (int jn = 0; jn < 8; jn++)
                    mma_tf32(c[im][jn], a[im], b[jn][0], b[jn][1]);
        }
        if (++stg == GST) stg = 0;
    }

#pragma unroll
    for (int im = 0; im < 2; im++) {
#pragma unroll
        for (int jn = 0; jn < 8; jn++) {
            int r = bm + wm * 32 + im * 16 + g;
            int col = bn + wn * 64 + jn * 8 + 2 * t;
            float v0 = c[im][jn][0], v1 = c[im][jn][1];
            float v2 = c[im][jn][2], v3 = c[im][jn][3];
            if (roundOut) { v0 = rtf(v0); v1 = rtf(v1); v2 = rtf(v2); v3 = rtf(v3); }
            *reinterpret_cast<float2*>(&C[(size_t)r * N + col])       = make_float2(v0, v1);
            *reinterpret_cast<float2*>(&C[(size_t)(r + 8) * N + col]) = make_float2(v2, v3);
        }
    }
}

// ---------------- flash attention (causal), ABM=128, 8 warps ----------------
#define ABM 128
#define ABN 32
#define KVPITCH 136
#define KVSTG (ABN * KVPITCH)            // 4352 floats per stage
#define ATT_SMEM (4 * KVSTG * 4)         // K[2] + V[2] = 69632 B dynamic

__global__ void __launch_bounds__(256) attn_kernel(float scale) {
    extern __shared__ float kvdyn[];     // [K0, K1, V0, V1]
    __shared__ float Ps[ABM][36];        // probs, warp-local rows

    int tid = threadIdx.x, lane = tid & 31, wid = tid >> 5;
    int g = lane >> 2, t = lane & 3;
    int qt = (int)(gridDim.x - 1 - blockIdx.x);   // heavy tiles first
    int h = blockIdx.y;
    int hoff = h * HD;
    int qrow = qt * ABM + wid * 16;
    int row0 = qrow + g, row1 = row0 + 8;
    int rl0 = wid * 16 + g, rl1 = rl0 + 8;

    uint32_t dynb = (uint32_t)__cvta_generic_to_shared(kvdyn);

    // Q A-fragments in registers (pre-rounded tf32 from rope_apply)
    uint32_t qf[16][4];
#pragma unroll
    for (int k8 = 0; k8 < 16; k8++) {
        int cb = hoff + k8 * 8 + t;
        qf[k8][0] = __float_as_uint(g_Q[(size_t)row0 * HID + cb]);
        qf[k8][1] = __float_as_uint(g_Q[(size_t)row1 * HID + cb]);
        qf[k8][2] = __float_as_uint(g_Q[(size_t)row0 * HID + cb + 4]);
        qf[k8][3] = __float_as_uint(g_Q[(size_t)row1 * HID + cb + 4]);
    }

    float of[16][4];
#pragma unroll
    for (int j = 0; j < 16; j++) { of[j][0] = 0.f; of[j][1] = 0.f; of[j][2] = 0.f; of[j][3] = 0.f; }
    float m0 = -1e30f, m1 = -1e30f, l0 = 0.f, l1 = 0.f;

    // one group = K tile + V tile for one kt (256 threads, 4 float4 each per operand)
    auto loadKV = [&](int b, int kt) {
        const float* Kg = g_K + (size_t)(kt * ABN) * HID + hoff;
        const float* Vg = g_V + (size_t)(kt * ABN) * HID + hoff;
        uint32_t kb = dynb + (uint32_t)(b * KVSTG) * 4;
        uint32_t vb = dynb + (uint32_t)((2 + b) * KVSTG) * 4;
#pragma unroll
        for (int j = 0; j < 4; j++) {
            int cidx = tid + 256 * j;          // 0..1023
            int rr = cidx >> 5, c16 = cidx & 31;
            uint32_t off = (uint32_t)(rr * KVPITCH * 4 + c16 * 16);
            cpasync16(kb + off, Kg + (size_t)rr * HID + c16 * 4);
            cpasync16(vb + off, Vg + (size_t)rr * HID + c16 * 4);
        }
    };

    int ktmax = 4 * qt + 3;
    loadKV(0, 0);
    cpcommit();
    int buf = 0;

    for (int kt = 0; kt <= ktmax; kt++) {
        if (kt < ktmax) {
            if (kt > 0) __syncthreads();       // buffer buf^1 free?
            loadKV(buf ^ 1, kt + 1);
            cpcommit();
            asm volatile("cp.async.wait_group 1;" ::: "memory");
        } else {
            if (kt > 0) __syncthreads();
            asm volatile("cp.async.wait_group 0;" ::: "memory");
        }
        __syncthreads();

        const float* Kb = kvdyn + buf * KVSTG;
        const float* Vb = kvdyn + (2 + buf) * KVSTG;

        // scores: Q (128x128) @ K^T (128x32), per-warp 16x32
        float sf[4][4];
#pragma unroll
        for (int j = 0; j < 4; j++) { sf[j][0] = 0.f; sf[j][1] = 0.f; sf[j][2] = 0.f; sf[j][3] = 0.f; }
#pragma unroll
        for (int k8 = 0; k8 < 16; k8++) {
#pragma unroll
            for (int j = 0; j < 4; j++) {
                uint32_t b0 = __float_as_uint(Kb[(j * 8 + g) * KVPITCH + k8 * 8 + t]);
                uint32_t b1 = __float_as_uint(Kb[(j * 8 + g) * KVPITCH + k8 * 8 + t + 4]);
                mma_tf32(sf[j], qf[k8], b0, b1);
            }
        }

        // scale + causal mask + row max
        float mx0 = -1e30f, mx1 = -1e30f;
#pragma unroll
        for (int j = 0; j < 4; j++) {
            int cg = kt * ABN + j * 8 + 2 * t;
            sf[j][0] = (cg     <= row0) ? sf[j][0] * scale : -1e30f;
            sf[j][1] = (cg + 1 <= row0) ? sf[j][1] * scale : -1e30f;
            sf[j][2] = (cg     <= row1) ? sf[j][2] * scale : -1e30f;
            sf[j][3] = (cg + 1 <= row1) ? sf[j][3] * scale : -1e30f;
            mx0 = fmaxf(mx0, fmaxf(sf[j][0], sf[j][1]));
            mx1 = fmaxf(mx1, fmaxf(sf[j][2], sf[j][3]));
        }
        mx0 = fmaxf(mx0, __shfl_xor_sync(0xffffffffu, mx0, 1));
        mx0 = fmaxf(mx0, __shfl_xor_sync(0xffffffffu, mx0, 2));
        mx1 = fmaxf(mx1, __shfl_xor_sync(0xffffffffu, mx1, 1));
        mx1 = fmaxf(mx1, __shfl_xor_sync(0xffffffffu, mx1, 2));

        float mn0 = fmaxf(m0, mx0), mn1 = fmaxf(m1, mx1);
        float al0 = __expf(m0 - mn0), al1 = __expf(m1 - mn1);

        float rs0 = 0.f, rs1 = 0.f;
#pragma unroll
        for (int j = 0; j < 4; j++) {
            float p0 = __expf(sf[j][0] - mn0);
            float p1 = __expf(sf[j][1] - mn0);
            float p2 = __expf(sf[j][2] - mn1);
            float p3 = __expf(sf[j][3] - mn1);
            rs0 += p0 + p1; rs1 += p2 + p3;
            int cl = j * 8 + 2 * t;
            *reinterpret_cast<float2*>(&Ps[rl0][cl]) = make_float2(rtf(p0), rtf(p1));
            *reinterpret_cast<float2*>(&Ps[rl1][cl]) = make_float2(rtf(p2), rtf(p3));
        }
        rs0 += __shfl_xor_sync(0xffffffffu, rs0, 1);
        rs0 += __shfl_xor_sync(0xffffffffu, rs0, 2);
        rs1 += __shfl_xor_sync(0xffffffffu, rs1, 1);
        rs1 += __shfl_xor_sync(0xffffffffu, rs1, 2);
        l0 = l0 * al0 + rs0;
        l1 = l1 * al1 + rs1;
        m0 = mn0; m1 = mn1;
#pragma unroll
        for (int j = 0; j < 16; j++) {
            of[j][0] *= al0; of[j][1] *= al0; of[j][2] *= al1; of[j][3] *= al1;
        }

        // PV: P (128x32) @ V (32x128); Ps rows are warp-local, no sync needed
#pragma unroll
        for (int k8 = 0; k8 < 4; k8++) {
            uint32_t a[4];
            a[0] = __float_as_uint(Ps[rl0][k8 * 8 + t]);
            a[1] = __float_as_uint(Ps[rl1][k8 * 8 + t]);
            a[2] = __float_as_uint(Ps[rl0][k8 * 8 + t + 4]);
            a[3] = __float_as_uint(Ps[rl1][k8 * 8 + t + 4]);
#pragma unroll
            for (int j = 0; j < 16; j++) {
                uint32_t b0 = __float_as_uint(Vb[(k8 * 8 + t) * KVPITCH + j * 8 + g]);
                uint32_t b1 = __float_as_uint(Vb[(k8 * 8 + t + 4) * KVPITCH + j * 8 + g]);
                mma_tf32(of[j], a, b0, b1);
            }
        }
        buf ^= 1;
    }

    float inv0 = 1.f / l0, inv1 = 1.f / l1;
#pragma unroll
    for (int j = 0; j < 16; j++) {
        int col = hoff + j * 8 + 2 * t;
        *reinterpret_cast<float2*>(&g_ctx[(size_t)row0 * HID + col]) =
            make_float2(rtf(of[j][0] * inv0), rtf(of[j][1] * inv0));
        *reinterpret_cast<float2*>(&g_ctx[(size_t)row1 * HID + col]) =
            make_float2(rtf(of[j][2] * inv1), rtf(of[j][3] * inv1));
    }
}

// ---------------- launch ----------------
extern "C" void kernel_launch(void* const* d_in, const int* in_sizes, int n_in,
                              void* d_out, int out_size) {
    const float* X  = (const float*)d_in[0];
    const float* Wq = (const float*)d_in[1];
    const float* Wk = (const float*)d_in[2];
    const float* Wv = (const float*)d_in[3];
    const float* Wo = (const float*)d_in[4];
    float* out = (float*)d_out;

    static int inited = 0;
    if (!inited) {
        cudaFuncSetAttribute(gemm_tn, cudaFuncAttributeMaxDynamicSharedMemorySize, GEMM_SMEM);
        cudaFuncSetAttribute(attn_kernel, cudaFuncAttributeMaxDynamicSharedMemorySize, ATT_SMEM);
        inited = 1;
    }

    round_kernel<<<(SEQ * HID / 4) / 256, 256>>>(X, 0, SEQ * HID / 4);
    round_kernel<<<(HID * HID / 4) / 256, 256>>>(Wq, 1, HID * HID / 4);
    round_kernel<<<(HID * HID / 4) / 256, 256>>>(Wk, 2, HID * HID / 4);
    round_kernel<<<(HID * HID / 4) / 256, 256>>>(Wv, 3, HID * HID / 4);
    round_kernel<<<(HID * HID / 4) / 256, 256>>>(Wo, 4, HID * HID / 4);
    rope_table<<<(SEQ * 64) / 256, 256>>>();

    dim3 gqkv(HID / GBN, SEQ / GBM, 3);     // fused Q,K,V projection
    gemm_tn<<<gqkv, 256, GEMM_SMEM>>>(1, nullptr);
    rope_apply<<<(SEQ * NHEADS * 64) / 256, 256>>>();

    attn_kernel<<<dim3(SEQ / ABM, NHEADS), 256, ATT_SMEM>>>(0.08838834764831845f);

    dim3 go(HID / GBN, SEQ / GBM, 1);       // output projection
    gemm_tn<<<go, 256, GEMM_SMEM>>>(0, out);
}

// round 6
// speedup vs baseline: 1.7478x; 1.3358x over previous
#include <cuda_runtime.h>
#include <cuda_fp16.h>
#include <cstdint>

#define SEQ 4096
#define HID 2048
#define NHEADS 16
#define HD 128

// ---------------- scratch (static device arrays; no allocation) ----------------
static __device__ __half g_Xh[SEQ * HID];
static __device__ __half g_Wqh[HID * HID];
static __device__ __half g_Wkh[HID * HID];
static __device__ __half g_Wvh[HID * HID];
static __device__ __half g_Woh[HID * HID];
static __device__ float  g_Q[SEQ * HID];     // fp32, tf32-rounded after rope
static __device__ float  g_K[SEQ * HID];
static __device__ float  g_V[SEQ * HID];     // fp32, tf32-rounded
static __device__ __half g_ctxh[SEQ * HID];  // attention output (half)
static __device__ float  g_cos[SEQ * 64];
static __device__ float  g_sin[SEQ * 64];

// ---------------- helpers ----------------
__device__ __forceinline__ uint32_t f2tf(float x) {
    uint32_t r;
    asm("cvt.rna.tf32.f32 %0, %1;" : "=r"(r) : "f"(x));
    return r;
}
__device__ __forceinline__ float rtf(float x) { return __uint_as_float(f2tf(x)); }

__device__ __forceinline__ void mma_tf32(float* c, const uint32_t* a, uint32_t b0, uint32_t b1) {
    asm volatile(
        "mma.sync.aligned.m16n8k8.row.col.f32.tf32.tf32.f32 "
        "{%0,%1,%2,%3}, {%4,%5,%6,%7}, {%8,%9}, {%0,%1,%2,%3};"
        : "+f"(c[0]), "+f"(c[1]), "+f"(c[2]), "+f"(c[3])
        : "r"(a[0]), "r"(a[1]), "r"(a[2]), "r"(a[3]), "r"(b0), "r"(b1));
}

__device__ __forceinline__ void mma_f16(float* c, const uint32_t* a, uint32_t b0, uint32_t b1) {
    asm volatile(
        "mma.sync.aligned.m16n8k16.row.col.f32.f16.f16.f32 "
        "{%0,%1,%2,%3}, {%4,%5,%6,%7}, {%8,%9}, {%0,%1,%2,%3};"
        : "+f"(c[0]), "+f"(c[1]), "+f"(c[2]), "+f"(c[3])
        : "r"(a[0]), "r"(a[1]), "r"(a[2]), "r"(a[3]), "r"(b0), "r"(b1));
}

__device__ __forceinline__ void cpasync16(uint32_t dst, const void* src) {
    asm volatile("cp.async.cg.shared.global [%0], [%1], 16;" :: "r"(dst), "l"(src));
}
__device__ __forceinline__ void cpcommit() { asm volatile("cp.async.commit_group;"); }

// ---------------- prep: fp32 -> fp16 ----------------
__global__ void tohalf_kernel(const float* __restrict__ in, int sel, int n4) {
    int i = blockIdx.x * blockDim.x + threadIdx.x;
    if (i >= n4) return;
    __half* dst = (sel == 0) ? g_Xh : (sel == 1) ? g_Wqh : (sel == 2) ? g_Wkh
                : (sel == 3) ? g_Wvh : g_Woh;
    float4 v = reinterpret_cast<const float4*>(in)[i];
    __half2* p = reinterpret_cast<__half2*>(&dst[4 * i]);
    p[0] = __floats2half2_rn(v.x, v.y);
    p[1] = __floats2half2_rn(v.z, v.w);
}

// ---------------- RoPE ----------------
__global__ void rope_table() {
    int idx = blockIdx.x * blockDim.x + threadIdx.x;
    if (idx >= SEQ * 64) return;
    int s = idx >> 6, j = idx & 63;
    double invf = exp(-(double)j * (9.210340371976184 / 64.0));  // 10000^(-j/64)
    float freq = (float)s * (float)invf;                          // fp32, like the ref
    g_cos[idx] = (float)cos((double)freq);
    g_sin[idx] = (float)sin((double)freq);
}

__global__ void rope_apply() {
    int idx = blockIdx.x * blockDim.x + threadIdx.x;
    if (idx >= SEQ * NHEADS * 64) return;
    int s = idx >> 10;
    int h = (idx >> 6) & (NHEADS - 1);
    int i = idx & 63;
    float c = g_cos[(s << 6) + i], sn = g_sin[(s << 6) + i];
    int base = s * HID + h * HD + i;
    float q1 = g_Q[base], q2 = g_Q[base + 64];
    g_Q[base]      = rtf(q1 * c - q2 * sn);
    g_Q[base + 64] = rtf(q2 * c + q1 * sn);
    float k1 = g_K[base], k2 = g_K[base + 64];
    g_K[base]      = rtf(k1 * c - k2 * sn);
    g_K[base + 64] = rtf(k2 * c + k1 * sn);
}

// ---------------- GEMM: C[M,N] = A[M,K] @ B[N,K]^T, fp16 mma, GBK=64, 3-stage --
#define GBM 128
#define GBN 128
#define GBK 64
#define GST 3
#define APITCH 72                          // halves
#define AHALFS (GBM * APITCH)              // 9216
#define STGH (2 * AHALFS)                  // 18432 halves = 36864 B
#define GEMM_SMEM (GST * STGH * 2)         // 110592 B

// fused=1: blockIdx.z selects Q/K/V; fused=0: output projection
__global__ void __launch_bounds__(256, 1) gemm_tn(int fused, float* __restrict__ extC) {
    extern __shared__ __half sm[];
    const __half* A; const __half* B;
    float* Cf; int roundOut = 0;
    const int N = HID, K = HID;
    int sel = fused ? (int)blockIdx.z : 3;
    if (sel == 0)      { A = g_Xh;   B = g_Wqh; Cf = g_Q; }
    else if (sel == 1) { A = g_Xh;   B = g_Wkh; Cf = g_K; }
    else if (sel == 2) { A = g_Xh;   B = g_Wvh; Cf = g_V; roundOut = 1; }
    else               { A = g_ctxh; B = g_Woh; Cf = extC; }

    int tid = threadIdx.x;
    int lane = tid & 31, wid = tid >> 5;
    int wm = wid & 3, wn = wid >> 2;
    int bm = blockIdx.y * GBM, bn = blockIdx.x * GBN;

    float c[2][8][4];
#pragma unroll
    for (int im = 0; im < 2; im++)
#pragma unroll
        for (int jn = 0; jn < 8; jn++)
#pragma unroll
            for (int q = 0; q < 4; q++) c[im][jn][q] = 0.f;

    const __half* Abase = A + (size_t)bm * K;
    const __half* Bbase = B + (size_t)bn * K;

    uint32_t smb = (uint32_t)__cvta_generic_to_shared(sm);

    // per-thread: rows lr+32i (i<4), 16B chunk lc8 (8 halves)
    int lr = tid >> 3, lc8 = tid & 7;

    auto load_tile = [&](int s, int kt) {
        int koff = kt * GBK + lc8 * 8;
        uint32_t sa = smb + (uint32_t)(s * STGH) * 2;
        uint32_t sb = sa + AHALFS * 2;
        uint32_t doff = (uint32_t)(lr * APITCH + lc8 * 8) * 2;
#pragma unroll
        for (int i = 0; i < 4; i++) {
            int r = lr + 32 * i;
            cpasync16(sa + doff + (uint32_t)(32 * i * APITCH) * 2, Abase + (size_t)r * K + koff);
            cpasync16(sb + doff + (uint32_t)(32 * i * APITCH) * 2, Bbase + (size_t)r * K + koff);
        }
    };

    const int NT = K / GBK;  // 32
    load_tile(0, 0); cpcommit();
    load_tile(1, 1); cpcommit();

    int g = lane >> 2, t = lane & 3;
    int stg = 0;

    for (int kt = 0; kt < NT; kt++) {
        if (kt + 2 < NT) {
            if (kt > 0) __syncthreads();
            int ns = stg + 2; if (ns >= GST) ns -= GST;
            load_tile(ns, kt + 2);
            cpcommit();
            asm volatile("cp.async.wait_group 2;" ::: "memory");
        } else {
            if (kt > 0) __syncthreads();
            asm volatile("cp.async.wait_group 0;" ::: "memory");
        }
        __syncthreads();

        const __half* As = sm + stg * STGH;
        const __half* Bs = As + AHALFS;
#pragma unroll
        for (int ks = 0; ks < 4; ks++) {
            int k0 = ks * 16;
            uint32_t a[2][4], b[8][2];
#pragma unroll
            for (int im = 0; im < 2; im++) {
                int r = wm * 32 + im * 16 + g;
                a[im][0] = *reinterpret_cast<const uint32_t*>(&As[r * APITCH + k0 + 2 * t]);
                a[im][1] = *reinterpret_cast<const uint32_t*>(&As[(r + 8) * APITCH + k0 + 2 * t]);
                a[im][2] = *reinterpret_cast<const uint32_t*>(&As[r * APITCH + k0 + 2 * t + 8]);
                a[im][3] = *reinterpret_cast<const uint32_t*>(&As[(r + 8) * APITCH + k0 + 2 * t + 8]);
            }
#pragma unroll
            for (int jn = 0; jn < 8; jn++) {
                int cc = wn * 64 + jn * 8 + g;
                b[jn][0] = *reinterpret_cast<const uint32_t*>(&Bs[cc * APITCH + k0 + 2 * t]);
                b[jn][1] = *reinterpret_cast<const uint32_t*>(&Bs[cc * APITCH + k0 + 2 * t + 8]);
            }
#pragma unroll
            for (int im = 0; im < 2; im++)
#pragma unroll
                for (int jn = 0; jn < 8; jn++)
                    mma_f16(c[im][jn], a[im], b[jn][0], b[jn][1]);
        }
        if (++stg == GST) stg = 0;
    }

#pragma unroll
    for (int im = 0; im < 2; im++) {
#pragma unroll
        for (int jn = 0; jn < 8; jn++) {
            int r = bm + wm * 32 + im * 16 + g;
            int col = bn + wn * 64 + jn * 8 + 2 * t;
            float v0 = c[im][jn][0], v1 = c[im][jn][1];
            float v2 = c[im][jn][2], v3 = c[im][jn][3];
            if (roundOut) { v0 = rtf(v0); v1 = rtf(v1); v2 = rtf(v2); v3 = rtf(v3); }
            *reinterpret_cast<float2*>(&Cf[(size_t)r * N + col])       = make_float2(v0, v1);
            *reinterpret_cast<float2*>(&Cf[(size_t)(r + 8) * N + col]) = make_float2(v2, v3);
        }
    }
}

// ---------------- flash attention (causal), tf32 mma — round-4 validated ------
#define ABM 128
#define ABN 32
#define KVPITCH 136
#define KVSTG (ABN * KVPITCH)            // 4352 floats per stage
#define ATT_SMEM (4 * KVSTG * 4)         // K[2] + V[2] = 69632 B dynamic

__global__ void __launch_bounds__(256) attn_kernel(float scale) {
    extern __shared__ float kvdyn[];     // [K0, K1, V0, V1]
    __shared__ float Ps[ABM][36];        // probs, warp-local rows

    int tid = threadIdx.x, lane = tid & 31, wid = tid >> 5;
    int g = lane >> 2, t = lane & 3;
    int qt = (int)(gridDim.x - 1 - blockIdx.x);   // heavy tiles first
    int h = blockIdx.y;
    int hoff = h * HD;
    int qrow = qt * ABM + wid * 16;
    int row0 = qrow + g, row1 = row0 + 8;
    int rl0 = wid * 16 + g, rl1 = rl0 + 8;

    uint32_t dynb = (uint32_t)__cvta_generic_to_shared(kvdyn);

    // Q A-fragments in registers (pre-rounded tf32 from rope_apply)
    uint32_t qf[16][4];
#pragma unroll
    for (int k8 = 0; k8 < 16; k8++) {
        int cb = hoff + k8 * 8 + t;
        qf[k8][0] = __float_as_uint(g_Q[(size_t)row0 * HID + cb]);
        qf[k8][1] = __float_as_uint(g_Q[(size_t)row1 * HID + cb]);
        qf[k8][2] = __float_as_uint(g_Q[(size_t)row0 * HID + cb + 4]);
        qf[k8][3] = __float_as_uint(g_Q[(size_t)row1 * HID + cb + 4]);
    }

    float of[16][4];
#pragma unroll
    for (int j = 0; j < 16; j++) { of[j][0] = 0.f; of[j][1] = 0.f; of[j][2] = 0.f; of[j][3] = 0.f; }
    float m0 = -1e30f, m1 = -1e30f, l0 = 0.f, l1 = 0.f;

    auto loadKV = [&](int b, int kt) {
        const float* Kg = g_K + (size_t)(kt * ABN) * HID + hoff;
        const float* Vg = g_V + (size_t)(kt * ABN) * HID + hoff;
        uint32_t kb = dynb + (uint32_t)(b * KVSTG) * 4;
        uint32_t vb = dynb + (uint32_t)((2 + b) * KVSTG) * 4;
#pragma unroll
        for (int j = 0; j < 4; j++) {
            int cidx = tid + 256 * j;          // 0..1023
            int rr = cidx >> 5, c16 = cidx & 31;
            uint32_t off = (uint32_t)(rr * KVPITCH * 4 + c16 * 16);
            cpasync16(kb + off, Kg + (size_t)rr * HID + c16 * 4);
            cpasync16(vb + off, Vg + (size_t)rr * HID + c16 * 4);
        }
    };

    int ktmax = 4 * qt + 3;
    loadKV(0, 0);
    cpcommit();
    int buf = 0;

    for (int kt = 0; kt <= ktmax; kt++) {
        if (kt < ktmax) {
            if (kt > 0) __syncthreads();
            loadKV(buf ^ 1, kt + 1);
            cpcommit();
            asm volatile("cp.async.wait_group 1;" ::: "memory");
        } else {
            if (kt > 0) __syncthreads();
            asm volatile("cp.async.wait_group 0;" ::: "memory");
        }
        __syncthreads();

        const float* Kb = kvdyn + buf * KVSTG;
        const float* Vb = kvdyn + (2 + buf) * KVSTG;

        float sf[4][4];
#pragma unroll
        for (int j = 0; j < 4; j++) { sf[j][0] = 0.f; sf[j][1] = 0.f; sf[j][2] = 0.f; sf[j][3] = 0.f; }
#pragma unroll
        for (int k8 = 0; k8 < 16; k8++) {
#pragma unroll
            for (int j = 0; j < 4; j++) {
                uint32_t b0 = __float_as_uint(Kb[(j * 8 + g) * KVPITCH + k8 * 8 + t]);
                uint32_t b1 = __float_as_uint(Kb[(j * 8 + g) * KVPITCH + k8 * 8 + t + 4]);
                mma_tf32(sf[j], qf[k8], b0, b1);
            }
        }

        float mx0 = -1e30f, mx1 = -1e30f;
#pragma unroll
        for (int j = 0; j < 4; j++) {
            int cg = kt * ABN + j * 8 + 2 * t;
            sf[j][0] = (cg     <= row0) ? sf[j][0] * scale : -1e30f;
            sf[j][1] = (cg + 1 <= row0) ? sf[j][1] * scale : -1e30f;
            sf[j][2] = (cg     <= row1) ? sf[j][2] * scale : -1e30f;
            sf[j][3] = (cg + 1 <= row1) ? sf[j][3] * scale : -1e30f;
            mx0 = fmaxf(mx0, fmaxf(sf[j][0], sf[j][1]));
            mx1 = fmaxf(mx1, fmaxf(sf[j][2], sf[j][3]));
        }
        mx0 = fmaxf(mx0, __shfl_xor_sync(0xffffffffu, mx0, 1));
        mx0 = fmaxf(mx0, __shfl_xor_sync(0xffffffffu, mx0, 2));
        mx1 = fmaxf(mx1, __shfl_xor_sync(0xffffffffu, mx1, 1));
        mx1 = fmaxf(mx1, __shfl_xor_sync(0xffffffffu, mx1, 2));

        float mn0 = fmaxf(m0, mx0), mn1 = fmaxf(m1, mx1);
        float al0 = __expf(m0 - mn0), al1 = __expf(m1 - mn1);

        float rs0 = 0.f, rs1 = 0.f;
#pragma unroll
        for (int j = 0; j < 4; j++) {
            float p0 = __expf(sf[j][0] - mn0);
            float p1 = __expf(sf[j][1] - mn0);
            float p2 = __expf(sf[j][2] - mn1);
            float p3 = __expf(sf[j][3] - mn1);
            rs0 += p0 + p1; rs1 += p2 + p3;
            int cl = j * 8 + 2 * t;
            *reinterpret_cast<float2*>(&Ps[rl0][cl]) = make_float2(rtf(p0), rtf(p1));
            *reinterpret_cast<float2*>(&Ps[rl1][cl]) = make_float2(rtf(p2), rtf(p3));
        }
        rs0 += __shfl_xor_sync(0xffffffffu, rs0, 1);
        rs0 += __shfl_xor_sync(0xffffffffu, rs0, 2);
        rs1 += __shfl_xor_sync(0xffffffffu, rs1, 1);
        rs1 += __shfl_xor_sync(0xffffffffu, rs1, 2);
        l0 = l0 * al0 + rs0;
        l1 = l1 * al1 + rs1;
        m0 = mn0; m1 = mn1;
#pragma unroll
        for (int j = 0; j < 16; j++) {
            of[j][0] *= al0; of[j][1] *= al0; of[j][2] *= al1; of[j][3] *= al1;
        }

#pragma unroll
        for (int k8 = 0; k8 < 4; k8++) {
            uint32_t a[4];
            a[0] = __float_as_uint(Ps[rl0][k8 * 8 + t]);
            a[1] = __float_as_uint(Ps[rl1][k8 * 8 + t]);
            a[2] = __float_as_uint(Ps[rl0][k8 * 8 + t + 4]);
            a[3] = __float_as_uint(Ps[rl1][k8 * 8 + t + 4]);
#pragma unroll
            for (int j = 0; j < 16; j++) {
                uint32_t b0 = __float_as_uint(Vb[(k8 * 8 + t) * KVPITCH + j * 8 + g]);
                uint32_t b1 = __float_as_uint(Vb[(k8 * 8 + t + 4) * KVPITCH + j * 8 + g]);
                mma_tf32(of[j], a, b0, b1);
            }
        }
        buf ^= 1;
    }

    float inv0 = 1.f / l0, inv1 = 1.f / l1;
#pragma unroll
    for (int j = 0; j < 16; j++) {
        int col = hoff + j * 8 + 2 * t;
        *reinterpret_cast<__half2*>(&g_ctxh[(size_t)row0 * HID + col]) =
            __floats2half2_rn(of[j][0] * inv0, of[j][1] * inv0);
        *reinterpret_cast<__half2*>(&g_ctxh[(size_t)row1 * HID + col]) =
            __floats2half2_rn(of[j][2] * inv1, of[j][3] * inv1);
    }
}

// ---------------- launch ----------------
extern "C" void kernel_launch(void* const* d_in, const int* in_sizes, int n_in,
                              void* d_out, int out_size) {
    const float* X  = (const float*)d_in[0];
    const float* Wq = (const float*)d_in[1];
    const float* Wk = (const float*)d_in[2];
    const float* Wv = (const float*)d_in[3];
    const float* Wo = (const float*)d_in[4];
    float* out = (float*)d_out;

    static int inited = 0;
    if (!inited) {
        cudaFuncSetAttribute(gemm_tn, cudaFuncAttributeMaxDynamicSharedMemorySize, GEMM_SMEM);
        cudaFuncSetAttribute(attn_kernel, cudaFuncAttributeMaxDynamicSharedMemorySize, ATT_SMEM);
        inited = 1;
    }

    tohalf_kernel<<<(SEQ * HID / 4) / 256, 256>>>(X, 0, SEQ * HID / 4);
    tohalf_kernel<<<(HID * HID / 4) / 256, 256>>>(Wq, 1, HID * HID / 4);
    tohalf_kernel<<<(HID * HID / 4) / 256, 256>>>(Wk, 2, HID * HID / 4);
    tohalf_kernel<<<(HID * HID / 4) / 256, 256>>>(Wv, 3, HID * HID / 4);
    tohalf_kernel<<<(HID * HID / 4) / 256, 256>>>(Wo, 4, HID * HID / 4);
    rope_table<<<(SEQ * 64) / 256, 256>>>();

    dim3 gqkv(HID / GBN, SEQ / GBM, 3);     // fused Q,K,V projection (fp16)
    gemm_tn<<<gqkv, 256, GEMM_SMEM>>>(1, nullptr);
    rope_apply<<<(SEQ * NHEADS * 64) / 256, 256>>>();

    attn_kernel<<<dim3(SEQ / ABM, NHEADS), 256, ATT_SMEM>>>(0.08838834764831845f);

    dim3 go(HID / GBN, SEQ / GBM, 1);       // output projection (fp16)
    gemm_tn<<<go, 256, GEMM_SMEM>>>(0, out);
}

// round 7
// speedup vs baseline: 2.4281x; 1.3892x over previous
#include <cuda_runtime.h>
#include <cuda_fp16.h>
#include <cstdint>

#define SEQ 4096
#define HID 2048
#define NHEADS 16
#define HD 128

// ---------------- scratch (static device arrays; no allocation) ----------------
static __device__ __half g_Xh[SEQ * HID];
static __device__ __half g_Wqh[HID * HID];
static __device__ __half g_Wkh[HID * HID];
static __device__ __half g_Wvh[HID * HID];
static __device__ __half g_Woh[HID * HID];
static __device__ float  g_Q[SEQ * HID];     // fp32 raw from GEMM, rope -> half
static __device__ float  g_K[SEQ * HID];
static __device__ __half g_Qh[SEQ * HID];
static __device__ __half g_Kh[SEQ * HID];
static __device__ __half g_Vh[SEQ * HID];
static __device__ __half g_ctxh[SEQ * HID];
static __device__ float  g_cos[SEQ * 64];
static __device__ float  g_sin[SEQ * 64];

// ---------------- helpers ----------------
__device__ __forceinline__ void mma_f16(float* c, const uint32_t* a, uint32_t b0, uint32_t b1) {
    asm volatile(
        "mma.sync.aligned.m16n8k16.row.col.f32.f16.f16.f32 "
        "{%0,%1,%2,%3}, {%4,%5,%6,%7}, {%8,%9}, {%0,%1,%2,%3};"
        : "+f"(c[0]), "+f"(c[1]), "+f"(c[2]), "+f"(c[3])
        : "r"(a[0]), "r"(a[1]), "r"(a[2]), "r"(a[3]), "r"(b0), "r"(b1));
}

__device__ __forceinline__ void cpasync16(uint32_t dst, const void* src) {
    asm volatile("cp.async.cg.shared.global [%0], [%1], 16;" :: "r"(dst), "l"(src));
}
__device__ __forceinline__ void cpcommit() { asm volatile("cp.async.commit_group;"); }

__device__ __forceinline__ uint32_t pack2(__half lo, __half hi) {
    return (uint32_t)__half_as_ushort(lo) | ((uint32_t)__half_as_ushort(hi) << 16);
}

// ---------------- prep: fp32 -> fp16 ----------------
__global__ void tohalf_kernel(const float* __restrict__ in, int sel, int n4) {
    int i = blockIdx.x * blockDim.x + threadIdx.x;
    if (i >= n4) return;
    __half* dst = (sel == 0) ? g_Xh : (sel == 1) ? g_Wqh : (sel == 2) ? g_Wkh
                : (sel == 3) ? g_Wvh : g_Woh;
    float4 v = reinterpret_cast<const float4*>(in)[i];
    __half2* p = reinterpret_cast<__half2*>(&dst[4 * i]);
    p[0] = __floats2half2_rn(v.x, v.y);
    p[1] = __floats2half2_rn(v.z, v.w);
}

// ---------------- RoPE ----------------
__global__ void rope_table() {
    int idx = blockIdx.x * blockDim.x + threadIdx.x;
    if (idx >= SEQ * 64) return;
    int s = idx >> 6, j = idx & 63;
    double invf = exp(-(double)j * (9.210340371976184 / 64.0));  // 10000^(-j/64)
    float freq = (float)s * (float)invf;                          // fp32, like the ref
    g_cos[idx] = (float)cos((double)freq);
    g_sin[idx] = (float)sin((double)freq);
}

__global__ void rope_apply() {
    int idx = blockIdx.x * blockDim.x + threadIdx.x;
    if (idx >= SEQ * NHEADS * 64) return;
    int s = idx >> 10;
    int h = (idx >> 6) & (NHEADS - 1);
    int i = idx & 63;
    float c = g_cos[(s << 6) + i], sn = g_sin[(s << 6) + i];
    int base = s * HID + h * HD + i;
    float q1 = g_Q[base], q2 = g_Q[base + 64];
    g_Qh[base]      = __float2half_rn(q1 * c - q2 * sn);
    g_Qh[base + 64] = __float2half_rn(q2 * c + q1 * sn);
    float k1 = g_K[base], k2 = g_K[base + 64];
    g_Kh[base]      = __float2half_rn(k1 * c - k2 * sn);
    g_Kh[base + 64] = __float2half_rn(k2 * c + k1 * sn);
}

// ---------------- GEMM: C[M,N] = A[M,K] @ B[N,K]^T, fp16 mma, GBK=64, 3-stage --
#define GBM 128
#define GBN 128
#define GBK 64
#define GST 3
#define APITCH 72                          // halves
#define AHALFS (GBM * APITCH)              // 9216
#define STGH (2 * AHALFS)                  // 18432 halves = 36864 B
#define GEMM_SMEM (GST * STGH * 2)         // 110592 B

// fused=1: blockIdx.z selects Q/K/V; fused=0: output projection
__global__ void __launch_bounds__(256, 1) gemm_tn(int fused, float* __restrict__ extC) {
    extern __shared__ __half sm[];
    const __half* A; const __half* B;
    float* Cf = nullptr; __half* Ch = nullptr;
    const int N = HID, K = HID;
    int sel = fused ? (int)blockIdx.z : 3;
    if (sel == 0)      { A = g_Xh;   B = g_Wqh; Cf = g_Q; }
    else if (sel == 1) { A = g_Xh;   B = g_Wkh; Cf = g_K; }
    else if (sel == 2) { A = g_Xh;   B = g_Wvh; Ch = g_Vh; }
    else               { A = g_ctxh; B = g_Woh; Cf = extC; }

    int tid = threadIdx.x;
    int lane = tid & 31, wid = tid >> 5;
    int wm = wid & 3, wn = wid >> 2;
    int bm = blockIdx.y * GBM, bn = blockIdx.x * GBN;

    float c[2][8][4];
#pragma unroll
    for (int im = 0; im < 2; im++)
#pragma unroll
        for (int jn = 0; jn < 8; jn++)
#pragma unroll
            for (int q = 0; q < 4; q++) c[im][jn][q] = 0.f;

    const __half* Abase = A + (size_t)bm * K;
    const __half* Bbase = B + (size_t)bn * K;

    uint32_t smb = (uint32_t)__cvta_generic_to_shared(sm);

    int lr = tid >> 3, lc8 = tid & 7;

    auto load_tile = [&](int s, int kt) {
        int koff = kt * GBK + lc8 * 8;
        uint32_t sa = smb + (uint32_t)(s * STGH) * 2;
        uint32_t sb = sa + AHALFS * 2;
        uint32_t doff = (uint32_t)(lr * APITCH + lc8 * 8) * 2;
#pragma unroll
        for (int i = 0; i < 4; i++) {
            int r = lr + 32 * i;
            cpasync16(sa + doff + (uint32_t)(32 * i * APITCH) * 2, Abase + (size_t)r * K + koff);
            cpasync16(sb + doff + (uint32_t)(32 * i * APITCH) * 2, Bbase + (size_t)r * K + koff);
        }
    };

    const int NT = K / GBK;  // 32
    load_tile(0, 0); cpcommit();
    load_tile(1, 1); cpcommit();

    int g = lane >> 2, t = lane & 3;
    int stg = 0;

    for (int kt = 0; kt < NT; kt++) {
        if (kt + 2 < NT) {
            if (kt > 0) __syncthreads();
            int ns = stg + 2; if (ns >= GST) ns -= GST;
            load_tile(ns, kt + 2);
            cpcommit();
            asm volatile("cp.async.wait_group 2;" ::: "memory");
        } else {
            if (kt > 0) __syncthreads();
            asm volatile("cp.async.wait_group 0;" ::: "memory");
        }
        __syncthreads();

        const __half* As = sm + stg * STGH;
        const __half* Bs = As + AHALFS;
#pragma unroll
        for (int ks = 0; ks < 4; ks++) {
            int k0 = ks * 16;
            uint32_t a[2][4], b[8][2];
#pragma unroll
            for (int im = 0; im < 2; im++) {
                int r = wm * 32 + im * 16 + g;
                a[im][0] = *reinterpret_cast<const uint32_t*>(&As[r * APITCH + k0 + 2 * t]);
                a[im][1] = *reinterpret_cast<const uint32_t*>(&As[(r + 8) * APITCH + k0 + 2 * t]);
                a[im][2] = *reinterpret_cast<const uint32_t*>(&As[r * APITCH + k0 + 2 * t + 8]);
                a[im][3] = *reinterpret_cast<const uint32_t*>(&As[(r + 8) * APITCH + k0 + 2 * t + 8]);
            }
#pragma unroll
            for (int jn = 0; jn < 8; jn++) {
                int cc = wn * 64 + jn * 8 + g;
                b[jn][0] = *reinterpret_cast<const uint32_t*>(&Bs[cc * APITCH + k0 + 2 * t]);
                b[jn][1] = *reinterpret_cast<const uint32_t*>(&Bs[cc * APITCH + k0 + 2 * t + 8]);
            }
#pragma unroll
            for (int im = 0; im < 2; im++)
#pragma unroll
                for (int jn = 0; jn < 8; jn++)
                    mma_f16(c[im][jn], a[im], b[jn][0], b[jn][1]);
        }
        if (++stg == GST) stg = 0;
    }

#pragma unroll
    for (int im = 0; im < 2; im++) {
#pragma unroll
        for (int jn = 0; jn < 8; jn++) {
            int r = bm + wm * 32 + im * 16 + g;
            int col = bn + wn * 64 + jn * 8 + 2 * t;
            if (Ch) {
                *reinterpret_cast<__half2*>(&Ch[(size_t)r * N + col]) =
                    __floats2half2_rn(c[im][jn][0], c[im][jn][1]);
                *reinterpret_cast<__half2*>(&Ch[(size_t)(r + 8) * N + col]) =
                    __floats2half2_rn(c[im][jn][2], c[im][jn][3]);
            } else {
                *reinterpret_cast<float2*>(&Cf[(size_t)r * N + col]) =
                    make_float2(c[im][jn][0], c[im][jn][1]);
                *reinterpret_cast<float2*>(&Cf[(size_t)(r + 8) * N + col]) =
                    make_float2(c[im][jn][2], c[im][jn][3]);
            }
        }
    }
}

// ---------------- flash attention (causal), fp16 mma, ABM=128, ABN=64 ----------
#define ABM 128
#define ABN 64
#define KVP 136                           // halves pitch (272 B)
#define KVSTGH (ABN * KVP)                // 8704 halves = 17408 B
#define ATT_SMEM (4 * KVSTGH * 2)         // K[2]+V[2] = 69632 B dynamic
#define PSP 72                            // Ps pitch: 64 keys + 8 pad

__global__ void __launch_bounds__(256) attn_kernel(float scale) {
    extern __shared__ __half kvdyn[];     // [K0, K1, V0, V1]
    __shared__ __half Ps[ABM][PSP];       // probs, warp-local rows

    int tid = threadIdx.x, lane = tid & 31, wid = tid >> 5;
    int g = lane >> 2, t = lane & 3;
    int qt = (int)(gridDim.x - 1 - blockIdx.x);   // heavy tiles first
    int h = blockIdx.y;
    int hoff = h * HD;
    int qrow = qt * ABM + wid * 16;
    int row0 = qrow + g, row1 = row0 + 8;
    int rl0 = wid * 16 + g, rl1 = rl0 + 8;

    uint32_t dynb = (uint32_t)__cvta_generic_to_shared(kvdyn);

    // Q fragments: 8 k16-steps over HD=128 (same mapping as validated GEMM A)
    uint32_t qf[8][4];
#pragma unroll
    for (int s = 0; s < 8; s++) {
        int cb = hoff + s * 16 + 2 * t;
        qf[s][0] = *reinterpret_cast<const uint32_t*>(&g_Qh[(size_t)row0 * HID + cb]);
        qf[s][1] = *reinterpret_cast<const uint32_t*>(&g_Qh[(size_t)row1 * HID + cb]);
        qf[s][2] = *reinterpret_cast<const uint32_t*>(&g_Qh[(size_t)row0 * HID + cb + 8]);
        qf[s][3] = *reinterpret_cast<const uint32_t*>(&g_Qh[(size_t)row1 * HID + cb + 8]);
    }

    float of[16][4];
#pragma unroll
    for (int j = 0; j < 16; j++) { of[j][0] = 0.f; of[j][1] = 0.f; of[j][2] = 0.f; of[j][3] = 0.f; }
    float m0 = -1e30f, m1 = -1e30f, l0 = 0.f, l1 = 0.f;

    // one group = K tile + V tile for one kt (64 keys x 128 dims, halves)
    auto loadKV = [&](int b, int kt) {
        const __half* Kg = g_Kh + (size_t)(kt * ABN) * HID + hoff;
        const __half* Vg = g_Vh + (size_t)(kt * ABN) * HID + hoff;
        uint32_t kb = dynb + (uint32_t)(b * KVSTGH) * 2;
        uint32_t vb = dynb + (uint32_t)((2 + b) * KVSTGH) * 2;
#pragma unroll
        for (int j = 0; j < 4; j++) {
            int cidx = tid + 256 * j;          // 0..1023 = 64 rows x 16 chunks
            int rr = cidx >> 4, c16 = cidx & 15;
            uint32_t off = (uint32_t)(rr * KVP * 2 + c16 * 16);
            cpasync16(kb + off, Kg + (size_t)rr * HID + c16 * 8);
            cpasync16(vb + off, Vg + (size_t)rr * HID + c16 * 8);
        }
    };

    int ktmax = 2 * qt + 1;
    loadKV(0, 0);
    cpcommit();
    int buf = 0;

    for (int kt = 0; kt <= ktmax; kt++) {
        if (kt < ktmax) {
            if (kt > 0) __syncthreads();
            loadKV(buf ^ 1, kt + 1);
            cpcommit();
            asm volatile("cp.async.wait_group 1;" ::: "memory");
        } else {
            if (kt > 0) __syncthreads();
            asm volatile("cp.async.wait_group 0;" ::: "memory");
        }
        __syncthreads();

        const __half* Kb = kvdyn + buf * KVSTGH;
        const __half* Vb = kvdyn + (2 + buf) * KVSTGH;

        // scores: Q (128x128) @ K^T (128x64), per-warp 16x64
        float sf[8][4];
#pragma unroll
        for (int j = 0; j < 8; j++) { sf[j][0] = 0.f; sf[j][1] = 0.f; sf[j][2] = 0.f; sf[j][3] = 0.f; }
#pragma unroll
        for (int s = 0; s < 8; s++) {
#pragma unroll
            for (int j = 0; j < 8; j++) {
                const __half* kr = &Kb[(j * 8 + g) * KVP + s * 16 + 2 * t];
                uint32_t b0 = *reinterpret_cast<const uint32_t*>(kr);
                uint32_t b1 = *reinterpret_cast<const uint32_t*>(kr + 8);
                mma_f16(sf[j], qf[s], b0, b1);
            }
        }

        // scale + causal mask + row max
        float mx0 = -1e30f, mx1 = -1e30f;
#pragma unroll
        for (int j = 0; j < 8; j++) {
            int cg = kt * ABN + j * 8 + 2 * t;
            sf[j][0] = (cg     <= row0) ? sf[j][0] * scale : -1e30f;
            sf[j][1] = (cg + 1 <= row0) ? sf[j][1] * scale : -1e30f;
            sf[j][2] = (cg     <= row1) ? sf[j][2] * scale : -1e30f;
            sf[j][3] = (cg + 1 <= row1) ? sf[j][3] * scale : -1e30f;
            mx0 = fmaxf(mx0, fmaxf(sf[j][0], sf[j][1]));
            mx1 = fmaxf(mx1, fmaxf(sf[j][2], sf[j][3]));
        }
        mx0 = fmaxf(mx0, __shfl_xor_sync(0xffffffffu, mx0, 1));
        mx0 = fmaxf(mx0, __shfl_xor_sync(0xffffffffu, mx0, 2));
        mx1 = fmaxf(mx1, __shfl_xor_sync(0xffffffffu, mx1, 1));
        mx1 = fmaxf(mx1, __shfl_xor_sync(0xffffffffu, mx1, 2));

        float mn0 = fmaxf(m0, mx0), mn1 = fmaxf(m1, mx1);
        float al0 = __expf(m0 - mn0), al1 = __expf(m1 - mn1);

        float rs0 = 0.f, rs1 = 0.f;
#pragma unroll
        for (int j = 0; j < 8; j++) {
            float p0 = __expf(sf[j][0] - mn0);
            float p1 = __expf(sf[j][1] - mn0);
            float p2 = __expf(sf[j][2] - mn1);
            float p3 = __expf(sf[j][3] - mn1);
            rs0 += p0 + p1; rs1 += p2 + p3;
            int cl = j * 8 + 2 * t;
            *reinterpret_cast<__half2*>(&Ps[rl0][cl]) = __floats2half2_rn(p0, p1);
            *reinterpret_cast<__half2*>(&Ps[rl1][cl]) = __floats2half2_rn(p2, p3);
        }
        rs0 += __shfl_xor_sync(0xffffffffu, rs0, 1);
        rs0 += __shfl_xor_sync(0xffffffffu, rs0, 2);
        rs1 += __shfl_xor_sync(0xffffffffu, rs1, 1);
        rs1 += __shfl_xor_sync(0xffffffffu, rs1, 2);
        l0 = l0 * al0 + rs0;
        l1 = l1 * al1 + rs1;
        m0 = mn0; m1 = mn1;
#pragma unroll
        for (int j = 0; j < 16; j++) {
            of[j][0] *= al0; of[j][1] *= al0; of[j][2] *= al1; of[j][3] *= al1;
        }

        // PV: P (128x64) @ V (64x128); Ps rows warp-local, no sync needed.
        // B fragment built element-wise from key-major V tile — direct fp16
        // analog of the validated tf32 mapping: b0 = V[k=2t,2t+1][n=dim],
        // b1 = V[k=2t+8,2t+9][n=dim].
#pragma unroll
        for (int kb = 0; kb < 4; kb++) {
            uint32_t a[4];
            a[0] = *reinterpret_cast<const uint32_t*>(&Ps[rl0][kb * 16 + 2 * t]);
            a[1] = *reinterpret_cast<const uint32_t*>(&Ps[rl1][kb * 16 + 2 * t]);
            a[2] = *reinterpret_cast<const uint32_t*>(&Ps[rl0][kb * 16 + 2 * t + 8]);
            a[3] = *reinterpret_cast<const uint32_t*>(&Ps[rl1][kb * 16 + 2 * t + 8]);
            const __half* v0 = Vb + (kb * 16 + 2 * t) * KVP;
            const __half* v1 = v0 + KVP;
            const __half* v8 = v0 + 8 * KVP;
            const __half* v9 = v0 + 9 * KVP;
#pragma unroll
            for (int jp = 0; jp < 16; jp++) {
                int d = jp * 8 + g;
                uint32_t b0 = pack2(v0[d], v1[d]);
                uint32_t b1 = pack2(v8[d], v9[d]);
                mma_f16(of[jp], a, b0, b1);
            }
        }
        buf ^= 1;
    }

    float inv0 = 1.f / l0, inv1 = 1.f / l1;
#pragma unroll
    for (int j = 0; j < 16; j++) {
        int col = hoff + j * 8 + 2 * t;
        *reinterpret_cast<__half2*>(&g_ctxh[(size_t)row0 * HID + col]) =
            __floats2half2_rn(of[j][0] * inv0, of[j][1] * inv0);
        *reinterpret_cast<__half2*>(&g_ctxh[(size_t)row1 * HID + col]) =
            __floats2half2_rn(of[j][2] * inv1, of[j][3] * inv1);
    }
}

// ---------------- launch ----------------
extern "C" void kernel_launch(void* const* d_in, const int* in_sizes, int n_in,
                              void* d_out, int out_size) {
    const float* X  = (const float*)d_in[0];
    const float* Wq = (const float*)d_in[1];
    const float* Wk = (const float*)d_in[2];
    const float* Wv = (const float*)d_in[3];
    const float* Wo = (const float*)d_in[4];
    float* out = (float*)d_out;

    static int inited = 0;
    if (!inited) {
        cudaFuncSetAttribute(gemm_tn, cudaFuncAttributeMaxDynamicSharedMemorySize, GEMM_SMEM);
        cudaFuncSetAttribute(attn_kernel, cudaFuncAttributeMaxDynamicSharedMemorySize, ATT_SMEM);
        inited = 1;
    }

    tohalf_kernel<<<(SEQ * HID / 4) / 256, 256>>>(X, 0, SEQ * HID / 4);
    tohalf_kernel<<<(HID * HID / 4) / 256, 256>>>(Wq, 1, HID * HID / 4);
    tohalf_kernel<<<(HID * HID / 4) / 256, 256>>>(Wk, 2, HID * HID / 4);
    tohalf_kernel<<<(HID * HID / 4) / 256, 256>>>(Wv, 3, HID * HID / 4);
    tohalf_kernel<<<(HID * HID / 4) / 256, 256>>>(Wo, 4, HID * HID / 4);
    rope_table<<<(SEQ * 64) / 256, 256>>>();

    dim3 gqkv(HID / GBN, SEQ / GBM, 3);     // fused Q,K,V projection (fp16)
    gemm_tn<<<gqkv, 256, GEMM_SMEM>>>(1, nullptr);
    rope_apply<<<(SEQ * NHEADS * 64) / 256, 256>>>();

    attn_kernel<<<dim3(SEQ / ABM, NHEADS), 256, ATT_SMEM>>>(0.08838834764831845f);

    dim3 go(HID / GBN, SEQ / GBM, 1);       // output projection (fp16)
    gemm_tn<<<go, 256, GEMM_SMEM>>>(0, out);
}

// round 8
// speedup vs baseline: 2.5770x; 1.0613x over previous
#include <cuda_runtime.h>
#include <cuda_fp16.h>
#include <cstdint>

#define SEQ 4096
#define HID 2048
#define NHEADS 16
#define HD 128

// ---------------- scratch (static device arrays; no allocation) ----------------
static __device__ __half g_Xh[SEQ * HID];
static __device__ __half g_Wqh[HID * HID];
static __device__ __half g_Wkh[HID * HID];
static __device__ __half g_Wvh[HID * HID];
static __device__ __half g_Woh[HID * HID];
static __device__ float  g_Q[SEQ * HID];     // fp32 raw from GEMM, rope -> half
static __device__ float  g_K[SEQ * HID];
static __device__ __half g_Qh[SEQ * HID];
static __device__ __half g_Kh[SEQ * HID];
static __device__ __half g_Vt[HID * SEQ];    // V TRANSPOSED: [dim][seq]
static __device__ __half g_ctxh[SEQ * HID];
static __device__ float  g_cos[SEQ * 64];
static __device__ float  g_sin[SEQ * 64];

// ---------------- helpers ----------------
__device__ __forceinline__ void mma_f16(float* c, const uint32_t* a, uint32_t b0, uint32_t b1) {
    asm volatile(
        "mma.sync.aligned.m16n8k16.row.col.f32.f16.f16.f32 "
        "{%0,%1,%2,%3}, {%4,%5,%6,%7}, {%8,%9}, {%0,%1,%2,%3};"
        : "+f"(c[0]), "+f"(c[1]), "+f"(c[2]), "+f"(c[3])
        : "r"(a[0]), "r"(a[1]), "r"(a[2]), "r"(a[3]), "r"(b0), "r"(b1));
}

__device__ __forceinline__ void cpasync16(uint32_t dst, const void* src) {
    asm volatile("cp.async.cg.shared.global [%0], [%1], 16;" :: "r"(dst), "l"(src));
}
__device__ __forceinline__ void cpcommit() { asm volatile("cp.async.commit_group;"); }

// ---------------- prep: fp32 -> fp16 ----------------
__global__ void tohalf_kernel(const float* __restrict__ in, int sel, int n4) {
    int i = blockIdx.x * blockDim.x + threadIdx.x;
    if (i >= n4) return;
    __half* dst = (sel == 0) ? g_Xh : (sel == 1) ? g_Wqh : (sel == 2) ? g_Wkh
                : (sel == 3) ? g_Wvh : g_Woh;
    float4 v = reinterpret_cast<const float4*>(in)[i];
    __half2* p = reinterpret_cast<__half2*>(&dst[4 * i]);
    p[0] = __floats2half2_rn(v.x, v.y);
    p[1] = __floats2half2_rn(v.z, v.w);
}

// ---------------- RoPE ----------------
__global__ void rope_table() {
    int idx = blockIdx.x * blockDim.x + threadIdx.x;
    if (idx >= SEQ * 64) return;
    int s = idx >> 6, j = idx & 63;
    double invf = exp(-(double)j * (9.210340371976184 / 64.0));  // 10000^(-j/64)
    float freq = (float)s * (float)invf;                          // fp32, like the ref
    g_cos[idx] = (float)cos((double)freq);
    g_sin[idx] = (float)sin((double)freq);
}

__global__ void rope_apply() {
    int idx = blockIdx.x * blockDim.x + threadIdx.x;
    if (idx >= SEQ * NHEADS * 64) return;
    int s = idx >> 10;
    int h = (idx >> 6) & (NHEADS - 1);
    int i = idx & 63;
    float c = g_cos[(s << 6) + i], sn = g_sin[(s << 6) + i];
    int base = s * HID + h * HD + i;
    float q1 = g_Q[base], q2 = g_Q[base + 64];
    g_Qh[base]      = __float2half_rn(q1 * c - q2 * sn);
    g_Qh[base + 64] = __float2half_rn(q2 * c + q1 * sn);
    float k1 = g_K[base], k2 = g_K[base + 64];
    g_Kh[base]      = __float2half_rn(k1 * c - k2 * sn);
    g_Kh[base + 64] = __float2half_rn(k2 * c + k1 * sn);
}

// ---------------- GEMM: C[M,N] = A[M,K] @ B[N,K]^T, fp16 mma, GBK=64, 3-stage --
#define GBM 128
#define GBN 128
#define GBK 64
#define GST 3
#define APITCH 72                          // halves
#define AHALFS (GBM * APITCH)              // 9216
#define STGH (2 * AHALFS)                  // 18432 halves = 36864 B
#define GEMM_SMEM (GST * STGH * 2)         // 110592 B

// mode 0: fused Q/K (blockIdx.z: 0->Q, 1->K), N=HID, C fp32
// mode 1: V^T = Wv @ X^T, A=Wv, B=X, N=SEQ, C half (g_Vt)
// mode 2: out = ctx @ Wo^T, N=HID, C fp32 (extC)
__global__ void __launch_bounds__(256, 1) gemm_tn(int mode, float* __restrict__ extC) {
    extern __shared__ __half sm[];
    const __half* A; const __half* B;
    float* Cf = nullptr; __half* Ch = nullptr;
    int N;
    const int K = HID;
    if (mode == 0) {
        N = HID;
        if (blockIdx.z == 0) { A = g_Xh; B = g_Wqh; Cf = g_Q; }
        else                 { A = g_Xh; B = g_Wkh; Cf = g_K; }
    } else if (mode == 1) {
        N = SEQ; A = g_Wvh; B = g_Xh; Ch = g_Vt;
    } else {
        N = HID; A = g_ctxh; B = g_Woh; Cf = extC;
    }

    int tid = threadIdx.x;
    int lane = tid & 31, wid = tid >> 5;
    int wm = wid & 3, wn = wid >> 2;
    int bm = blockIdx.y * GBM, bn = blockIdx.x * GBN;

    float c[2][8][4];
#pragma unroll
    for (int im = 0; im < 2; im++)
#pragma unroll
        for (int jn = 0; jn < 8; jn++)
#pragma unroll
            for (int q = 0; q < 4; q++) c[im][jn][q] = 0.f;

    const __half* Abase = A + (size_t)bm * K;
    const __half* Bbase = B + (size_t)bn * K;

    uint32_t smb = (uint32_t)__cvta_generic_to_shared(sm);

    int lr = tid >> 3, lc8 = tid & 7;

    auto load_tile = [&](int s, int kt) {
        int koff = kt * GBK + lc8 * 8;
        uint32_t sa = smb + (uint32_t)(s * STGH) * 2;
        uint32_t sb = sa + AHALFS * 2;
        uint32_t doff = (uint32_t)(lr * APITCH + lc8 * 8) * 2;
#pragma unroll
        for (int i = 0; i < 4; i++) {
            int r = lr + 32 * i;
            cpasync16(sa + doff + (uint32_t)(32 * i * APITCH) * 2, Abase + (size_t)r * K + koff);
            cpasync16(sb + doff + (uint32_t)(32 * i * APITCH) * 2, Bbase + (size_t)r * K + koff);
        }
    };

    const int NT = K / GBK;  // 32
    load_tile(0, 0); cpcommit();
    load_tile(1, 1); cpcommit();

    int g = lane >> 2, t = lane & 3;
    int stg = 0;

    for (int kt = 0; kt < NT; kt++) {
        if (kt + 2 < NT) {
            if (kt > 0) __syncthreads();
            int ns = stg + 2; if (ns >= GST) ns -= GST;
            load_tile(ns, kt + 2);
            cpcommit();
            asm volatile("cp.async.wait_group 2;" ::: "memory");
        } else {
            if (kt > 0) __syncthreads();
            asm volatile("cp.async.wait_group 0;" ::: "memory");
        }
        __syncthreads();

        const __half* As = sm + stg * STGH;
        const __half* Bs = As + AHALFS;
#pragma unroll
        for (int ks = 0; ks < 4; ks++) {
            int k0 = ks * 16;
            uint32_t a[2][4], b[8][2];
#pragma unroll
            for (int im = 0; im < 2; im++) {
                int r = wm * 32 + im * 16 + g;
                a[im][0] = *reinterpret_cast<const uint32_t*>(&As[r * APITCH + k0 + 2 * t]);
                a[im][1] = *reinterpret_cast<const uint32_t*>(&As[(r + 8) * APITCH + k0 + 2 * t]);
                a[im][2] = *reinterpret_cast<const uint32_t*>(&As[r * APITCH + k0 + 2 * t + 8]);
                a[im][3] = *reinterpret_cast<const uint32_t*>(&As[(r + 8) * APITCH + k0 + 2 * t + 8]);
            }
#pragma unroll
            for (int jn = 0; jn < 8; jn++) {
                int cc = wn * 64 + jn * 8 + g;
                b[jn][0] = *reinterpret_cast<const uint32_t*>(&Bs[cc * APITCH + k0 + 2 * t]);
                b[jn][1] = *reinterpret_cast<const uint32_t*>(&Bs[cc * APITCH + k0 + 2 * t + 8]);
            }
#pragma unroll
            for (int im = 0; im < 2; im++)
#pragma unroll
                for (int jn = 0; jn < 8; jn++)
                    mma_f16(c[im][jn], a[im], b[jn][0], b[jn][1]);
        }
        if (++stg == GST) stg = 0;
    }

#pragma unroll
    for (int im = 0; im < 2; im++) {
#pragma unroll
        for (int jn = 0; jn < 8; jn++) {
            int r = bm + wm * 32 + im * 16 + g;
            int col = bn + wn * 64 + jn * 8 + 2 * t;
            if (Ch) {
                *reinterpret_cast<__half2*>(&Ch[(size_t)r * N + col]) =
                    __floats2half2_rn(c[im][jn][0], c[im][jn][1]);
                *reinterpret_cast<__half2*>(&Ch[(size_t)(r + 8) * N + col]) =
                    __floats2half2_rn(c[im][jn][2], c[im][jn][3]);
            } else {
                *reinterpret_cast<float2*>(&Cf[(size_t)r * N + col]) =
                    make_float2(c[im][jn][0], c[im][jn][1]);
                *reinterpret_cast<float2*>(&Cf[(size_t)(r + 8) * N + col]) =
                    make_float2(c[im][jn][2], c[im][jn][3]);
            }
        }
    }
}

// ---------------- flash attention (causal), fp16 mma, ABM=128, ABN=64 ----------
// K tile: [64 keys][128 dims+pad], pitch 136. V tile: TRANSPOSED [128 dims][64 keys+pad], pitch 72.
#define ABM 128
#define ABN 64
#define KVP 136                            // K tile pitch (halves)
#define KSTGH (ABN * KVP)                  // 8704 halves
#define VPITCH 72                          // V^T tile pitch (halves)
#define VSTGH (HD * VPITCH)                // 9216 halves
#define ATT_SMEM ((2 * KSTGH + 2 * VSTGH) * 2)  // 71680 B dynamic
#define PSP 72                             // Ps pitch: 64 keys + 8 pad

__global__ void __launch_bounds__(256) attn_kernel(float scale) {
    extern __shared__ __half kvdyn[];      // [K0, K1, V0, V1]
    __shared__ __half Ps[ABM][PSP];        // probs, warp-local rows

    int tid = threadIdx.x, lane = tid & 31, wid = tid >> 5;
    int g = lane >> 2, t = lane & 3;
    int qt = (int)(gridDim.x - 1 - blockIdx.x);   // heavy tiles first
    int h = blockIdx.y;
    int hoff = h * HD;
    int qrow = qt * ABM + wid * 16;
    int row0 = qrow + g, row1 = row0 + 8;
    int rl0 = wid * 16 + g, rl1 = rl0 + 8;

    uint32_t dynb = (uint32_t)__cvta_generic_to_shared(kvdyn);

    // Q fragments: 8 k16-steps over HD=128
    uint32_t qf[8][4];
#pragma unroll
    for (int s = 0; s < 8; s++) {
        int cb = hoff + s * 16 + 2 * t;
        qf[s][0] = *reinterpret_cast<const uint32_t*>(&g_Qh[(size_t)row0 * HID + cb]);
        qf[s][1] = *reinterpret_cast<const uint32_t*>(&g_Qh[(size_t)row1 * HID + cb]);
        qf[s][2] = *reinterpret_cast<const uint32_t*>(&g_Qh[(size_t)row0 * HID + cb + 8]);
        qf[s][3] = *reinterpret_cast<const uint32_t*>(&g_Qh[(size_t)row1 * HID + cb + 8]);
    }

    float of[16][4];
#pragma unroll
    for (int j = 0; j < 16; j++) { of[j][0] = 0.f; of[j][1] = 0.f; of[j][2] = 0.f; of[j][3] = 0.f; }
    float m0 = -1e30f, m1 = -1e30f, l0 = 0.f, l1 = 0.f;

    // one group: K tile (64 keys x 128 dims) + V^T tile (128 dims x 64 keys)
    auto loadKV = [&](int b, int kt) {
        const __half* Kg = g_Kh + (size_t)(kt * ABN) * HID + hoff;
        const __half* Vg = g_Vt + (size_t)hoff * SEQ + kt * ABN;
        uint32_t kb = dynb + (uint32_t)(b * KSTGH) * 2;
        uint32_t vb = dynb + (uint32_t)(2 * KSTGH + b * VSTGH) * 2;
#pragma unroll
        for (int j = 0; j < 4; j++) {       // K: 64 rows x 16 chunks
            int cidx = tid + 256 * j;
            int rr = cidx >> 4, c = cidx & 15;
            cpasync16(kb + (uint32_t)(rr * KVP + c * 8) * 2, Kg + (size_t)rr * HID + c * 8);
        }
#pragma unroll
        for (int j = 0; j < 4; j++) {       // V^T: 128 rows x 8 chunks
            int cidx = tid + 256 * j;
            int rr = cidx >> 3, c = cidx & 7;
            cpasync16(vb + (uint32_t)(rr * VPITCH + c * 8) * 2, Vg + (size_t)rr * SEQ + c * 8);
        }
    };

    int ktmax = 2 * qt + 1;
    loadKV(0, 0);
    cpcommit();
    int buf = 0;

    for (int kt = 0; kt <= ktmax; kt++) {
        if (kt < ktmax) {
            if (kt > 0) __syncthreads();
            loadKV(buf ^ 1, kt + 1);
            cpcommit();
            asm volatile("cp.async.wait_group 1;" ::: "memory");
        } else {
            if (kt > 0) __syncthreads();
            asm volatile("cp.async.wait_group 0;" ::: "memory");
        }
        __syncthreads();

        const __half* Kb  = kvdyn + buf * KSTGH;
        const __half* Vts = kvdyn + 2 * KSTGH + buf * VSTGH;

        // scores: Q (128x128) @ K^T (128x64), per-warp 16x64
        float sf[8][4];
#pragma unroll
        for (int j = 0; j < 8; j++) { sf[j][0] = 0.f; sf[j][1] = 0.f; sf[j][2] = 0.f; sf[j][3] = 0.f; }
#pragma unroll
        for (int s = 0; s < 8; s++) {
#pragma unroll
            for (int j = 0; j < 8; j++) {
                const __half* kr = &Kb[(j * 8 + g) * KVP + s * 16 + 2 * t];
                uint32_t b0 = *reinterpret_cast<const uint32_t*>(kr);
                uint32_t b1 = *reinterpret_cast<const uint32_t*>(kr + 8);
                mma_f16(sf[j], qf[s], b0, b1);
            }
        }

        // scale + causal mask + row max
        float mx0 = -1e30f, mx1 = -1e30f;
#pragma unroll
        for (int j = 0; j < 8; j++) {
            int cg = kt * ABN + j * 8 + 2 * t;
            sf[j][0] = (cg     <= row0) ? sf[j][0] * scale : -1e30f;
            sf[j][1] = (cg + 1 <= row0) ? sf[j][1] * scale : -1e30f;
            sf[j][2] = (cg     <= row1) ? sf[j][2] * scale : -1e30f;
            sf[j][3] = (cg + 1 <= row1) ? sf[j][3] * scale : -1e30f;
            mx0 = fmaxf(mx0, fmaxf(sf[j][0], sf[j][1]));
            mx1 = fmaxf(mx1, fmaxf(sf[j][2], sf[j][3]));
        }
        mx0 = fmaxf(mx0, __shfl_xor_sync(0xffffffffu, mx0, 1));
        mx0 = fmaxf(mx0, __shfl_xor_sync(0xffffffffu, mx0, 2));
        mx1 = fmaxf(mx1, __shfl_xor_sync(0xffffffffu, mx1, 1));
        mx1 = fmaxf(mx1, __shfl_xor_sync(0xffffffffu, mx1, 2));

        float mn0 = fmaxf(m0, mx0), mn1 = fmaxf(m1, mx1);
        float al0 = __expf(m0 - mn0), al1 = __expf(m1 - mn1);

        float rs0 = 0.f, rs1 = 0.f;
#pragma unroll
        for (int j = 0; j < 8; j++) {
            float p0 = __expf(sf[j][0] - mn0);
            float p1 = __expf(sf[j][1] - mn0);
            float p2 = __expf(sf[j][2] - mn1);
            float p3 = __expf(sf[j][3] - mn1);
            rs0 += p0 + p1; rs1 += p2 + p3;
            int cl = j * 8 + 2 * t;
            *reinterpret_cast<__half2*>(&Ps[rl0][cl]) = __floats2half2_rn(p0, p1);
            *reinterpret_cast<__half2*>(&Ps[rl1][cl]) = __floats2half2_rn(p2, p3);
        }
        rs0 += __shfl_xor_sync(0xffffffffu, rs0, 1);
        rs0 += __shfl_xor_sync(0xffffffffu, rs0, 2);
        rs1 += __shfl_xor_sync(0xffffffffu, rs1, 1);
        rs1 += __shfl_xor_sync(0xffffffffu, rs1, 2);
        l0 = l0 * al0 + rs0;
        l1 = l1 * al1 + rs1;
        m0 = mn0; m1 = mn1;
#pragma unroll
        for (int j = 0; j < 16; j++) {
            of[j][0] *= al0; of[j][1] *= al0; of[j][2] *= al1; of[j][3] *= al1;
        }

        // PV: P (128x64) @ V (64x128); V^T tile is dim-major, so B-fragments are
        // two LDS.32 per mma — same validated pattern as the K path.
#pragma unroll
        for (int kb = 0; kb < 4; kb++) {
            uint32_t a[4];
            a[0] = *reinterpret_cast<const uint32_t*>(&Ps[rl0][kb * 16 + 2 * t]);
            a[1] = *reinterpret_cast<const uint32_t*>(&Ps[rl1][kb * 16 + 2 * t]);
            a[2] = *reinterpret_cast<const uint32_t*>(&Ps[rl0][kb * 16 + 2 * t + 8]);
            a[3] = *reinterpret_cast<const uint32_t*>(&Ps[rl1][kb * 16 + 2 * t + 8]);
#pragma unroll
            for (int jp = 0; jp < 16; jp++) {
                const __half* vr = &Vts[(jp * 8 + g) * VPITCH + kb * 16 + 2 * t];
                uint32_t b0 = *reinterpret_cast<const uint32_t*>(vr);
                uint32_t b1 = *reinterpret_cast<const uint32_t*>(vr + 8);
                mma_f16(of[jp], a, b0, b1);
            }
        }
        buf ^= 1;
    }

    float inv0 = 1.f / l0, inv1 = 1.f / l1;
#pragma unroll
    for (int j = 0; j < 16; j++) {
        int col = hoff + j * 8 + 2 * t;
        *reinterpret_cast<__half2*>(&g_ctxh[(size_t)row0 * HID + col]) =
            __floats2half2_rn(of[j][0] * inv0, of[j][1] * inv0);
        *reinterpret_cast<__half2*>(&g_ctxh[(size_t)row1 * HID + col]) =
            __floats2half2_rn(of[j][2] * inv1, of[j][3] * inv1);
    }
}

// ---------------- launch ----------------
extern "C" void kernel_launch(void* const* d_in, const int* in_sizes, int n_in,
                              void* d_out, int out_size) {
    const float* X  = (const float*)d_in[0];
    const float* Wq = (const float*)d_in[1];
    const float* Wk = (const float*)d_in[2];
    const float* Wv = (const float*)d_in[3];
    const float* Wo = (const float*)d_in[4];
    float* out = (float*)d_out;

    static int inited = 0;
    if (!inited) {
        cudaFuncSetAttribute(gemm_tn, cudaFuncAttributeMaxDynamicSharedMemorySize, GEMM_SMEM);
        cudaFuncSetAttribute(attn_kernel, cudaFuncAttributeMaxDynamicSharedMemorySize, ATT_SMEM);
        inited = 1;
    }

    tohalf_kernel<<<(SEQ * HID / 4) / 256, 256>>>(X, 0, SEQ * HID / 4);
    tohalf_kernel<<<(HID * HID / 4) / 256, 256>>>(Wq, 1, HID * HID / 4);
    tohalf_kernel<<<(HID * HID / 4) / 256, 256>>>(Wk, 2, HID * HID / 4);
    tohalf_kernel<<<(HID * HID / 4) / 256, 256>>>(Wv, 3, HID * HID / 4);
    tohalf_kernel<<<(HID * HID / 4) / 256, 256>>>(Wo, 4, HID * HID / 4);
    rope_table<<<(SEQ * 64) / 256, 256>>>();

    dim3 gqk(HID / GBN, SEQ / GBM, 2);      // fused Q,K projection
    gemm_tn<<<gqk, 256, GEMM_SMEM>>>(0, nullptr);
    dim3 gv(SEQ / GBN, HID / GBM, 1);       // V^T = Wv @ X^T
    gemm_tn<<<gv, 256, GEMM_SMEM>>>(1, nullptr);
    rope_apply<<<(SEQ * NHEADS * 64) / 256, 256>>>();

    attn_kernel<<<dim3(SEQ / ABM, NHEADS), 256, ATT_SMEM>>>(0.08838834764831845f);

    dim3 go(HID / GBN, SEQ / GBM, 1);       // output projection
    gemm_tn<<<go, 256, GEMM_SMEM>>>(2, out);
}

// round 9
// speedup vs baseline: 2.6201x; 1.0167x over previous
#include <cuda_runtime.h>
#include <cuda_fp16.h>
#include <cstdint>

#define SEQ 4096
#define HID 2048
#define NHEADS 16
#define HD 128

// ---------------- scratch (static device arrays; no allocation) ----------------
static __device__ __half g_Xh[SEQ * HID];
static __device__ __half g_Wqh[HID * HID];
static __device__ __half g_Wkh[HID * HID];
static __device__ __half g_Wvh[HID * HID];
static __device__ __half g_Woh[HID * HID];
static __device__ __half g_Qh[SEQ * HID];
static __device__ __half g_Kh[SEQ * HID];
static __device__ __half g_Vt[HID * SEQ];    // V TRANSPOSED: [dim][seq]
static __device__ __half g_ctxh[SEQ * HID];
static __device__ float  g_cos[SEQ * 64];
static __device__ float  g_sin[SEQ * 64];

// ---------------- helpers ----------------
__device__ __forceinline__ void mma_f16(float* c, const uint32_t* a, uint32_t b0, uint32_t b1) {
    asm volatile(
        "mma.sync.aligned.m16n8k16.row.col.f32.f16.f16.f32 "
        "{%0,%1,%2,%3}, {%4,%5,%6,%7}, {%8,%9}, {%0,%1,%2,%3};"
        : "+f"(c[0]), "+f"(c[1]), "+f"(c[2]), "+f"(c[3])
        : "r"(a[0]), "r"(a[1]), "r"(a[2]), "r"(a[3]), "r"(b0), "r"(b1));
}

__device__ __forceinline__ void cpasync16(uint32_t dst, const void* src) {
    asm volatile("cp.async.cg.shared.global [%0], [%1], 16;" :: "r"(dst), "l"(src));
}
__device__ __forceinline__ void cpcommit() { asm volatile("cp.async.commit_group;"); }

__device__ __forceinline__ uint32_t h2u(__half2 h) {
    return *reinterpret_cast<uint32_t*>(&h);
}

// ---------------- prep: fp32 -> fp16, all five tensors in one launch ----------
#define NX (SEQ * HID / 4)
#define NW (HID * HID / 4)
__global__ void tohalf_all(const float* __restrict__ X,  const float* __restrict__ Wq,
                           const float* __restrict__ Wk, const float* __restrict__ Wv,
                           const float* __restrict__ Wo) {
    int i = blockIdx.x * blockDim.x + threadIdx.x;
    const float* src; __half* dst; int off;
    if (i < NX)               { src = X;  dst = g_Xh;  off = i; }
    else if (i < NX + NW)     { src = Wq; dst = g_Wqh; off = i - NX; }
    else if (i < NX + 2 * NW) { src = Wk; dst = g_Wkh; off = i - NX - NW; }
    else if (i < NX + 3 * NW) { src = Wv; dst = g_Wvh; off = i - NX - 2 * NW; }
    else                      { src = Wo; dst = g_Woh; off = i - NX - 3 * NW; }
    float4 v = reinterpret_cast<const float4*>(src)[off];
    __half2* p = reinterpret_cast<__half2*>(&dst[4 * off]);
    p[0] = __floats2half2_rn(v.x, v.y);
    p[1] = __floats2half2_rn(v.z, v.w);
}

// ---------------- RoPE tables ----------------
__global__ void rope_table() {
    int idx = blockIdx.x * blockDim.x + threadIdx.x;
    if (idx >= SEQ * 64) return;
    int s = idx >> 6, j = idx & 63;
    double invf = exp(-(double)j * (9.210340371976184 / 64.0));  // 10000^(-j/64)
    float freq = (float)s * (float)invf;                          // fp32, like the ref
    g_cos[idx] = (float)cos((double)freq);
    g_sin[idx] = (float)sin((double)freq);
}

// ---------------- GEMM: C[M,N] = A[M,K] @ B[N,K]^T, fp16 mma, GBK=64, 3-stage --
// mode 0: fused Q/K (blockIdx.z: 0->Q, 1->K), rope applied in epilogue -> half
// mode 1: V^T = Wv @ X^T, N=SEQ, C half (g_Vt)
// mode 2: out = ctx @ Wo^T, N=HID, C fp32 (extC)
#define GBM 128
#define GBN 128
#define GBK 64
#define GST 3
#define APITCH 72                          // halves
#define AHALFS (GBM * APITCH)              // 9216
#define STGH (2 * AHALFS)                  // 18432 halves = 36864 B
#define GEMM_SMEM (GST * STGH * 2)         // 110592 B
#define CPITCH 132                         // fp32 epilogue staging pitch

__global__ void __launch_bounds__(256, 1) gemm_tn(int mode, float* __restrict__ extC) {
    extern __shared__ __half sm[];
    const __half* A; const __half* B;
    float* Cf = nullptr; __half* Ch = nullptr;
    int N;
    const int K = HID;
    if (mode == 0) {
        N = HID;
        A = g_Xh;
        B = (blockIdx.z == 0) ? g_Wqh : g_Wkh;
    } else if (mode == 1) {
        N = SEQ; A = g_Wvh; B = g_Xh; Ch = g_Vt;
    } else {
        N = HID; A = g_ctxh; B = g_Woh; Cf = extC;
    }

    int tid = threadIdx.x;
    int lane = tid & 31, wid = tid >> 5;
    int wm = wid & 3, wn = wid >> 2;
    int bm = blockIdx.y * GBM, bn = blockIdx.x * GBN;

    float c[2][8][4];
#pragma unroll
    for (int im = 0; im < 2; im++)
#pragma unroll
        for (int jn = 0; jn < 8; jn++)
#pragma unroll
            for (int q = 0; q < 4; q++) c[im][jn][q] = 0.f;

    const __half* Abase = A + (size_t)bm * K;
    const __half* Bbase = B + (size_t)bn * K;

    uint32_t smb = (uint32_t)__cvta_generic_to_shared(sm);

    int lr = tid >> 3, lc8 = tid & 7;

    auto load_tile = [&](int s, int kt) {
        int koff = kt * GBK + lc8 * 8;
        uint32_t sa = smb + (uint32_t)(s * STGH) * 2;
        uint32_t sb = sa + AHALFS * 2;
        uint32_t doff = (uint32_t)(lr * APITCH + lc8 * 8) * 2;
#pragma unroll
        for (int i = 0; i < 4; i++) {
            int r = lr + 32 * i;
            cpasync16(sa + doff + (uint32_t)(32 * i * APITCH) * 2, Abase + (size_t)r * K + koff);
            cpasync16(sb + doff + (uint32_t)(32 * i * APITCH) * 2, Bbase + (size_t)r * K + koff);
        }
    };

    const int NT = K / GBK;  // 32
    load_tile(0, 0); cpcommit();
    load_tile(1, 1); cpcommit();

    int g = lane >> 2, t = lane & 3;
    int stg = 0;

    for (int kt = 0; kt < NT; kt++) {
        if (kt + 2 < NT) {
            if (kt > 0) __syncthreads();
            int ns = stg + 2; if (ns >= GST) ns -= GST;
            load_tile(ns, kt + 2);
            cpcommit();
            asm volatile("cp.async.wait_group 2;" ::: "memory");
        } else {
            if (kt > 0) __syncthreads();
            asm volatile("cp.async.wait_group 0;" ::: "memory");
        }
        __syncthreads();

        const __half* As = sm + stg * STGH;
        const __half* Bs = As + AHALFS;
#pragma unroll
        for (int ks = 0; ks < 4; ks++) {
            int k0 = ks * 16;
            uint32_t a[2][4], b[8][2];
#pragma unroll
            for (int im = 0; im < 2; im++) {
                int r = wm * 32 + im * 16 + g;
                a[im][0] = *reinterpret_cast<const uint32_t*>(&As[r * APITCH + k0 + 2 * t]);
                a[im][1] = *reinterpret_cast<const uint32_t*>(&As[(r + 8) * APITCH + k0 + 2 * t]);
                a[im][2] = *reinterpret_cast<const uint32_t*>(&As[r * APITCH + k0 + 2 * t + 8]);
                a[im][3] = *reinterpret_cast<const uint32_t*>(&As[(r + 8) * APITCH + k0 + 2 * t + 8]);
            }
#pragma unroll
            for (int jn = 0; jn < 8; jn++) {
                int cc = wn * 64 + jn * 8 + g;
                b[jn][0] = *reinterpret_cast<const uint32_t*>(&Bs[cc * APITCH + k0 + 2 * t]);
                b[jn][1] = *reinterpret_cast<const uint32_t*>(&Bs[cc * APITCH + k0 + 2 * t + 8]);
            }
#pragma unroll
            for (int im = 0; im < 2; im++)
#pragma unroll
                for (int jn = 0; jn < 8; jn++)
                    mma_f16(c[im][jn], a[im], b[jn][0], b[jn][1]);
        }
        if (++stg == GST) stg = 0;
    }

    if (mode == 0) {
        // ---- fused RoPE epilogue: stage fp32 C in smem, pair (i, i+64), write half
        __syncthreads();                       // mainloop smem reads done
        float* cs = reinterpret_cast<float*>(sm);
#pragma unroll
        for (int im = 0; im < 2; im++)
#pragma unroll
            for (int jn = 0; jn < 8; jn++) {
                int r = wm * 32 + im * 16 + g;
                int lc = wn * 64 + jn * 8 + 2 * t;
                cs[r * CPITCH + lc]           = c[im][jn][0];
                cs[r * CPITCH + lc + 1]       = c[im][jn][1];
                cs[(r + 8) * CPITCH + lc]     = c[im][jn][2];
                cs[(r + 8) * CPITCH + lc + 1] = c[im][jn][3];
            }
        __syncthreads();
        __half* dst = (blockIdx.z == 0) ? g_Qh : g_Kh;
        int r = tid >> 1;
        int i0 = (tid & 1) * 32;
        int s = bm + r;
        const float* crow = cs + r * CPITCH;
#pragma unroll
        for (int ii = 0; ii < 32; ii += 4) {
            int i = i0 + ii;
            float4 x1 = *reinterpret_cast<const float4*>(&crow[i]);
            float4 x2 = *reinterpret_cast<const float4*>(&crow[i + 64]);
            float4 co = *reinterpret_cast<const float4*>(&g_cos[s * 64 + i]);
            float4 si = *reinterpret_cast<const float4*>(&g_sin[s * 64 + i]);
            __half2* d1 = reinterpret_cast<__half2*>(&dst[(size_t)s * HID + bn + i]);
            __half2* d2 = reinterpret_cast<__half2*>(&dst[(size_t)s * HID + bn + 64 + i]);
            d1[0] = __floats2half2_rn(x1.x * co.x - x2.x * si.x, x1.y * co.y - x2.y * si.y);
            d1[1] = __floats2half2_rn(x1.z * co.z - x2.z * si.z, x1.w * co.w - x2.w * si.w);
            d2[0] = __floats2half2_rn(x2.x * co.x + x1.x * si.x, x2.y * co.y + x1.y * si.y);
            d2[1] = __floats2half2_rn(x2.z * co.z + x1.z * si.z, x2.w * co.w + x1.w * si.w);
        }
        return;
    }

#pragma unroll
    for (int im = 0; im < 2; im++) {
#pragma unroll
        for (int jn = 0; jn < 8; jn++) {
            int r = bm + wm * 32 + im * 16 + g;
            int col = bn + wn * 64 + jn * 8 + 2 * t;
            if (Ch) {
                *reinterpret_cast<__half2*>(&Ch[(size_t)r * N + col]) =
                    __floats2half2_rn(c[im][jn][0], c[im][jn][1]);
                *reinterpret_cast<__half2*>(&Ch[(size_t)(r + 8) * N + col]) =
                    __floats2half2_rn(c[im][jn][2], c[im][jn][3]);
            } else {
                *reinterpret_cast<float2*>(&Cf[(size_t)r * N + col]) =
                    make_float2(c[im][jn][0], c[im][jn][1]);
                *reinterpret_cast<float2*>(&Cf[(size_t)(r + 8) * N + col]) =
                    make_float2(c[im][jn][2], c[im][jn][3]);
            }
        }
    }
}

// ---------------- flash attention (causal), fp16 mma, P kept in registers ------
#define ABM 128
#define ABN 64
#define KVP 136                            // K tile pitch (halves)
#define KSTGH (ABN * KVP)                  // 8704 halves
#define VPITCH 72                          // V^T tile pitch (halves)
#define VSTGH (HD * VPITCH)                // 9216 halves
#define ATT_SMEM ((2 * KSTGH + 2 * VSTGH) * 2)  // 71680 B dynamic

__global__ void __launch_bounds__(256) attn_kernel(float scale) {
    extern __shared__ __half kvdyn[];      // [K0, K1, V0, V1]

    int tid = threadIdx.x, lane = tid & 31, wid = tid >> 5;
    int g = lane >> 2, t = lane & 3;
    int qt = (int)(gridDim.x - 1 - blockIdx.x);   // heavy tiles first
    int h = blockIdx.y;
    int hoff = h * HD;
    int qrow = qt * ABM + wid * 16;
    int row0 = qrow + g, row1 = row0 + 8;

    uint32_t dynb = (uint32_t)__cvta_generic_to_shared(kvdyn);

    // Q fragments: 8 k16-steps over HD=128
    uint32_t qf[8][4];
#pragma unroll
    for (int s = 0; s < 8; s++) {
        int cb = hoff + s * 16 + 2 * t;
        qf[s][0] = *reinterpret_cast<const uint32_t*>(&g_Qh[(size_t)row0 * HID + cb]);
        qf[s][1] = *reinterpret_cast<const uint32_t*>(&g_Qh[(size_t)row1 * HID + cb]);
        qf[s][2] = *reinterpret_cast<const uint32_t*>(&g_Qh[(size_t)row0 * HID + cb + 8]);
        qf[s][3] = *reinterpret_cast<const uint32_t*>(&g_Qh[(size_t)row1 * HID + cb + 8]);
    }

    float of[16][4];
#pragma unroll
    for (int j = 0; j < 16; j++) { of[j][0] = 0.f; of[j][1] = 0.f; of[j][2] = 0.f; of[j][3] = 0.f; }
    float m0 = -1e30f, m1 = -1e30f, l0 = 0.f, l1 = 0.f;

    auto loadKV = [&](int b, int kt) {
        const __half* Kg = g_Kh + (size_t)(kt * ABN) * HID + hoff;
        const __half* Vg = g_Vt + (size_t)hoff * SEQ + kt * ABN;
        uint32_t kb = dynb + (uint32_t)(b * KSTGH) * 2;
        uint32_t vb = dynb + (uint32_t)(2 * KSTGH + b * VSTGH) * 2;
#pragma unroll
        for (int j = 0; j < 4; j++) {       // K: 64 rows x 16 chunks
            int cidx = tid + 256 * j;
            int rr = cidx >> 4, c = cidx & 15;
            cpasync16(kb + (uint32_t)(rr * KVP + c * 8) * 2, Kg + (size_t)rr * HID + c * 8);
        }
#pragma unroll
        for (int j = 0; j < 4; j++) {       // V^T: 128 rows x 8 chunks
            int cidx = tid + 256 * j;
            int rr = cidx >> 3, c = cidx & 7;
            cpasync16(vb + (uint32_t)(rr * VPITCH + c * 8) * 2, Vg + (size_t)rr * SEQ + c * 8);
        }
    };

    int ktmax = 2 * qt + 1;
    loadKV(0, 0);
    cpcommit();
    int buf = 0;

    for (int kt = 0; kt <= ktmax; kt++) {
        if (kt < ktmax) {
            if (kt > 0) __syncthreads();
            loadKV(buf ^ 1, kt + 1);
            cpcommit();
            asm volatile("cp.async.wait_group 1;" ::: "memory");
        } else {
            if (kt > 0) __syncthreads();
            asm volatile("cp.async.wait_group 0;" ::: "memory");
        }
        __syncthreads();

        const __half* Kb  = kvdyn + buf * KSTGH;
        const __half* Vts = kvdyn + 2 * KSTGH + buf * VSTGH;

        // scores: Q (128x128) @ K^T (128x64), per-warp 16x64
        float sf[8][4];
#pragma unroll
        for (int j = 0; j < 8; j++) { sf[j][0] = 0.f; sf[j][1] = 0.f; sf[j][2] = 0.f; sf[j][3] = 0.f; }
#pragma unroll
        for (int s = 0; s < 8; s++) {
#pragma unroll
            for (int j = 0; j < 8; j++) {
                const __half* kr = &Kb[(j * 8 + g) * KVP + s * 16 + 2 * t];
                uint32_t b0 = *reinterpret_cast<const uint32_t*>(kr);
                uint32_t b1 = *reinterpret_cast<const uint32_t*>(kr + 8);
                mma_f16(sf[j], qf[s], b0, b1);
            }
        }

        // scale + causal mask + row max
        float mx0 = -1e30f, mx1 = -1e30f;
#pragma unroll
        for (int j = 0; j < 8; j++) {
            int cg = kt * ABN + j * 8 + 2 * t;
            sf[j][0] = (cg     <= row0) ? sf[j][0] * scale : -1e30f;
            sf[j][1] = (cg + 1 <= row0) ? sf[j][1] * scale : -1e30f;
            sf[j][2] = (cg     <= row1) ? sf[j][2] * scale : -1e30f;
            sf[j][3] = (cg + 1 <= row1) ? sf[j][3] * scale : -1e30f;
            mx0 = fmaxf(mx0, fmaxf(sf[j][0], sf[j][1]));
            mx1 = fmaxf(mx1, fmaxf(sf[j][2], sf[j][3]));
        }
        mx0 = fmaxf(mx0, __shfl_xor_sync(0xffffffffu, mx0, 1));
        mx0 = fmaxf(mx0, __shfl_xor_sync(0xffffffffu, mx0, 2));
        mx1 = fmaxf(mx1, __shfl_xor_sync(0xffffffffu, mx1, 1));
        mx1 = fmaxf(mx1, __shfl_xor_sync(0xffffffffu, mx1, 2));

        float mn0 = fmaxf(m0, mx0), mn1 = fmaxf(m1, mx1);
        float al0 = __expf(m0 - mn0), al1 = __expf(m1 - mn1);

        // exp + pack P directly into PV A-fragments (C-frag and A-frag layouts match)
        uint32_t p01[8], p23[8];
        float rs0 = 0.f, rs1 = 0.f;
#pragma unroll
        for (int j = 0; j < 8; j++) {
            float p0 = __expf(sf[j][0] - mn0);
            float p1 = __expf(sf[j][1] - mn0);
            float p2 = __expf(sf[j][2] - mn1);
            float p3 = __expf(sf[j][3] - mn1);
            rs0 += p0 + p1; rs1 += p2 + p3;
            p01[j] = h2u(__floats2half2_rn(p0, p1));
            p23[j] = h2u(__floats2half2_rn(p2, p3));
        }
        rs0 += __shfl_xor_sync(0xffffffffu, rs0, 1);
        rs0 += __shfl_xor_sync(0xffffffffu, rs0, 2);
        rs1 += __shfl_xor_sync(0xffffffffu, rs1, 1);
        rs1 += __shfl_xor_sync(0xffffffffu, rs1, 2);
        l0 = l0 * al0 + rs0;
        l1 = l1 * al1 + rs1;
        m0 = mn0; m1 = mn1;
#pragma unroll
        for (int j = 0; j < 16; j++) {
            of[j][0] *= al0; of[j][1] *= al0; of[j][2] *= al1; of[j][3] *= al1;
        }

        // PV: P (128x64) @ V (64x128); A-fragments straight from registers,
        // B-fragments two LDS.32 from dim-major V^T tile.
#pragma unroll
        for (int kb = 0; kb < 4; kb++) {
            uint32_t a[4];
            a[0] = p01[2 * kb];
            a[1] = p23[2 * kb];
            a[2] = p01[2 * kb + 1];
            a[3] = p23[2 * kb + 1];
#pragma unroll
            for (int jp = 0; jp < 16; jp++) {
                const __half* vr = &Vts[(jp * 8 + g) * VPITCH + kb * 16 + 2 * t];
                uint32_t b0 = *reinterpret_cast<const uint32_t*>(vr);
                uint32_t b1 = *reinterpret_cast<const uint32_t*>(vr + 8);
                mma_f16(of[jp], a, b0, b1);
            }
        }
        buf ^= 1;
    }

    float inv0 = 1.f / l0, inv1 = 1.f / l1;
#pragma unroll
    for (int j = 0; j < 16; j++) {
        int col = hoff + j * 8 + 2 * t;
        *reinterpret_cast<__half2*>(&g_ctxh[(size_t)row0 * HID + col]) =
            __floats2half2_rn(of[j][0] * inv0, of[j][1] * inv0);
        *reinterpret_cast<__half2*>(&g_ctxh[(size_t)row1 * HID + col]) =
            __floats2half2_rn(of[j][2] * inv1, of[j][3] * inv1);
    }
}

// ---------------- launch ----------------
extern "C" void kernel_launch(void* const* d_in, const int* in_sizes, int n_in,
                              void* d_out, int out_size) {
    const float* X  = (const float*)d_in[0];
    const float* Wq = (const float*)d_in[1];
    const float* Wk = (const float*)d_in[2];
    const float* Wv = (const float*)d_in[3];
    const float* Wo = (const float*)d_in[4];
    float* out = (float*)d_out;

    static int inited = 0;
    if (!inited) {
        cudaFuncSetAttribute(gemm_tn, cudaFuncAttributeMaxDynamicSharedMemorySize, GEMM_SMEM);
        cudaFuncSetAttribute(attn_kernel, cudaFuncAttributeMaxDynamicSharedMemorySize, ATT_SMEM);
        inited = 1;
    }

    tohalf_all<<<(NX + 4 * NW) / 256, 256>>>(X, Wq, Wk, Wv, Wo);
    rope_table<<<(SEQ * 64) / 256, 256>>>();

    dim3 gqk(HID / GBN, SEQ / GBM, 2);      // fused Q,K projection + rope epilogue
    gemm_tn<<<gqk, 256, GEMM_SMEM>>>(0, nullptr);
    dim3 gv(SEQ / GBN, HID / GBM, 1);       // V^T = Wv @ X^T
    gemm_tn<<<gv, 256, GEMM_SMEM>>>(1, nullptr);

    attn_kernel<<<dim3(SEQ / ABM, NHEADS), 256, ATT_SMEM>>>(0.08838834764831845f);

    dim3 go(HID / GBN, SEQ / GBM, 1);       // output projection
    gemm_tn<<<go, 256, GEMM_SMEM>>>(2, out);
}

// round 10
// speedup vs baseline: 2.7642x; 1.0550x over previous
#include <cuda_runtime.h>
#include <cuda_fp16.h>
#include <cstdint>

#define SEQ 4096
#define HID 2048
#define NHEADS 16
#define HD 128

// ---------------- scratch (static device arrays; no allocation) ----------------
static __device__ __half g_Xh[SEQ * HID];
static __device__ __half g_Wqh[HID * HID];
static __device__ __half g_Wkh[HID * HID];
static __device__ __half g_Wvh[HID * HID];
static __device__ __half g_Woh[HID * HID];
static __device__ __half g_Qh[SEQ * HID];
static __device__ __half g_Kh[SEQ * HID];
static __device__ __half g_Vt[HID * SEQ];    // V TRANSPOSED: [dim][seq]
static __device__ __half g_ctxh[SEQ * HID];
static __device__ float  g_cos[SEQ * 64];
static __device__ float  g_sin[SEQ * 64];

// ---------------- helpers ----------------
__device__ __forceinline__ void mma_f16(float* c, const uint32_t* a, uint32_t b0, uint32_t b1) {
    asm volatile(
        "mma.sync.aligned.m16n8k16.row.col.f32.f16.f16.f32 "
        "{%0,%1,%2,%3}, {%4,%5,%6,%7}, {%8,%9}, {%0,%1,%2,%3};"
        : "+f"(c[0]), "+f"(c[1]), "+f"(c[2]), "+f"(c[3])
        : "r"(a[0]), "r"(a[1]), "r"(a[2]), "r"(a[3]), "r"(b0), "r"(b1));
}

__device__ __forceinline__ void cpasync16(uint32_t dst, const void* src) {
    asm volatile("cp.async.cg.shared.global [%0], [%1], 16;" :: "r"(dst), "l"(src));
}
__device__ __forceinline__ void cpcommit() { asm volatile("cp.async.commit_group;"); }

__device__ __forceinline__ uint32_t h2u(__half2 h) {
    return *reinterpret_cast<uint32_t*>(&h);
}

// ---------------- prep: fp32 -> fp16, all five tensors in one launch ----------
#define NX (SEQ * HID / 4)
#define NW (HID * HID / 4)
__global__ void tohalf_all(const float* __restrict__ X,  const float* __restrict__ Wq,
                           const float* __restrict__ Wk, const float* __restrict__ Wv,
                           const float* __restrict__ Wo) {
    int i = blockIdx.x * blockDim.x + threadIdx.x;
    const float* src; __half* dst; int off;
    if (i < NX)               { src = X;  dst = g_Xh;  off = i; }
    else if (i < NX + NW)     { src = Wq; dst = g_Wqh; off = i - NX; }
    else if (i < NX + 2 * NW) { src = Wk; dst = g_Wkh; off = i - NX - NW; }
    else if (i < NX + 3 * NW) { src = Wv; dst = g_Wvh; off = i - NX - 2 * NW; }
    else                      { src = Wo; dst = g_Woh; off = i - NX - 3 * NW; }
    float4 v = reinterpret_cast<const float4*>(src)[off];
    __half2* p = reinterpret_cast<__half2*>(&dst[4 * off]);
    p[0] = __floats2half2_rn(v.x, v.y);
    p[1] = __floats2half2_rn(v.z, v.w);
}

// ---------------- RoPE tables ----------------
__global__ void rope_table() {
    int idx = blockIdx.x * blockDim.x + threadIdx.x;
    if (idx >= SEQ * 64) return;
    int s = idx >> 6, j = idx & 63;
    double invf = exp(-(double)j * (9.210340371976184 / 64.0));  // 10000^(-j/64)
    float freq = (float)s * (float)invf;                          // fp32, like the ref
    g_cos[idx] = (float)cos((double)freq);
    g_sin[idx] = (float)sin((double)freq);
}

// ---------------- GEMM: C[M,N] = A[M,K] @ B[N,K]^T, fp16 mma, GBK=64, 3-stage --
// mode 0, z=0/1: Q/K projection, rope epilogue -> half
// mode 0, z=2  : V^T = Wv @ X^T (block coords swapped), -> half g_Vt
// mode 2       : out = ctx @ Wo^T, -> fp32 extC
#define GBM 128
#define GBN 128
#define GBK 64
#define GST 3
#define APITCH 72                          // halves
#define AHALFS (GBM * APITCH)              // 9216
#define STGH (2 * AHALFS)                  // 18432 halves = 36864 B
#define GEMM_SMEM (GST * STGH * 2)         // 110592 B  (2 CTAs/SM: 221184 <= 233472)
#define CPITCH 132                         // fp32 epilogue staging pitch

__global__ void __launch_bounds__(256, 2) gemm_tn(int mode, float* __restrict__ extC) {
    extern __shared__ __half sm[];
    const __half* A; const __half* B;
    float* Cf = nullptr; __half* Ch = nullptr;
    int N;
    const int K = HID;
    int z = (int)blockIdx.z;
    int bm, bn;
    if (mode == 0) {
        if (z == 0)      { A = g_Xh;  B = g_Wqh; N = HID; }
        else if (z == 1) { A = g_Xh;  B = g_Wkh; N = HID; }
        else             { A = g_Wvh; B = g_Xh;  N = SEQ; Ch = g_Vt; }
        if (z == 2) { bm = blockIdx.x * GBM; bn = blockIdx.y * GBN; }   // 16 x 32
        else        { bm = blockIdx.y * GBM; bn = blockIdx.x * GBN; }   // 32 x 16
    } else {
        A = g_ctxh; B = g_Woh; N = HID; Cf = extC;
        bm = blockIdx.y * GBM; bn = blockIdx.x * GBN;
    }

    int tid = threadIdx.x;
    int lane = tid & 31, wid = tid >> 5;
    int wm = wid & 3, wn = wid >> 2;

    float c[2][8][4];
#pragma unroll
    for (int im = 0; im < 2; im++)
#pragma unroll
        for (int jn = 0; jn < 8; jn++)
#pragma unroll
            for (int q = 0; q < 4; q++) c[im][jn][q] = 0.f;

    const __half* Abase = A + (size_t)bm * K;
    const __half* Bbase = B + (size_t)bn * K;

    uint32_t smb = (uint32_t)__cvta_generic_to_shared(sm);

    int lr = tid >> 3, lc8 = tid & 7;

    auto load_tile = [&](int s, int kt) {
        int koff = kt * GBK + lc8 * 8;
        uint32_t sa = smb + (uint32_t)(s * STGH) * 2;
        uint32_t sb = sa + AHALFS * 2;
        uint32_t doff = (uint32_t)(lr * APITCH + lc8 * 8) * 2;
#pragma unroll
        for (int i = 0; i < 4; i++) {
            int r = lr + 32 * i;
            cpasync16(sa + doff + (uint32_t)(32 * i * APITCH) * 2, Abase + (size_t)r * K + koff);
            cpasync16(sb + doff + (uint32_t)(32 * i * APITCH) * 2, Bbase + (size_t)r * K + koff);
        }
    };

    const int NT = K / GBK;  // 32
    load_tile(0, 0); cpcommit();
    load_tile(1, 1); cpcommit();

    int g = lane >> 2, t = lane & 3;
    int stg = 0;

    for (int kt = 0; kt < NT; kt++) {
        if (kt + 2 < NT) {
            if (kt > 0) __syncthreads();
            int ns = stg + 2; if (ns >= GST) ns -= GST;
            load_tile(ns, kt + 2);
            cpcommit();
            asm volatile("cp.async.wait_group 2;" ::: "memory");
        } else {
            if (kt > 0) __syncthreads();
            asm volatile("cp.async.wait_group 0;" ::: "memory");
        }
        __syncthreads();

        const __half* As = sm + stg * STGH;
        const __half* Bs = As + AHALFS;
#pragma unroll
        for (int ks = 0; ks < 4; ks++) {
            int k0 = ks * 16;
            uint32_t a[2][4], b[8][2];
#pragma unroll
            for (int im = 0; im < 2; im++) {
                int r = wm * 32 + im * 16 + g;
                a[im][0] = *reinterpret_cast<const uint32_t*>(&As[r * APITCH + k0 + 2 * t]);
                a[im][1] = *reinterpret_cast<const uint32_t*>(&As[(r + 8) * APITCH + k0 + 2 * t]);
                a[im][2] = *reinterpret_cast<const uint32_t*>(&As[r * APITCH + k0 + 2 * t + 8]);
                a[im][3] = *reinterpret_cast<const uint32_t*>(&As[(r + 8) * APITCH + k0 + 2 * t + 8]);
            }
#pragma unroll
            for (int jn = 0; jn < 8; jn++) {
                int cc = wn * 64 + jn * 8 + g;
                b[jn][0] = *reinterpret_cast<const uint32_t*>(&Bs[cc * APITCH + k0 + 2 * t]);
                b[jn][1] = *reinterpret_cast<const uint32_t*>(&Bs[cc * APITCH + k0 + 2 * t + 8]);
            }
#pragma unroll
            for (int im = 0; im < 2; im++)
#pragma unroll
                for (int jn = 0; jn < 8; jn++)
                    mma_f16(c[im][jn], a[im], b[jn][0], b[jn][1]);
        }
        if (++stg == GST) stg = 0;
    }

    if (mode == 0 && z < 2) {
        // ---- fused RoPE epilogue: stage fp32 C in smem, pair (i, i+64), write half
        __syncthreads();                       // mainloop smem reads done
        float* cs = reinterpret_cast<float*>(sm);
#pragma unroll
        for (int im = 0; im < 2; im++)
#pragma unroll
            for (int jn = 0; jn < 8; jn++) {
                int r = wm * 32 + im * 16 + g;
                int lc = wn * 64 + jn * 8 + 2 * t;
                cs[r * CPITCH + lc]           = c[im][jn][0];
                cs[r * CPITCH + lc + 1]       = c[im][jn][1];
                cs[(r + 8) * CPITCH + lc]     = c[im][jn][2];
                cs[(r + 8) * CPITCH + lc + 1] = c[im][jn][3];
            }
        __syncthreads();
        __half* dst = (z == 0) ? g_Qh : g_Kh;
        int r = tid >> 1;
        int i0 = (tid & 1) * 32;
        int s = bm + r;
        const float* crow = cs + r * CPITCH;
#pragma unroll
        for (int ii = 0; ii < 32; ii += 4) {
            int i = i0 + ii;
            float4 x1 = *reinterpret_cast<const float4*>(&crow[i]);
            float4 x2 = *reinterpret_cast<const float4*>(&crow[i + 64]);
            float4 co = *reinterpret_cast<const float4*>(&g_cos[s * 64 + i]);
            float4 si = *reinterpret_cast<const float4*>(&g_sin[s * 64 + i]);
            __half2* d1 = reinterpret_cast<__half2*>(&dst[(size_t)s * HID + bn + i]);
            __half2* d2 = reinterpret_cast<__half2*>(&dst[(size_t)s * HID + bn + 64 + i]);
            d1[0] = __floats2half2_rn(x1.x * co.x - x2.x * si.x, x1.y * co.y - x2.y * si.y);
            d1[1] = __floats2half2_rn(x1.z * co.z - x2.z * si.z, x1.w * co.w - x2.w * si.w);
            d2[0] = __floats2half2_rn(x2.x * co.x + x1.x * si.x, x2.y * co.y + x1.y * si.y);
            d2[1] = __floats2half2_rn(x2.z * co.z + x1.z * si.z, x2.w * co.w + x1.w * si.w);
        }
        return;
    }

#pragma unroll
    for (int im = 0; im < 2; im++) {
#pragma unroll
        for (int jn = 0; jn < 8; jn++) {
            int r = bm + wm * 32 + im * 16 + g;
            int col = bn + wn * 64 + jn * 8 + 2 * t;
            if (Ch) {
                *reinterpret_cast<__half2*>(&Ch[(size_t)r * N + col]) =
                    __floats2half2_rn(c[im][jn][0], c[im][jn][1]);
                *reinterpret_cast<__half2*>(&Ch[(size_t)(r + 8) * N + col]) =
                    __floats2half2_rn(c[im][jn][2], c[im][jn][3]);
            } else {
                *reinterpret_cast<float2*>(&Cf[(size_t)r * N + col]) =
                    make_float2(c[im][jn][0], c[im][jn][1]);
                *reinterpret_cast<float2*>(&Cf[(size_t)(r + 8) * N + col]) =
                    make_float2(c[im][jn][2], c[im][jn][3]);
            }
        }
    }
}

// ---------------- flash attention (causal), fp16 mma, P kept in registers ------
#define ABM 128
#define ABN 64
#define KVP 136                            // K tile pitch (halves)
#define KSTGH (ABN * KVP)                  // 8704 halves
#define VPITCH 72                          // V^T tile pitch (halves)
#define VSTGH (HD * VPITCH)                // 9216 halves
#define ATT_SMEM ((2 * KSTGH + 2 * VSTGH) * 2)  // 71680 B dynamic

__global__ void __launch_bounds__(256) attn_kernel(float scale) {
    extern __shared__ __half kvdyn[];      // [K0, K1, V0, V1]

    int tid = threadIdx.x, lane = tid & 31, wid = tid >> 5;
    int g = lane >> 2, t = lane & 3;
    int qt = (int)(gridDim.x - 1 - blockIdx.x);   // heavy tiles first
    int h = blockIdx.y;
    int hoff = h * HD;
    int qrow = qt * ABM + wid * 16;
    int row0 = qrow + g, row1 = row0 + 8;

    uint32_t dynb = (uint32_t)__cvta_generic_to_shared(kvdyn);

    // Q fragments: 8 k16-steps over HD=128
    uint32_t qf[8][4];
#pragma unroll
    for (int s = 0; s < 8; s++) {
        int cb = hoff + s * 16 + 2 * t;
        qf[s][0] = *reinterpret_cast<const uint32_t*>(&g_Qh[(size_t)row0 * HID + cb]);
        qf[s][1] = *reinterpret_cast<const uint32_t*>(&g_Qh[(size_t)row1 * HID + cb]);
        qf[s][2] = *reinterpret_cast<const uint32_t*>(&g_Qh[(size_t)row0 * HID + cb + 8]);
        qf[s][3] = *reinterpret_cast<const uint32_t*>(&g_Qh[(size_t)row1 * HID + cb + 8]);
    }

    float of[16][4];
#pragma unroll
    for (int j = 0; j < 16; j++) { of[j][0] = 0.f; of[j][1] = 0.f; of[j][2] = 0.f; of[j][3] = 0.f; }
    float m0 = -1e30f, m1 = -1e30f, l0 = 0.f, l1 = 0.f;

    auto loadKV = [&](int b, int kt) {
        const __half* Kg = g_Kh + (size_t)(kt * ABN) * HID + hoff;
        const __half* Vg = g_Vt + (size_t)hoff * SEQ + kt * ABN;
        uint32_t kb = dynb + (uint32_t)(b * KSTGH) * 2;
        uint32_t vb = dynb + (uint32_t)(2 * KSTGH + b * VSTGH) * 2;
#pragma unroll
        for (int j = 0; j < 4; j++) {       // K: 64 rows x 16 chunks
            int cidx = tid + 256 * j;
            int rr = cidx >> 4, c = cidx & 15;
            cpasync16(kb + (uint32_t)(rr * KVP + c * 8) * 2, Kg + (size_t)rr * HID + c * 8);
        }
#pragma unroll
        for (int j = 0; j < 4; j++) {       // V^T: 128 rows x 8 chunks
            int cidx = tid + 256 * j;
            int rr = cidx >> 3, c = cidx & 7;
            cpasync16(vb + (uint32_t)(rr * VPITCH + c * 8) * 2, Vg + (size_t)rr * SEQ + c * 8);
        }
    };

    int ktmax = 2 * qt + 1;
    loadKV(0, 0);
    cpcommit();
    int buf = 0;

    for (int kt = 0; kt <= ktmax; kt++) {
        if (kt < ktmax) {
            if (kt > 0) __syncthreads();
            loadKV(buf ^ 1, kt + 1);
            cpcommit();
            asm volatile("cp.async.wait_group 1;" ::: "memory");
        } else {
            if (kt > 0) __syncthreads();
            asm volatile("cp.async.wait_group 0;" ::: "memory");
        }
        __syncthreads();

        const __half* Kb  = kvdyn + buf * KSTGH;
        const __half* Vts = kvdyn + 2 * KSTGH + buf * VSTGH;

        // scores: Q (128x128) @ K^T (128x64), per-warp 16x64
        float sf[8][4];
#pragma unroll
        for (int j = 0; j < 8; j++) { sf[j][0] = 0.f; sf[j][1] = 0.f; sf[j][2] = 0.f; sf[j][3] = 0.f; }
#pragma unroll
        for (int s = 0; s < 8; s++) {
#pragma unroll
            for (int j = 0; j < 8; j++) {
                const __half* kr = &Kb[(j * 8 + g) * KVP + s * 16 + 2 * t];
                uint32_t b0 = *reinterpret_cast<const uint32_t*>(kr);
                uint32_t b1 = *reinterpret_cast<const uint32_t*>(kr + 8);
                mma_f16(sf[j], qf[s], b0, b1);
            }
        }

        // scale + causal mask + row max
        float mx0 = -1e30f, mx1 = -1e30f;
#pragma unroll
        for (int j = 0; j < 8; j++) {
            int cg = kt * ABN + j * 8 + 2 * t;
            sf[j][0] = (cg     <= row0) ? sf[j][0] * scale : -1e30f;
            sf[j][1] = (cg + 1 <= row0) ? sf[j][1] * scale : -1e30f;
            sf[j][2] = (cg     <= row1) ? sf[j][2] * scale : -1e30f;
            sf[j][3] = (cg + 1 <= row1) ? sf[j][3] * scale : -1e30f;
            mx0 = fmaxf(mx0, fmaxf(sf[j][0], sf[j][1]));
            mx1 = fmaxf(mx1, fmaxf(sf[j][2], sf[j][3]));
        }
        mx0 = fmaxf(mx0, __shfl_xor_sync(0xffffffffu, mx0, 1));
        mx0 = fmaxf(mx0, __shfl_xor_sync(0xffffffffu, mx0, 2));
        mx1 = fmaxf(mx1, __shfl_xor_sync(0xffffffffu, mx1, 1));
        mx1 = fmaxf(mx1, __shfl_xor_sync(0xffffffffu, mx1, 2));

        float mn0 = fmaxf(m0, mx0), mn1 = fmaxf(m1, mx1);
        float al0 = __expf(m0 - mn0), al1 = __expf(m1 - mn1);

        // exp + pack P directly into PV A-fragments (C-frag and A-frag layouts match)
        uint32_t p01[8], p23[8];
        float rs0 = 0.f, rs1 = 0.f;
#pragma unroll
        for (int j = 0; j < 8; j++) {
            float p0 = __expf(sf[j][0] - mn0);
            float p1 = __expf(sf[j][1] - mn0);
            float p2 = __expf(sf[j][2] - mn1);
            float p3 = __expf(sf[j][3] - mn1);
            rs0 += p0 + p1; rs1 += p2 + p3;
            p01[j] = h2u(__floats2half2_rn(p0, p1));
            p23[j] = h2u(__floats2half2_rn(p2, p3));
        }
        rs0 += __shfl_xor_sync(0xffffffffu, rs0, 1);
        rs0 += __shfl_xor_sync(0xffffffffu, rs0, 2);
        rs1 += __shfl_xor_sync(0xffffffffu, rs1, 1);
        rs1 += __shfl_xor_sync(0xffffffffu, rs1, 2);
        l0 = l0 * al0 + rs0;
        l1 = l1 * al1 + rs1;
        m0 = mn0; m1 = mn1;
#pragma unroll
        for (int j = 0; j < 16; j++) {
            of[j][0] *= al0; of[j][1] *= al0; of[j][2] *= al1; of[j][3] *= al1;
        }

        // PV: P (128x64) @ V (64x128); A-fragments straight from registers,
        // B-fragments two LDS.32 from dim-major V^T tile.
#pragma unroll
        for (int kb = 0; kb < 4; kb++) {
            uint32_t a[4];
            a[0] = p01[2 * kb];
            a[1] = p23[2 * kb];
            a[2] = p01[2 * kb + 1];
            a[3] = p23[2 * kb + 1];
#pragma unroll
            for (int jp = 0; jp < 16; jp++) {
                const __half* vr = &Vts[(jp * 8 + g) * VPITCH + kb * 16 + 2 * t];
                uint32_t b0 = *reinterpret_cast<const uint32_t*>(vr);
                uint32_t b1 = *reinterpret_cast<const uint32_t*>(vr + 8);
                mma_f16(of[jp], a, b0, b1);
            }
        }
        buf ^= 1;
    }

    float inv0 = 1.f / l0, inv1 = 1.f / l1;
#pragma unroll
    for (int j = 0; j < 16; j++) {
        int col = hoff + j * 8 + 2 * t;
        *reinterpret_cast<__half2*>(&g_ctxh[(size_t)row0 * HID + col]) =
            __floats2half2_rn(of[j][0] * inv0, of[j][1] * inv0);
        *reinterpret_cast<__half2*>(&g_ctxh[(size_t)row1 * HID + col]) =
            __floats2half2_rn(of[j][2] * inv1, of[j][3] * inv1);
    }
}

// ---------------- launch ----------------
extern "C" void kernel_launch(void* const* d_in, const int* in_sizes, int n_in,
                              void* d_out, int out_size) {
    const float* X  = (const float*)d_in[0];
    const float* Wq = (const float*)d_in[1];
    const float* Wk = (const float*)d_in[2];
    const float* Wv = (const float*)d_in[3];
    const float* Wo = (const float*)d_in[4];
    float* out = (float*)d_out;

    static int inited = 0;
    if (!inited) {
        cudaFuncSetAttribute(gemm_tn, cudaFuncAttributeMaxDynamicSharedMemorySize, GEMM_SMEM);
        cudaFuncSetAttribute(attn_kernel, cudaFuncAttributeMaxDynamicSharedMemorySize, ATT_SMEM);
        inited = 1;
    }

    tohalf_all<<<(NX + 4 * NW) / 256, 256>>>(X, Wq, Wk, Wv, Wo);
    rope_table<<<(SEQ * 64) / 256, 256>>>();

    // fused Q, K (rope epilogue) and V^T in one launch; z=2 swaps block coords
    dim3 gqkv(16, 32, 3);
    gemm_tn<<<gqkv, 256, GEMM_SMEM>>>(0, nullptr);

    attn_kernel<<<dim3(SEQ / ABM, NHEADS), 256, ATT_SMEM>>>(0.08838834764831845f);

    dim3 go(HID / GBN, SEQ / GBM, 1);       // output projection
    gemm_tn<<<go, 256, GEMM_SMEM>>>(2, out);
}

// round 11
// speedup vs baseline: 2.8058x; 1.0151x over previous
#include <cuda_runtime.h>
#include <cuda_fp16.h>
#include <cstdint>

#define SEQ 4096
#define HID 2048
#define NHEADS 16
#define HD 128

// ---------------- scratch (static device arrays; no allocation) ----------------
static __device__ __half g_Xh[SEQ * HID];
static __device__ __half g_Wqh[HID * HID];
static __device__ __half g_Wkh[HID * HID];
static __device__ __half g_Wvh[HID * HID];
static __device__ __half g_Woh[HID * HID];
static __device__ __half g_Qh[SEQ * HID];
static __device__ __half g_Kh[SEQ * HID];
static __device__ __half g_Vt[HID * SEQ];    // V TRANSPOSED: [dim][seq]
static __device__ __half g_ctxh[SEQ * HID];
static __device__ float  g_cos[SEQ * 64];
static __device__ float  g_sin[SEQ * 64];

// ---------------- helpers ----------------
__device__ __forceinline__ void mma_f16(float* c, const uint32_t* a, uint32_t b0, uint32_t b1) {
    asm volatile(
        "mma.sync.aligned.m16n8k16.row.col.f32.f16.f16.f32 "
        "{%0,%1,%2,%3}, {%4,%5,%6,%7}, {%8,%9}, {%0,%1,%2,%3};"
        : "+f"(c[0]), "+f"(c[1]), "+f"(c[2]), "+f"(c[3])
        : "r"(a[0]), "r"(a[1]), "r"(a[2]), "r"(a[3]), "r"(b0), "r"(b1));
}

__device__ __forceinline__ void ldsm4(uint32_t& r0, uint32_t& r1, uint32_t& r2, uint32_t& r3,
                                      uint32_t addr) {
    asm volatile("ldmatrix.sync.aligned.m8n8.x4.shared.b16 {%0,%1,%2,%3}, [%4];"
                 : "=r"(r0), "=r"(r1), "=r"(r2), "=r"(r3) : "r"(addr));
}

__device__ __forceinline__ void cpasync16(uint32_t dst, const void* src) {
    asm volatile("cp.async.cg.shared.global [%0], [%1], 16;" :: "r"(dst), "l"(src));
}
__device__ __forceinline__ void cpcommit() { asm volatile("cp.async.commit_group;"); }

__device__ __forceinline__ uint32_t h2u(__half2 h) {
    return *reinterpret_cast<uint32_t*>(&h);
}

// ---------------- prep: fp32 -> fp16, all five tensors in one launch ----------
#define NX (SEQ * HID / 4)
#define NW (HID * HID / 4)
__global__ void tohalf_all(const float* __restrict__ X,  const float* __restrict__ Wq,
                           const float* __restrict__ Wk, const float* __restrict__ Wv,
                           const float* __restrict__ Wo) {
    int i = blockIdx.x * blockDim.x + threadIdx.x;
    const float* src; __half* dst; int off;
    if (i < NX)               { src = X;  dst = g_Xh;  off = i; }
    else if (i < NX + NW)     { src = Wq; dst = g_Wqh; off = i - NX; }
    else if (i < NX + 2 * NW) { src = Wk; dst = g_Wkh; off = i - NX - NW; }
    else if (i < NX + 3 * NW) { src = Wv; dst = g_Wvh; off = i - NX - 2 * NW; }
    else                      { src = Wo; dst = g_Woh; off = i - NX - 3 * NW; }
    float4 v = reinterpret_cast<const float4*>(src)[off];
    __half2* p = reinterpret_cast<__half2*>(&dst[4 * off]);
    p[0] = __floats2half2_rn(v.x, v.y);
    p[1] = __floats2half2_rn(v.z, v.w);
}

// ---------------- RoPE tables ----------------
__global__ void rope_table() {
    int idx = blockIdx.x * blockDim.x + threadIdx.x;
    if (idx >= SEQ * 64) return;
    int s = idx >> 6, j = idx & 63;
    double invf = exp(-(double)j * (9.210340371976184 / 64.0));  // 10000^(-j/64)
    float freq = (float)s * (float)invf;                          // fp32, like the ref
    g_cos[idx] = (float)cos((double)freq);
    g_sin[idx] = (float)sin((double)freq);
}

// ---------------- GEMM: C[M,N] = A[M,K] @ B[N,K]^T, fp16 mma, GBK=64, 3-stage --
// mode 0, z=0/1: Q/K projection, rope epilogue -> half
// mode 0, z=2  : V^T = Wv @ X^T (block coords swapped), -> half g_Vt
// mode 2       : out = ctx @ Wo^T, -> fp32 extC
#define GBM 128
#define GBN 128
#define GBK 64
#define GST 3
#define APITCH 72                          // halves
#define AHALFS (GBM * APITCH)              // 9216
#define STGH (2 * AHALFS)                  // 18432 halves = 36864 B
#define GEMM_SMEM (GST * STGH * 2)         // 110592 B  (2 CTAs/SM)
#define CPITCH 132                         // fp32 epilogue staging pitch

__global__ void __launch_bounds__(256, 2) gemm_tn(int mode, float* __restrict__ extC) {
    extern __shared__ __half sm[];
    const __half* A; const __half* B;
    float* Cf = nullptr; __half* Ch = nullptr;
    int N;
    const int K = HID;
    int z = (int)blockIdx.z;
    int bm, bn;
    if (mode == 0) {
        if (z == 0)      { A = g_Xh;  B = g_Wqh; N = HID; }
        else if (z == 1) { A = g_Xh;  B = g_Wkh; N = HID; }
        else             { A = g_Wvh; B = g_Xh;  N = SEQ; Ch = g_Vt; }
        if (z == 2) { bm = blockIdx.x * GBM; bn = blockIdx.y * GBN; }   // 16 x 32
        else        { bm = blockIdx.y * GBM; bn = blockIdx.x * GBN; }   // 32 x 16
    } else {
        A = g_ctxh; B = g_Woh; N = HID; Cf = extC;
        bm = blockIdx.y * GBM; bn = blockIdx.x * GBN;
    }

    int tid = threadIdx.x;
    int lane = tid & 31, wid = tid >> 5;
    int wm = wid & 3, wn = wid >> 2;

    float c[2][8][4];
#pragma unroll
    for (int im = 0; im < 2; im++)
#pragma unroll
        for (int jn = 0; jn < 8; jn++)
#pragma unroll
            for (int q = 0; q < 4; q++) c[im][jn][q] = 0.f;

    const __half* Abase = A + (size_t)bm * K;
    const __half* Bbase = B + (size_t)bn * K;

    uint32_t smb = (uint32_t)__cvta_generic_to_shared(sm);

    int lr = tid >> 3, lc8 = tid & 7;

    auto load_tile = [&](int s, int kt) {
        int koff = kt * GBK + lc8 * 8;
        uint32_t sa = smb + (uint32_t)(s * STGH) * 2;
        uint32_t sb = sa + AHALFS * 2;
        uint32_t doff = (uint32_t)(lr * APITCH + lc8 * 8) * 2;
#pragma unroll
        for (int i = 0; i < 4; i++) {
            int r = lr + 32 * i;
            cpasync16(sa + doff + (uint32_t)(32 * i * APITCH) * 2, Abase + (size_t)r * K + koff);
            cpasync16(sb + doff + (uint32_t)(32 * i * APITCH) * 2, Bbase + (size_t)r * K + koff);
        }
    };

    const int NT = K / GBK;  // 32
    load_tile(0, 0); cpcommit();
    load_tile(1, 1); cpcommit();

    int g = lane >> 2, t = lane & 3;
    int stg = 0;

    for (int kt = 0; kt < NT; kt++) {
        if (kt + 2 < NT) {
            if (kt > 0) __syncthreads();
            int ns = stg + 2; if (ns >= GST) ns -= GST;
            load_tile(ns, kt + 2);
            cpcommit();
            asm volatile("cp.async.wait_group 2;" ::: "memory");
        } else {
            if (kt > 0) __syncthreads();
            asm volatile("cp.async.wait_group 0;" ::: "memory");
        }
        __syncthreads();

        const __half* As = sm + stg * STGH;
        const __half* Bs = As + AHALFS;
#pragma unroll
        for (int ks = 0; ks < 4; ks++) {
            int k0 = ks * 16;
            uint32_t a[2][4], b[8][2];
#pragma unroll
            for (int im = 0; im < 2; im++) {
                int r = wm * 32 + im * 16 + g;
                a[im][0] = *reinterpret_cast<const uint32_t*>(&As[r * APITCH + k0 + 2 * t]);
                a[im][1] = *reinterpret_cast<const uint32_t*>(&As[(r + 8) * APITCH + k0 + 2 * t]);
                a[im][2] = *reinterpret_cast<const uint32_t*>(&As[r * APITCH + k0 + 2 * t + 8]);
                a[im][3] = *reinterpret_cast<const uint32_t*>(&As[(r + 8) * APITCH + k0 + 2 * t + 8]);
            }
#pragma unroll
            for (int jn = 0; jn < 8; jn++) {
                int cc = wn * 64 + jn * 8 + g;
                b[jn][0] = *reinterpret_cast<const uint32_t*>(&Bs[cc * APITCH + k0 + 2 * t]);
                b[jn][1] = *reinterpret_cast<const uint32_t*>(&Bs[cc * APITCH + k0 + 2 * t + 8]);
            }
#pragma unroll
            for (int im = 0; im < 2; im++)
#pragma unroll
                for (int jn = 0; jn < 8; jn++)
                    mma_f16(c[im][jn], a[im], b[jn][0], b[jn][1]);
        }
        if (++stg == GST) stg = 0;
    }

    if (mode == 0 && z < 2) {
        // ---- fused RoPE epilogue: stage fp32 C in smem, pair (i, i+64), write half
        __syncthreads();                       // mainloop smem reads done
        float* cs = reinterpret_cast<float*>(sm);
#pragma unroll
        for (int im = 0; im < 2; im++)
#pragma unroll
            for (int jn = 0; jn < 8; jn++) {
                int r = wm * 32 + im * 16 + g;
                int lc = wn * 64 + jn * 8 + 2 * t;
                cs[r * CPITCH + lc]           = c[im][jn][0];
                cs[r * CPITCH + lc + 1]       = c[im][jn][1];
                cs[(r + 8) * CPITCH + lc]     = c[im][jn][2];
                cs[(r + 8) * CPITCH + lc + 1] = c[im][jn][3];
            }
        __syncthreads();
        __half* dst = (z == 0) ? g_Qh : g_Kh;
        int r = tid >> 1;
        int i0 = (tid & 1) * 32;
        int s = bm + r;
        const float* crow = cs + r * CPITCH;
#pragma unroll
        for (int ii = 0; ii < 32; ii += 4) {
            int i = i0 + ii;
            float4 x1 = *reinterpret_cast<const float4*>(&crow[i]);
            float4 x2 = *reinterpret_cast<const float4*>(&crow[i + 64]);
            float4 co = *reinterpret_cast<const float4*>(&g_cos[s * 64 + i]);
            float4 si = *reinterpret_cast<const float4*>(&g_sin[s * 64 + i]);
            __half2* d1 = reinterpret_cast<__half2*>(&dst[(size_t)s * HID + bn + i]);
            __half2* d2 = reinterpret_cast<__half2*>(&dst[(size_t)s * HID + bn + 64 + i]);
            d1[0] = __floats2half2_rn(x1.x * co.x - x2.x * si.x, x1.y * co.y - x2.y * si.y);
            d1[1] = __floats2half2_rn(x1.z * co.z - x2.z * si.z, x1.w * co.w - x2.w * si.w);
            d2[0] = __floats2half2_rn(x2.x * co.x + x1.x * si.x, x2.y * co.y + x1.y * si.y);
            d2[1] = __floats2half2_rn(x2.z * co.z + x1.z * si.z, x2.w * co.w + x1.w * si.w);
        }
        return;
    }

#pragma unroll
    for (int im = 0; im < 2; im++) {
#pragma unroll
        for (int jn = 0; jn < 8; jn++) {
            int r = bm + wm * 32 + im * 16 + g;
            int col = bn + wn * 64 + jn * 8 + 2 * t;
            if (Ch) {
                *reinterpret_cast<__half2*>(&Ch[(size_t)r * N + col]) =
                    __floats2half2_rn(c[im][jn][0], c[im][jn][1]);
                *reinterpret_cast<__half2*>(&Ch[(size_t)(r + 8) * N + col]) =
                    __floats2half2_rn(c[im][jn][2], c[im][jn][3]);
            } else {
                *reinterpret_cast<float2*>(&Cf[(size_t)r * N + col]) =
                    make_float2(c[im][jn][0], c[im][jn][1]);
                *reinterpret_cast<float2*>(&Cf[(size_t)(r + 8) * N + col]) =
                    make_float2(c[im][jn][2], c[im][jn][3]);
            }
        }
    }
}

// ---------------- flash attention (causal), fp16 mma, ldmatrix B-fragments ----
#define ABM 128
#define ABN 64
#define KVP 136                            // K tile pitch (halves)
#define KSTGH (ABN * KVP)                  // 8704 halves
#define VPITCH 72                          // V^T tile pitch (halves)
#define VSTGH (HD * VPITCH)                // 9216 halves
#define ATT_SMEM ((2 * KSTGH + 2 * VSTGH) * 2)  // 71680 B dynamic

__global__ void __launch_bounds__(256) attn_kernel(float scale) {
    extern __shared__ __half kvdyn[];      // [K0, K1, V0, V1]

    int tid = threadIdx.x, lane = tid & 31, wid = tid >> 5;
    int g = lane >> 2, t = lane & 3;
    int qt = (int)(gridDim.x - 1 - blockIdx.x);   // heavy tiles first
    int h = blockIdx.y;
    int hoff = h * HD;
    int qrow = qt * ABM + wid * 16;
    int row0 = qrow + g, row1 = row0 + 8;

    uint32_t dynb = (uint32_t)__cvta_generic_to_shared(kvdyn);

    // ldmatrix lane address components: matrix lm = lane>>3, row-in-matrix = lane&7
    int lrow = lane & 7, lm = lane >> 3;
    // K: matrices (jj,klo),(jj,khi),(jj+1,klo),(jj+1,khi)
    int kroff = ((((lm >> 1) * 8 + lrow) * KVP) + (lm & 1) * 8) * 2;     // bytes
    int vroff = ((((lm >> 1) * 8 + lrow) * VPITCH) + (lm & 1) * 8) * 2;  // bytes

    // Q fragments: 8 k16-steps over HD=128
    uint32_t qf[8][4];
#pragma unroll
    for (int s = 0; s < 8; s++) {
        int cb = hoff + s * 16 + 2 * t;
        qf[s][0] = *reinterpret_cast<const uint32_t*>(&g_Qh[(size_t)row0 * HID + cb]);
        qf[s][1] = *reinterpret_cast<const uint32_t*>(&g_Qh[(size_t)row1 * HID + cb]);
        qf[s][2] = *reinterpret_cast<const uint32_t*>(&g_Qh[(size_t)row0 * HID + cb + 8]);
        qf[s][3] = *reinterpret_cast<const uint32_t*>(&g_Qh[(size_t)row1 * HID + cb + 8]);
    }

    float of[16][4];
#pragma unroll
    for (int j = 0; j < 16; j++) { of[j][0] = 0.f; of[j][1] = 0.f; of[j][2] = 0.f; of[j][3] = 0.f; }
    float m0 = -1e30f, m1 = -1e30f, l0 = 0.f, l1 = 0.f;

    auto loadKV = [&](int b, int kt) {
        const __half* Kg = g_Kh + (size_t)(kt * ABN) * HID + hoff;
        const __half* Vg = g_Vt + (size_t)hoff * SEQ + kt * ABN;
        uint32_t kb = dynb + (uint32_t)(b * KSTGH) * 2;
        uint32_t vb = dynb + (uint32_t)(2 * KSTGH + b * VSTGH) * 2;
#pragma unroll
        for (int j = 0; j < 4; j++) {       // K: 64 rows x 16 chunks
            int cidx = tid + 256 * j;
            int rr = cidx >> 4, c = cidx & 15;
            cpasync16(kb + (uint32_t)(rr * KVP + c * 8) * 2, Kg + (size_t)rr * HID + c * 8);
        }
#pragma unroll
        for (int j = 0; j < 4; j++) {       // V^T: 128 rows x 8 chunks
            int cidx = tid + 256 * j;
            int rr = cidx >> 3, c = cidx & 7;
            cpasync16(vb + (uint32_t)(rr * VPITCH + c * 8) * 2, Vg + (size_t)rr * SEQ + c * 8);
        }
    };

    int ktmax = 2 * qt + 1;
    loadKV(0, 0);
    cpcommit();
    int buf = 0;

    for (int kt = 0; kt <= ktmax; kt++) {
        if (kt < ktmax) {
            if (kt > 0) __syncthreads();
            loadKV(buf ^ 1, kt + 1);
            cpcommit();
            asm volatile("cp.async.wait_group 1;" ::: "memory");
        } else {
            if (kt > 0) __syncthreads();
            asm volatile("cp.async.wait_group 0;" ::: "memory");
        }
        __syncthreads();

        uint32_t kbU = dynb + (uint32_t)(buf * KSTGH) * 2;
        uint32_t vbU = dynb + (uint32_t)(2 * KSTGH + buf * VSTGH) * 2;

        // scores: Q (128x128) @ K^T (128x64), per-warp 16x64; B via ldmatrix.x4
        float sf[8][4];
#pragma unroll
        for (int j = 0; j < 8; j++) { sf[j][0] = 0.f; sf[j][1] = 0.f; sf[j][2] = 0.f; sf[j][3] = 0.f; }
#pragma unroll
        for (int s = 0; s < 8; s++) {
#pragma unroll
            for (int jj = 0; jj < 8; jj += 2) {
                uint32_t addr = kbU + (uint32_t)(jj * 8 * KVP * 2 + kroff + s * 32);
                uint32_t b0, b1, b2, b3;
                ldsm4(b0, b1, b2, b3, addr);
                mma_f16(sf[jj],     qf[s], b0, b1);
                mma_f16(sf[jj + 1], qf[s], b2, b3);
            }
        }

        // scale + causal mask + row max
        float mx0 = -1e30f, mx1 = -1e30f;
#pragma unroll
        for (int j = 0; j < 8; j++) {
            int cg = kt * ABN + j * 8 + 2 * t;
            sf[j][0] = (cg     <= row0) ? sf[j][0] * scale : -1e30f;
            sf[j][1] = (cg + 1 <= row0) ? sf[j][1] * scale : -1e30f;
            sf[j][2] = (cg     <= row1) ? sf[j][2] * scale : -1e30f;
            sf[j][3] = (cg + 1 <= row1) ? sf[j][3] * scale : -1e30f;
            mx0 = fmaxf(mx0, fmaxf(sf[j][0], sf[j][1]));
            mx1 = fmaxf(mx1, fmaxf(sf[j][2], sf[j][3]));
        }
        mx0 = fmaxf(mx0, __shfl_xor_sync(0xffffffffu, mx0, 1));
        mx0 = fmaxf(mx0, __shfl_xor_sync(0xffffffffu, mx0, 2));
        mx1 = fmaxf(mx1, __shfl_xor_sync(0xffffffffu, mx1, 1));
        mx1 = fmaxf(mx1, __shfl_xor_sync(0xffffffffu, mx1, 2));

        float mn0 = fmaxf(m0, mx0), mn1 = fmaxf(m1, mx1);
        float al0 = __expf(m0 - mn0), al1 = __expf(m1 - mn1);

        // exp + pack P directly into PV A-fragments (C-frag and A-frag layouts match)
        uint32_t p01[8], p23[8];
        float rs0 = 0.f, rs1 = 0.f;
#pragma unroll
        for (int j = 0; j < 8; j++) {
            float p0 = __expf(sf[j][0] - mn0);
            float p1 = __expf(sf[j][1] - mn0);
            float p2 = __expf(sf[j][2] - mn1);
            float p3 = __expf(sf[j][3] - mn1);
            rs0 += p0 + p1; rs1 += p2 + p3;
            p01[j] = h2u(__floats2half2_rn(p0, p1));
            p23[j] = h2u(__floats2half2_rn(p2, p3));
        }
        rs0 += __shfl_xor_sync(0xffffffffu, rs0, 1);
        rs0 += __shfl_xor_sync(0xffffffffu, rs0, 2);
        rs1 += __shfl_xor_sync(0xffffffffu, rs1, 1);
        rs1 += __shfl_xor_sync(0xffffffffu, rs1, 2);
        l0 = l0 * al0 + rs0;
        l1 = l1 * al1 + rs1;
        m0 = mn0; m1 = mn1;
#pragma unroll
        for (int j = 0; j < 16; j++) {
            of[j][0] *= al0; of[j][1] *= al0; of[j][2] *= al1; of[j][3] *= al1;
        }

        // PV: P (128x64) @ V (64x128); A from registers, B via ldmatrix.x4 on V^T
#pragma unroll
        for (int kb4 = 0; kb4 < 4; kb4++) {
            uint32_t a[4];
            a[0] = p01[2 * kb4];
            a[1] = p23[2 * kb4];
            a[2] = p01[2 * kb4 + 1];
            a[3] = p23[2 * kb4 + 1];
#pragma unroll
            for (int jj = 0; jj < 16; jj += 2) {
                uint32_t addr = vbU + (uint32_t)(jj * 8 * VPITCH * 2 + vroff + kb4 * 32);
                uint32_t b0, b1, b2, b3;
                ldsm4(b0, b1, b2, b3, addr);
                mma_f16(of[jj],     a, b0, b1);
                mma_f16(of[jj + 1], a, b2, b3);
            }
        }
        buf ^= 1;
    }

    float inv0 = 1.f / l0, inv1 = 1.f / l1;
#pragma unroll
    for (int j = 0; j < 16; j++) {
        int col = hoff + j * 8 + 2 * t;
        *reinterpret_cast<__half2*>(&g_ctxh[(size_t)row0 * HID + col]) =
            __floats2half2_rn(of[j][0] * inv0, of[j][1] * inv0);
        *reinterpret_cast<__half2*>(&g_ctxh[(size_t)row1 * HID + col]) =
            __floats2half2_rn(of[j][2] * inv1, of[j][3] * inv1);
    }
}

// ---------------- launch ----------------
extern "C" void kernel_launch(void* const* d_in, const int* in_sizes, int n_in,
                              void* d_out, int out_size) {
    const float* X  = (const float*)d_in[0];
    const float* Wq = (const float*)d_in[1];
    const float* Wk = (const float*)d_in[2];
    const float* Wv = (const float*)d_in[3];
    const float* Wo = (const float*)d_in[4];
    float* out = (float*)d_out;

    static int inited = 0;
    if (!inited) {
        cudaFuncSetAttribute(gemm_tn, cudaFuncAttributeMaxDynamicSharedMemorySize, GEMM_SMEM);
        cudaFuncSetAttribute(attn_kernel, cudaFuncAttributeMaxDynamicSharedMemorySize, ATT_SMEM);
        inited = 1;
    }

    tohalf_all<<<(NX + 4 * NW) / 256, 256>>>(X, Wq, Wk, Wv, Wo);
    rope_table<<<(SEQ * 64) / 256, 256>>>();

    // fused Q, K (rope epilogue) and V^T in one launch; z=2 swaps block coords
    dim3 gqkv(16, 32, 3);
    gemm_tn<<<gqkv, 256, GEMM_SMEM>>>(0, nullptr);

    attn_kernel<<<dim3(SEQ / ABM, NHEADS), 256, ATT_SMEM>>>(0.08838834764831845f);

    dim3 go(HID / GBN, SEQ / GBM, 1);       // output projection
    gemm_tn<<<go, 256, GEMM_SMEM>>>(2, out);
}

// round 12
// speedup vs baseline: 2.9307x; 1.0445x over previous
#include <cuda_runtime.h>
#include <cuda_fp16.h>
#include <cstdint>

#define SEQ 4096
#define HID 2048
#define NHEADS 16
#define HD 128

// Q pre-scale: (1/sqrt(128)) * log2(e)  -> softmax runs in exp2 domain
#define QSC 0.12751291181090523f

// ---------------- scratch (static device arrays; no allocation) ----------------
static __device__ __half g_Xh[SEQ * HID];
static __device__ __half g_Wqh[HID * HID];
static __device__ __half g_Wkh[HID * HID];
static __device__ __half g_Wvh[HID * HID];
static __device__ __half g_Woh[HID * HID];
static __device__ __half g_Qh[SEQ * HID];
static __device__ __half g_Kh[SEQ * HID];
static __device__ __half g_Vt[HID * SEQ];    // V TRANSPOSED: [dim][seq]
static __device__ __half g_ctxh[SEQ * HID];
static __device__ float  g_cos[SEQ * 64];
static __device__ float  g_sin[SEQ * 64];

// ---------------- helpers ----------------
__device__ __forceinline__ void mma_f16(float* c, const uint32_t* a, uint32_t b0, uint32_t b1) {
    asm volatile(
        "mma.sync.aligned.m16n8k16.row.col.f32.f16.f16.f32 "
        "{%0,%1,%2,%3}, {%4,%5,%6,%7}, {%8,%9}, {%0,%1,%2,%3};"
        : "+f"(c[0]), "+f"(c[1]), "+f"(c[2]), "+f"(c[3])
        : "r"(a[0]), "r"(a[1]), "r"(a[2]), "r"(a[3]), "r"(b0), "r"(b1));
}

__device__ __forceinline__ void ldsm4(uint32_t& r0, uint32_t& r1, uint32_t& r2, uint32_t& r3,
                                      uint32_t addr) {
    asm volatile("ldmatrix.sync.aligned.m8n8.x4.shared.b16 {%0,%1,%2,%3}, [%4];"
                 : "=r"(r0), "=r"(r1), "=r"(r2), "=r"(r3) : "r"(addr));
}

__device__ __forceinline__ void cpasync16(uint32_t dst, const void* src) {
    asm volatile("cp.async.cg.shared.global [%0], [%1], 16;" :: "r"(dst), "l"(src));
}
__device__ __forceinline__ void cpcommit() { asm volatile("cp.async.commit_group;"); }

__device__ __forceinline__ uint32_t h2u(__half2 h) {
    return *reinterpret_cast<uint32_t*>(&h);
}
__device__ __forceinline__ uint32_t ex2_h2(uint32_t x) {
    uint32_t r;
    asm("ex2.approx.f16x2 %0, %1;" : "=r"(r) : "r"(x));
    return r;
}

// ---------------- prep: fp32 -> fp16, all five tensors in one launch ----------
#define NX (SEQ * HID / 4)
#define NW (HID * HID / 4)
__global__ void tohalf_all(const float* __restrict__ X,  const float* __restrict__ Wq,
                           const float* __restrict__ Wk, const float* __restrict__ Wv,
                           const float* __restrict__ Wo) {
    int i = blockIdx.x * blockDim.x + threadIdx.x;
    const float* src; __half* dst; int off;
    if (i < NX)               { src = X;  dst = g_Xh;  off = i; }
    else if (i < NX + NW)     { src = Wq; dst = g_Wqh; off = i - NX; }
    else if (i < NX + 2 * NW) { src = Wk; dst = g_Wkh; off = i - NX - NW; }
    else if (i < NX + 3 * NW) { src = Wv; dst = g_Wvh; off = i - NX - 2 * NW; }
    else                      { src = Wo; dst = g_Woh; off = i - NX - 3 * NW; }
    float4 v = reinterpret_cast<const float4*>(src)[off];
    __half2* p = reinterpret_cast<__half2*>(&dst[4 * off]);
    p[0] = __floats2half2_rn(v.x, v.y);
    p[1] = __floats2half2_rn(v.z, v.w);
}

// ---------------- RoPE tables ----------------
__global__ void rope_table() {
    int idx = blockIdx.x * blockDim.x + threadIdx.x;
    if (idx >= SEQ * 64) return;
    int s = idx >> 6, j = idx & 63;
    double invf = exp(-(double)j * (9.210340371976184 / 64.0));  // 10000^(-j/64)
    float freq = (float)s * (float)invf;                          // fp32, like the ref
    g_cos[idx] = (float)cos((double)freq);
    g_sin[idx] = (float)sin((double)freq);
}

// ---------------- GEMM: C[M,N] = A[M,K] @ B[N,K]^T, fp16 mma, GBK=64, 3-stage --
// mode 0, z=0/1: Q/K projection, rope epilogue -> half (Q additionally * QSC)
// mode 0, z=2  : V^T = Wv @ X^T (block coords swapped), -> half g_Vt
// mode 2       : out = ctx @ Wo^T, -> fp32 extC
#define GBM 128
#define GBN 128
#define GBK 64
#define GST 3
#define APITCH 72                          // halves
#define AHALFS (GBM * APITCH)              // 9216
#define STGH (2 * AHALFS)                  // 18432 halves = 36864 B
#define GEMM_SMEM (GST * STGH * 2)         // 110592 B  (2 CTAs/SM)
#define CPITCH 132                         // fp32 epilogue staging pitch

__global__ void __launch_bounds__(256, 2) gemm_tn(int mode, float* __restrict__ extC) {
    extern __shared__ __half sm[];
    const __half* A; const __half* B;
    float* Cf = nullptr; __half* Ch = nullptr;
    int N;
    const int K = HID;
    int z = (int)blockIdx.z;
    int bm, bn;
    if (mode == 0) {
        if (z == 0)      { A = g_Xh;  B = g_Wqh; N = HID; }
        else if (z == 1) { A = g_Xh;  B = g_Wkh; N = HID; }
        else             { A = g_Wvh; B = g_Xh;  N = SEQ; Ch = g_Vt; }
        if (z == 2) { bm = blockIdx.x * GBM; bn = blockIdx.y * GBN; }   // 16 x 32
        else        { bm = blockIdx.y * GBM; bn = blockIdx.x * GBN; }   // 32 x 16
    } else {
        A = g_ctxh; B = g_Woh; N = HID; Cf = extC;
        bm = blockIdx.y * GBM; bn = blockIdx.x * GBN;
    }

    int tid = threadIdx.x;
    int lane = tid & 31, wid = tid >> 5;
    int wm = wid & 3, wn = wid >> 2;

    float c[2][8][4];
#pragma unroll
    for (int im = 0; im < 2; im++)
#pragma unroll
        for (int jn = 0; jn < 8; jn++)
#pragma unroll
            for (int q = 0; q < 4; q++) c[im][jn][q] = 0.f;

    const __half* Abase = A + (size_t)bm * K;
    const __half* Bbase = B + (size_t)bn * K;

    uint32_t smb = (uint32_t)__cvta_generic_to_shared(sm);

    int lr = tid >> 3, lc8 = tid & 7;

    auto load_tile = [&](int s, int kt) {
        int koff = kt * GBK + lc8 * 8;
        uint32_t sa = smb + (uint32_t)(s * STGH) * 2;
        uint32_t sb = sa + AHALFS * 2;
        uint32_t doff = (uint32_t)(lr * APITCH + lc8 * 8) * 2;
#pragma unroll
        for (int i = 0; i < 4; i++) {
            int r = lr + 32 * i;
            cpasync16(sa + doff + (uint32_t)(32 * i * APITCH) * 2, Abase + (size_t)r * K + koff);
            cpasync16(sb + doff + (uint32_t)(32 * i * APITCH) * 2, Bbase + (size_t)r * K + koff);
        }
    };

    const int NT = K / GBK;  // 32
    load_tile(0, 0); cpcommit();
    load_tile(1, 1); cpcommit();

    int g = lane >> 2, t = lane & 3;
    int stg = 0;

    for (int kt = 0; kt < NT; kt++) {
        if (kt + 2 < NT) {
            if (kt > 0) __syncthreads();
            int ns = stg + 2; if (ns >= GST) ns -= GST;
            load_tile(ns, kt + 2);
            cpcommit();
            asm volatile("cp.async.wait_group 2;" ::: "memory");
        } else {
            if (kt > 0) __syncthreads();
            asm volatile("cp.async.wait_group 0;" ::: "memory");
        }
        __syncthreads();

        const __half* As = sm + stg * STGH;
        const __half* Bs = As + AHALFS;
#pragma unroll
        for (int ks = 0; ks < 4; ks++) {
            int k0 = ks * 16;
            uint32_t a[2][4], b[8][2];
#pragma unroll
            for (int im = 0; im < 2; im++) {
                int r = wm * 32 + im * 16 + g;
                a[im][0] = *reinterpret_cast<const uint32_t*>(&As[r * APITCH + k0 + 2 * t]);
                a[im][1] = *reinterpret_cast<const uint32_t*>(&As[(r + 8) * APITCH + k0 + 2 * t]);
                a[im][2] = *reinterpret_cast<const uint32_t*>(&As[r * APITCH + k0 + 2 * t + 8]);
                a[im][3] = *reinterpret_cast<const uint32_t*>(&As[(r + 8) * APITCH + k0 + 2 * t + 8]);
            }
#pragma unroll
            for (int jn = 0; jn < 8; jn++) {
                int cc = wn * 64 + jn * 8 + g;
                b[jn][0] = *reinterpret_cast<const uint32_t*>(&Bs[cc * APITCH + k0 + 2 * t]);
                b[jn][1] = *reinterpret_cast<const uint32_t*>(&Bs[cc * APITCH + k0 + 2 * t + 8]);
            }
#pragma unroll
            for (int im = 0; im < 2; im++)
#pragma unroll
                for (int jn = 0; jn < 8; jn++)
                    mma_f16(c[im][jn], a[im], b[jn][0], b[jn][1]);
        }
        if (++stg == GST) stg = 0;
    }

    if (mode == 0 && z < 2) {
        // ---- fused RoPE epilogue: stage fp32 C in smem, pair (i, i+64), write half
        __syncthreads();                       // mainloop smem reads done
        float* cs = reinterpret_cast<float*>(sm);
#pragma unroll
        for (int im = 0; im < 2; im++)
#pragma unroll
            for (int jn = 0; jn < 8; jn++) {
                int r = wm * 32 + im * 16 + g;
                int lc = wn * 64 + jn * 8 + 2 * t;
                cs[r * CPITCH + lc]           = c[im][jn][0];
                cs[r * CPITCH + lc + 1]       = c[im][jn][1];
                cs[(r + 8) * CPITCH + lc]     = c[im][jn][2];
                cs[(r + 8) * CPITCH + lc + 1] = c[im][jn][3];
            }
        __syncthreads();
        __half* dst = (z == 0) ? g_Qh : g_Kh;
        float qs = (z == 0) ? QSC : 1.0f;      // Q carries softmax scale (log2 domain)
        int r = tid >> 1;
        int i0 = (tid & 1) * 32;
        int s = bm + r;
        const float* crow = cs + r * CPITCH;
#pragma unroll
        for (int ii = 0; ii < 32; ii += 4) {
            int i = i0 + ii;
            float4 x1 = *reinterpret_cast<const float4*>(&crow[i]);
            float4 x2 = *reinterpret_cast<const float4*>(&crow[i + 64]);
            float4 co = *reinterpret_cast<const float4*>(&g_cos[s * 64 + i]);
            float4 si = *reinterpret_cast<const float4*>(&g_sin[s * 64 + i]);
            __half2* d1 = reinterpret_cast<__half2*>(&dst[(size_t)s * HID + bn + i]);
            __half2* d2 = reinterpret_cast<__half2*>(&dst[(size_t)s * HID + bn + 64 + i]);
            d1[0] = __floats2half2_rn((x1.x * co.x - x2.x * si.x) * qs,
                                      (x1.y * co.y - x2.y * si.y) * qs);
            d1[1] = __floats2half2_rn((x1.z * co.z - x2.z * si.z) * qs,
                                      (x1.w * co.w - x2.w * si.w) * qs);
            d2[0] = __floats2half2_rn((x2.x * co.x + x1.x * si.x) * qs,
                                      (x2.y * co.y + x1.y * si.y) * qs);
            d2[1] = __floats2half2_rn((x2.z * co.z + x1.z * si.z) * qs,
                                      (x2.w * co.w + x1.w * si.w) * qs);
        }
        return;
    }

#pragma unroll
    for (int im = 0; im < 2; im++) {
#pragma unroll
        for (int jn = 0; jn < 8; jn++) {
            int r = bm + wm * 32 + im * 16 + g;
            int col = bn + wn * 64 + jn * 8 + 2 * t;
            if (Ch) {
                *reinterpret_cast<__half2*>(&Ch[(size_t)r * N + col]) =
                    __floats2half2_rn(c[im][jn][0], c[im][jn][1]);
                *reinterpret_cast<__half2*>(&Ch[(size_t)(r + 8) * N + col]) =
                    __floats2half2_rn(c[im][jn][2], c[im][jn][3]);
            } else {
                *reinterpret_cast<float2*>(&Cf[(size_t)r * N + col]) =
                    make_float2(c[im][jn][0], c[im][jn][1]);
                *reinterpret_cast<float2*>(&Cf[(size_t)(r + 8) * N + col]) =
                    make_float2(c[im][jn][2], c[im][jn][3]);
            }
        }
    }
}

// ---------------- flash attention (causal), fp16 mma, exp2-domain softmax -----
#define ABM 128
#define ABN 64
#define KVP 136                            // K tile pitch (halves)
#define KSTGH (ABN * KVP)                  // 8704 halves
#define VPITCH 72                          // V^T tile pitch (halves)
#define VSTGH (HD * VPITCH)                // 9216 halves
#define ATT_SMEM ((2 * KSTGH + 2 * VSTGH) * 2)  // 71680 B dynamic

__global__ void __launch_bounds__(256) attn_kernel() {
    extern __shared__ __half kvdyn[];      // [K0, K1, V0, V1]

    int tid = threadIdx.x, lane = tid & 31, wid = tid >> 5;
    int g = lane >> 2, t = lane & 3;
    int qt = (int)(gridDim.x - 1 - blockIdx.x);   // heavy tiles first
    int h = blockIdx.y;
    int hoff = h * HD;
    int qrow = qt * ABM + wid * 16;
    int row0 = qrow + g, row1 = row0 + 8;

    uint32_t dynb = (uint32_t)__cvta_generic_to_shared(kvdyn);

    // ldmatrix lane address components
    int lrow = lane & 7, lm = lane >> 3;
    int kroff = ((((lm >> 1) * 8 + lrow) * KVP) + (lm & 1) * 8) * 2;     // bytes
    int vroff = ((((lm >> 1) * 8 + lrow) * VPITCH) + (lm & 1) * 8) * 2;  // bytes

    // Q fragments (pre-scaled by QSC): 8 k16-steps over HD=128
    uint32_t qf[8][4];
#pragma unroll
    for (int s = 0; s < 8; s++) {
        int cb = hoff + s * 16 + 2 * t;
        qf[s][0] = *reinterpret_cast<const uint32_t*>(&g_Qh[(size_t)row0 * HID + cb]);
        qf[s][1] = *reinterpret_cast<const uint32_t*>(&g_Qh[(size_t)row1 * HID + cb]);
        qf[s][2] = *reinterpret_cast<const uint32_t*>(&g_Qh[(size_t)row0 * HID + cb + 8]);
        qf[s][3] = *reinterpret_cast<const uint32_t*>(&g_Qh[(size_t)row1 * HID + cb + 8]);
    }

    float of[16][4];
#pragma unroll
    for (int j = 0; j < 16; j++) { of[j][0] = 0.f; of[j][1] = 0.f; of[j][2] = 0.f; of[j][3] = 0.f; }
    float m0 = -1e30f, m1 = -1e30f, l0 = 0.f, l1 = 0.f;

    auto loadKV = [&](int b, int kt) {
        const __half* Kg = g_Kh + (size_t)(kt * ABN) * HID + hoff;
        const __half* Vg = g_Vt + (size_t)hoff * SEQ + kt * ABN;
        uint32_t kb = dynb + (uint32_t)(b * KSTGH) * 2;
        uint32_t vb = dynb + (uint32_t)(2 * KSTGH + b * VSTGH) * 2;
#pragma unroll
        for (int j = 0; j < 4; j++) {       // K: 64 rows x 16 chunks
            int cidx = tid + 256 * j;
            int rr = cidx >> 4, c = cidx & 15;
            cpasync16(kb + (uint32_t)(rr * KVP + c * 8) * 2, Kg + (size_t)rr * HID + c * 8);
        }
#pragma unroll
        for (int j = 0; j < 4; j++) {       // V^T: 128 rows x 8 chunks
            int cidx = tid + 256 * j;
            int rr = cidx >> 3, c = cidx & 7;
            cpasync16(vb + (uint32_t)(rr * VPITCH + c * 8) * 2, Vg + (size_t)rr * SEQ + c * 8);
        }
    };

    int ktmax = 2 * qt + 1;
    loadKV(0, 0);
    cpcommit();
    int buf = 0;

    for (int kt = 0; kt <= ktmax; kt++) {
        if (kt < ktmax) {
            if (kt > 0) __syncthreads();
            loadKV(buf ^ 1, kt + 1);
            cpcommit();
            asm volatile("cp.async.wait_group 1;" ::: "memory");
        } else {
            if (kt > 0) __syncthreads();
            asm volatile("cp.async.wait_group 0;" ::: "memory");
        }
        __syncthreads();

        uint32_t kbU = dynb + (uint32_t)(buf * KSTGH) * 2;
        uint32_t vbU = dynb + (uint32_t)(2 * KSTGH + buf * VSTGH) * 2;

        // scores (already log2-scaled via Q): Q (128x128) @ K^T (128x64)
        float sf[8][4];
#pragma unroll
        for (int j = 0; j < 8; j++) { sf[j][0] = 0.f; sf[j][1] = 0.f; sf[j][2] = 0.f; sf[j][3] = 0.f; }
#pragma unroll
        for (int s = 0; s < 8; s++) {
#pragma unroll
            for (int jj = 0; jj < 8; jj += 2) {
                uint32_t addr = kbU + (uint32_t)(jj * 8 * KVP * 2 + kroff + s * 32);
                uint32_t b0, b1, b2, b3;
                ldsm4(b0, b1, b2, b3, addr);
                mma_f16(sf[jj],     qf[s], b0, b1);
                mma_f16(sf[jj + 1], qf[s], b2, b3);
            }
        }

        // causal mask only needed for the last two tiles of this q block
        if (kt >= 2 * qt) {
#pragma unroll
            for (int j = 0; j < 8; j++) {
                int cg = kt * ABN + j * 8 + 2 * t;
                if (cg     > row0) sf[j][0] = -1e30f;
                if (cg + 1 > row0) sf[j][1] = -1e30f;
                if (cg     > row1) sf[j][2] = -1e30f;
                if (cg + 1 > row1) sf[j][3] = -1e30f;
            }
        }

        // row max
        float mx0 = -1e30f, mx1 = -1e30f;
#pragma unroll
        for (int j = 0; j < 8; j++) {
            mx0 = fmaxf(mx0, fmaxf(sf[j][0], sf[j][1]));
            mx1 = fmaxf(mx1, fmaxf(sf[j][2], sf[j][3]));
        }
        mx0 = fmaxf(mx0, __shfl_xor_sync(0xffffffffu, mx0, 1));
        mx0 = fmaxf(mx0, __shfl_xor_sync(0xffffffffu, mx0, 2));
        mx1 = fmaxf(mx1, __shfl_xor_sync(0xffffffffu, mx1, 1));
        mx1 = fmaxf(mx1, __shfl_xor_sync(0xffffffffu, mx1, 2));

        float mn0 = fmaxf(m0, mx0), mn1 = fmaxf(m1, mx1);
        float al0 = exp2f(m0 - mn0), al1 = exp2f(m1 - mn1);

        // p = 2^(s - m), computed in packed half2 (MUFU halved); packed result
        // is directly the PV A-fragment.
        uint32_t p01[8], p23[8];
        float rs0 = 0.f, rs1 = 0.f;
#pragma unroll
        for (int j = 0; j < 8; j++) {
            uint32_t a01 = h2u(__floats2half2_rn(sf[j][0] - mn0, sf[j][1] - mn0));
            uint32_t a23 = h2u(__floats2half2_rn(sf[j][2] - mn1, sf[j][3] - mn1));
            uint32_t e01 = ex2_h2(a01);
            uint32_t e23 = ex2_h2(a23);
            p01[j] = e01; p23[j] = e23;
            float2 f01 = __half22float2(*reinterpret_cast<__half2*>(&e01));
            float2 f23 = __half22float2(*reinterpret_cast<__half2*>(&e23));
            rs0 += f01.x + f01.y;
            rs1 += f23.x + f23.y;
        }
        rs0 += __shfl_xor_sync(0xffffffffu, rs0, 1);
        rs0 += __shfl_xor_sync(0xffffffffu, rs0, 2);
        rs1 += __shfl_xor_sync(0xffffffffu, rs1, 1);
        rs1 += __shfl_xor_sync(0xffffffffu, rs1, 2);
        l0 = l0 * al0 + rs0;
        l1 = l1 * al1 + rs1;
        m0 = mn0; m1 = mn1;
#pragma unroll
        for (int j = 0; j < 16; j++) {
            of[j][0] *= al0; of[j][1] *= al0; of[j][2] *= al1; of[j][3] *= al1;
        }

        // PV: P (128x64) @ V (64x128); A from registers, B via ldmatrix.x4 on V^T
#pragma unroll
        for (int kb4 = 0; kb4 < 4; kb4++) {
            uint32_t a[4];
            a[0] = p01[2 * kb4];
            a[1] = p23[2 * kb4];
            a[2] = p01[2 * kb4 + 1];
            a[3] = p23[2 * kb4 + 1];
#pragma unroll
            for (int jj = 0; jj < 16; jj += 2) {
                uint32_t addr = vbU + (uint32_t)(jj * 8 * VPITCH * 2 + vroff + kb4 * 32);
                uint32_t b0, b1, b2, b3;
                ldsm4(b0, b1, b2, b3, addr);
                mma_f16(of[jj],     a, b0, b1);
                mma_f16(of[jj + 1], a, b2, b3);
            }
        }
        buf ^= 1;
    }

    float inv0 = 1.f / l0, inv1 = 1.f / l1;
#pragma unroll
    for (int j = 0; j < 16; j++) {
        int col = hoff + j * 8 + 2 * t;
        *reinterpret_cast<__half2*>(&g_ctxh[(size_t)row0 * HID + col]) =
            __floats2half2_rn(of[j][0] * inv0, of[j][1] * inv0);
        *reinterpret_cast<__half2*>(&g_ctxh[(size_t)row1 * HID + col]) =
            __floats2half2_rn(of[j][2] * inv1, of[j][3] * inv1);
    }
}

// ---------------- launch ----------------
extern "C" void kernel_launch(void* const* d_in, const int* in_sizes, int n_in,
                              void* d_out, int out_size) {
    const float* X  = (const float*)d_in[0];
    const float* Wq = (const float*)d_in[1];
    const float* Wk = (const float*)d_in[2];
    const float* Wv = (const float*)d_in[3];
    const float* Wo = (const float*)d_in[4];
    float* out = (float*)d_out;

    static int inited = 0;
    if (!inited) {
        cudaFuncSetAttribute(gemm_tn, cudaFuncAttributeMaxDynamicSharedMemorySize, GEMM_SMEM);
        cudaFuncSetAttribute(attn_kernel, cudaFuncAttributeMaxDynamicSharedMemorySize, ATT_SMEM);
        inited = 1;
    }

    tohalf_all<<<(NX + 4 * NW) / 256, 256>>>(X, Wq, Wk, Wv, Wo);
    rope_table<<<(SEQ * 64) / 256, 256>>>();

    // fused Q (pre-scaled), K (rope epilogue) and V^T in one launch
    dim3 gqkv(16, 32, 3);
    gemm_tn<<<gqkv, 256, GEMM_SMEM>>>(0, nullptr);

    attn_kernel<<<dim3(SEQ / ABM, NHEADS), 256, ATT_SMEM>>>();

    dim3 go(HID / GBN, SEQ / GBM, 1);       // output projection
    gemm_tn<<<go, 256, GEMM_SMEM>>>(2, out);
}

// round 13
// speedup vs baseline: 3.1491x; 1.0745x over previous
#include <cuda_runtime.h>
#include <cuda_fp16.h>
#include <cstdint>

#define SEQ 4096
#define HID 2048
#define NHEADS 16
#define HD 128

// Q pre-scale: (1/sqrt(128)) * log2(e)  -> softmax runs in exp2 domain
#define QSC 0.12751291181090523f

// ---------------- scratch (static device arrays; no allocation) ----------------
static __device__ __half g_Xh[SEQ * HID];
static __device__ __half g_Wqh[HID * HID];
static __device__ __half g_Wkh[HID * HID];
static __device__ __half g_Wvh[HID * HID];
static __device__ __half g_Woh[HID * HID];
static __device__ __half g_Qh[SEQ * HID];
static __device__ __half g_Kh[SEQ * HID];
static __device__ __half g_Vt[HID * SEQ];    // V TRANSPOSED: [dim][seq]
static __device__ __half g_ctxh[SEQ * HID];
static __device__ float  g_cos[SEQ * 64];
static __device__ float  g_sin[SEQ * 64];

// ---------------- helpers ----------------
__device__ __forceinline__ void mma_f16(float* c, const uint32_t* a, uint32_t b0, uint32_t b1) {
    asm volatile(
        "mma.sync.aligned.m16n8k16.row.col.f32.f16.f16.f32 "
        "{%0,%1,%2,%3}, {%4,%5,%6,%7}, {%8,%9}, {%0,%1,%2,%3};"
        : "+f"(c[0]), "+f"(c[1]), "+f"(c[2]), "+f"(c[3])
        : "r"(a[0]), "r"(a[1]), "r"(a[2]), "r"(a[3]), "r"(b0), "r"(b1));
}

__device__ __forceinline__ void ldsm4(uint32_t& r0, uint32_t& r1, uint32_t& r2, uint32_t& r3,
                                      uint32_t addr) {
    asm volatile("ldmatrix.sync.aligned.m8n8.x4.shared.b16 {%0,%1,%2,%3}, [%4];"
                 : "=r"(r0), "=r"(r1), "=r"(r2), "=r"(r3) : "r"(addr));
}

__device__ __forceinline__ void cpasync16(uint32_t dst, const void* src) {
    asm volatile("cp.async.cg.shared.global [%0], [%1], 16;" :: "r"(dst), "l"(src));
}
__device__ __forceinline__ void cpcommit() { asm volatile("cp.async.commit_group;"); }

__device__ __forceinline__ uint32_t h2u(__half2 h) {
    return *reinterpret_cast<uint32_t*>(&h);
}
__device__ __forceinline__ uint32_t ex2_h2(uint32_t x) {
    uint32_t r;
    asm("ex2.approx.f16x2 %0, %1;" : "=r"(r) : "r"(x));
    return r;
}

// ---------------- prep: fp32 -> fp16, all five tensors in one launch ----------
#define NX (SEQ * HID / 4)
#define NW (HID * HID / 4)
__global__ void tohalf_all(const float* __restrict__ X,  const float* __restrict__ Wq,
                           const float* __restrict__ Wk, const float* __restrict__ Wv,
                           const float* __restrict__ Wo) {
    int i = blockIdx.x * blockDim.x + threadIdx.x;
    const float* src; __half* dst; int off;
    if (i < NX)               { src = X;  dst = g_Xh;  off = i; }
    else if (i < NX + NW)     { src = Wq; dst = g_Wqh; off = i - NX; }
    else if (i < NX + 2 * NW) { src = Wk; dst = g_Wkh; off = i - NX - NW; }
    else if (i < NX + 3 * NW) { src = Wv; dst = g_Wvh; off = i - NX - 2 * NW; }
    else                      { src = Wo; dst = g_Woh; off = i - NX - 3 * NW; }
    float4 v = reinterpret_cast<const float4*>(src)[off];
    __half2* p = reinterpret_cast<__half2*>(&dst[4 * off]);
    p[0] = __floats2half2_rn(v.x, v.y);
    p[1] = __floats2half2_rn(v.z, v.w);
}

// ---------------- RoPE tables ----------------
__global__ void rope_table() {
    int idx = blockIdx.x * blockDim.x + threadIdx.x;
    if (idx >= SEQ * 64) return;
    int s = idx >> 6, j = idx & 63;
    double invf = exp(-(double)j * (9.210340371976184 / 64.0));  // 10000^(-j/64)
    float freq = (float)s * (float)invf;                          // fp32, like the ref
    g_cos[idx] = (float)cos((double)freq);
    g_sin[idx] = (float)sin((double)freq);
}

// ---------------- GEMM: C[M,N] = A[M,K] @ B[N,K]^T, fp16 mma, GBK=64, 3-stage --
// mode 0, z=0/1: Q/K projection, rope epilogue -> half (Q additionally * QSC)
// mode 0, z=2  : V^T = Wv @ X^T (block coords swapped), -> half g_Vt
// mode 2       : out = ctx @ Wo^T, -> fp32 extC
#define GBM 128
#define GBN 128
#define GBK 64
#define GST 3
#define APITCH 72                          // halves
#define AHALFS (GBM * APITCH)              // 9216
#define STGH (2 * AHALFS)                  // 18432 halves = 36864 B
#define GEMM_SMEM (GST * STGH * 2)         // 110592 B  (2 CTAs/SM)
#define CPITCH 132                         // fp32 epilogue staging pitch

__global__ void __launch_bounds__(256, 2) gemm_tn(int mode, float* __restrict__ extC) {
    extern __shared__ __half sm[];
    const __half* A; const __half* B;
    float* Cf = nullptr; __half* Ch = nullptr;
    int N;
    const int K = HID;
    int z = (int)blockIdx.z;
    int bm, bn;
    if (mode == 0) {
        if (z == 0)      { A = g_Xh;  B = g_Wqh; N = HID; }
        else if (z == 1) { A = g_Xh;  B = g_Wkh; N = HID; }
        else             { A = g_Wvh; B = g_Xh;  N = SEQ; Ch = g_Vt; }
        if (z == 2) { bm = blockIdx.x * GBM; bn = blockIdx.y * GBN; }   // 16 x 32
        else        { bm = blockIdx.y * GBM; bn = blockIdx.x * GBN; }   // 32 x 16
    } else {
        A = g_ctxh; B = g_Woh; N = HID; Cf = extC;
        bm = blockIdx.y * GBM; bn = blockIdx.x * GBN;
    }

    int tid = threadIdx.x;
    int lane = tid & 31, wid = tid >> 5;
    int wm = wid & 3, wn = wid >> 2;

    float c[2][8][4];
#pragma unroll
    for (int im = 0; im < 2; im++)
#pragma unroll
        for (int jn = 0; jn < 8; jn++)
#pragma unroll
            for (int q = 0; q < 4; q++) c[im][jn][q] = 0.f;

    const __half* Abase = A + (size_t)bm * K;
    const __half* Bbase = B + (size_t)bn * K;

    uint32_t smb = (uint32_t)__cvta_generic_to_shared(sm);

    int lr = tid >> 3, lc8 = tid & 7;

    // ldmatrix lane address components
    int lrow = lane & 7;
    int arow = ((lane >> 3) & 1) * 8 + lrow;   // A: m0/m1 = row-halves, m2/m3 = k-hi
    int acol = (lane >> 4) * 8;
    int brow = (lane >> 4) * 8 + lrow;         // B: m0/m1 = k-halves of jj, m2/m3 = jj+1
    int bcol = ((lane >> 3) & 1) * 8;

    auto load_tile = [&](int s, int kt) {
        int koff = kt * GBK + lc8 * 8;
        uint32_t sa = smb + (uint32_t)(s * STGH) * 2;
        uint32_t sb = sa + AHALFS * 2;
        uint32_t doff = (uint32_t)(lr * APITCH + lc8 * 8) * 2;
#pragma unroll
        for (int i = 0; i < 4; i++) {
            int r = lr + 32 * i;
            cpasync16(sa + doff + (uint32_t)(32 * i * APITCH) * 2, Abase + (size_t)r * K + koff);
            cpasync16(sb + doff + (uint32_t)(32 * i * APITCH) * 2, Bbase + (size_t)r * K + koff);
        }
    };

    const int NT = K / GBK;  // 32
    load_tile(0, 0); cpcommit();
    load_tile(1, 1); cpcommit();

    int g = lane >> 2, t = lane & 3;
    int stg = 0;

    for (int kt = 0; kt < NT; kt++) {
        if (kt + 2 < NT) {
            if (kt > 0) __syncthreads();
            int ns = stg + 2; if (ns >= GST) ns -= GST;
            load_tile(ns, kt + 2);
            cpcommit();
            asm volatile("cp.async.wait_group 2;" ::: "memory");
        } else {
            if (kt > 0) __syncthreads();
            asm volatile("cp.async.wait_group 0;" ::: "memory");
        }
        __syncthreads();

        uint32_t saU = smb + (uint32_t)(stg * STGH) * 2;
        uint32_t sbU = saU + AHALFS * 2;
#pragma unroll
        for (int ks = 0; ks < 4; ks++) {
            int k0 = ks * 16;
            uint32_t a[2][4], b[8][2];
#pragma unroll
            for (int im = 0; im < 2; im++) {
                uint32_t addr = saU +
                    (uint32_t)(((wm * 32 + im * 16 + arow) * APITCH + k0 + acol) * 2);
                ldsm4(a[im][0], a[im][1], a[im][2], a[im][3], addr);
            }
#pragma unroll
            for (int jj = 0; jj < 8; jj += 2) {
                uint32_t addr = sbU +
                    (uint32_t)(((wn * 64 + jj * 8 + brow) * APITCH + k0 + bcol) * 2);
                ldsm4(b[jj][0], b[jj][1], b[jj + 1][0], b[jj + 1][1], addr);
            }
#pragma unroll
            for (int im = 0; im < 2; im++)
#pragma unroll
                for (int jn = 0; jn < 8; jn++)
                    mma_f16(c[im][jn], a[im], b[jn][0], b[jn][1]);
        }
        if (++stg == GST) stg = 0;
    }

    if (mode == 0 && z < 2) {
        // ---- fused RoPE epilogue: stage fp32 C in smem, pair (i, i+64), write half
        __syncthreads();                       // mainloop smem reads done
        float* cs = reinterpret_cast<float*>(sm);
#pragma unroll
        for (int im = 0; im < 2; im++)
#pragma unroll
            for (int jn = 0; jn < 8; jn++) {
                int r = wm * 32 + im * 16 + g;
                int lc = wn * 64 + jn * 8 + 2 * t;
                cs[r * CPITCH + lc]           = c[im][jn][0];
                cs[r * CPITCH + lc + 1]       = c[im][jn][1];
                cs[(r + 8) * CPITCH + lc]     = c[im][jn][2];
                cs[(r + 8) * CPITCH + lc + 1] = c[im][jn][3];
            }
        __syncthreads();
        __half* dst = (z == 0) ? g_Qh : g_Kh;
        float qs = (z == 0) ? QSC : 1.0f;      // Q carries softmax scale (log2 domain)
        int r = tid >> 1;
        int i0 = (tid & 1) * 32;
        int s = bm + r;
        const float* crow = cs + r * CPITCH;
#pragma unroll
        for (int ii = 0; ii < 32; ii += 4) {
            int i = i0 + ii;
            float4 x1 = *reinterpret_cast<const float4*>(&crow[i]);
            float4 x2 = *reinterpret_cast<const float4*>(&crow[i + 64]);
            float4 co = *reinterpret_cast<const float4*>(&g_cos[s * 64 + i]);
            float4 si = *reinterpret_cast<const float4*>(&g_sin[s * 64 + i]);
            __half2* d1 = reinterpret_cast<__half2*>(&dst[(size_t)s * HID + bn + i]);
            __half2* d2 = reinterpret_cast<__half2*>(&dst[(size_t)s * HID + bn + 64 + i]);
            d1[0] = __floats2half2_rn((x1.x * co.x - x2.x * si.x) * qs,
                                      (x1.y * co.y - x2.y * si.y) * qs);
            d1[1] = __floats2half2_rn((x1.z * co.z - x2.z * si.z) * qs,
                                      (x1.w * co.w - x2.w * si.w) * qs);
            d2[0] = __floats2half2_rn((x2.x * co.x + x1.x * si.x) * qs,
                                      (x2.y * co.y + x1.y * si.y) * qs);
            d2[1] = __floats2half2_rn((x2.z * co.z + x1.z * si.z) * qs,
                                      (x2.w * co.w + x1.w * si.w) * qs);
        }
        return;
    }

#pragma unroll
    for (int im = 0; im < 2; im++) {
#pragma unroll
        for (int jn = 0; jn < 8; jn++) {
            int r = bm + wm * 32 + im * 16 + g;
            int col = bn + wn * 64 + jn * 8 + 2 * t;
            if (Ch) {
                *reinterpret_cast<__half2*>(&Ch[(size_t)r * N + col]) =
                    __floats2half2_rn(c[im][jn][0], c[im][jn][1]);
                *reinterpret_cast<__half2*>(&Ch[(size_t)(r + 8) * N + col]) =
                    __floats2half2_rn(c[im][jn][2], c[im][jn][3]);
            } else {
                *reinterpret_cast<float2*>(&Cf[(size_t)r * N + col]) =
                    make_float2(c[im][jn][0], c[im][jn][1]);
                *reinterpret_cast<float2*>(&Cf[(size_t)(r + 8) * N + col]) =
                    make_float2(c[im][jn][2], c[im][jn][3]);
            }
        }
    }
}

// ---------------- flash attention (causal), fp16 mma, exp2-domain softmax -----
#define ABM 128
#define ABN 64
#define KVP 136                            // K tile pitch (halves)
#define KSTGH (ABN * KVP)                  // 8704 halves
#define VPITCH 72                          // V^T tile pitch (halves)
#define VSTGH (HD * VPITCH)                // 9216 halves
#define ATT_SMEM ((2 * KSTGH + 2 * VSTGH) * 2)  // 71680 B dynamic

__global__ void __launch_bounds__(256) attn_kernel() {
    extern __shared__ __half kvdyn[];      // [K0, K1, V0, V1]

    int tid = threadIdx.x, lane = tid & 31, wid = tid >> 5;
    int g = lane >> 2, t = lane & 3;
    int qt = (int)(gridDim.x - 1 - blockIdx.x);   // heavy tiles first
    int h = blockIdx.y;
    int hoff = h * HD;
    int qrow = qt * ABM + wid * 16;
    int row0 = qrow + g, row1 = row0 + 8;

    uint32_t dynb = (uint32_t)__cvta_generic_to_shared(kvdyn);

    // ldmatrix lane address components
    int lrow = lane & 7, lm = lane >> 3;
    int kroff = ((((lm >> 1) * 8 + lrow) * KVP) + (lm & 1) * 8) * 2;     // bytes
    int vroff = ((((lm >> 1) * 8 + lrow) * VPITCH) + (lm & 1) * 8) * 2;  // bytes

    // Q fragments (pre-scaled by QSC): 8 k16-steps over HD=128
    uint32_t qf[8][4];
#pragma unroll
    for (int s = 0; s < 8; s++) {
        int cb = hoff + s * 16 + 2 * t;
        qf[s][0] = *reinterpret_cast<const uint32_t*>(&g_Qh[(size_t)row0 * HID + cb]);
        qf[s][1] = *reinterpret_cast<const uint32_t*>(&g_Qh[(size_t)row1 * HID + cb]);
        qf[s][2] = *reinterpret_cast<const uint32_t*>(&g_Qh[(size_t)row0 * HID + cb + 8]);
        qf[s][3] = *reinterpret_cast<const uint32_t*>(&g_Qh[(size_t)row1 * HID + cb + 8]);
    }

    float of[16][4];
#pragma unroll
    for (int j = 0; j < 16; j++) { of[j][0] = 0.f; of[j][1] = 0.f; of[j][2] = 0.f; of[j][3] = 0.f; }
    float m0 = -1e30f, m1 = -1e30f, l0 = 0.f, l1 = 0.f;   // l: per-lane partials

    auto loadKV = [&](int b, int kt) {
        const __half* Kg = g_Kh + (size_t)(kt * ABN) * HID + hoff;
        const __half* Vg = g_Vt + (size_t)hoff * SEQ + kt * ABN;
        uint32_t kb = dynb + (uint32_t)(b * KSTGH) * 2;
        uint32_t vb = dynb + (uint32_t)(2 * KSTGH + b * VSTGH) * 2;
#pragma unroll
        for (int j = 0; j < 4; j++) {       // K: 64 rows x 16 chunks
            int cidx = tid + 256 * j;
            int rr = cidx >> 4, c = cidx & 15;
            cpasync16(kb + (uint32_t)(rr * KVP + c * 8) * 2, Kg + (size_t)rr * HID + c * 8);
        }
#pragma unroll
        for (int j = 0; j < 4; j++) {       // V^T: 128 rows x 8 chunks
            int cidx = tid + 256 * j;
            int rr = cidx >> 3, c = cidx & 7;
            cpasync16(vb + (uint32_t)(rr * VPITCH + c * 8) * 2, Vg + (size_t)rr * SEQ + c * 8);
        }
    };

    int ktmax = 2 * qt + 1;
    loadKV(0, 0);
    cpcommit();
    int buf = 0;

    for (int kt = 0; kt <= ktmax; kt++) {
        if (kt < ktmax) {
            if (kt > 0) __syncthreads();
            loadKV(buf ^ 1, kt + 1);
            cpcommit();
            asm volatile("cp.async.wait_group 1;" ::: "memory");
        } else {
            if (kt > 0) __syncthreads();
            asm volatile("cp.async.wait_group 0;" ::: "memory");
        }
        __syncthreads();

        uint32_t kbU = dynb + (uint32_t)(buf * KSTGH) * 2;
        uint32_t vbU = dynb + (uint32_t)(2 * KSTGH + buf * VSTGH) * 2;

        // scores (already log2-scaled via Q): Q (128x128) @ K^T (128x64)
        float sf[8][4];
#pragma unroll
        for (int j = 0; j < 8; j++) { sf[j][0] = 0.f; sf[j][1] = 0.f; sf[j][2] = 0.f; sf[j][3] = 0.f; }
#pragma unroll
        for (int s = 0; s < 8; s++) {
#pragma unroll
            for (int jj = 0; jj < 8; jj += 2) {
                uint32_t addr = kbU + (uint32_t)(jj * 8 * KVP * 2 + kroff + s * 32);
                uint32_t b0, b1, b2, b3;
                ldsm4(b0, b1, b2, b3, addr);
                mma_f16(sf[jj],     qf[s], b0, b1);
                mma_f16(sf[jj + 1], qf[s], b2, b3);
            }
        }

        // causal mask only needed for the last two tiles of this q block
        if (kt >= 2 * qt) {
#pragma unroll
            for (int j = 0; j < 8; j++) {
                int cg = kt * ABN + j * 8 + 2 * t;
                if (cg     > row0) sf[j][0] = -1e30f;
                if (cg + 1 > row0) sf[j][1] = -1e30f;
                if (cg     > row1) sf[j][2] = -1e30f;
                if (cg + 1 > row1) sf[j][3] = -1e30f;
            }
        }

        // row max
        float mx0 = -1e30f, mx1 = -1e30f;
#pragma unroll
        for (int j = 0; j < 8; j++) {
            mx0 = fmaxf(mx0, fmaxf(sf[j][0], sf[j][1]));
            mx1 = fmaxf(mx1, fmaxf(sf[j][2], sf[j][3]));
        }
        mx0 = fmaxf(mx0, __shfl_xor_sync(0xffffffffu, mx0, 1));
        mx0 = fmaxf(mx0, __shfl_xor_sync(0xffffffffu, mx0, 2));
        mx1 = fmaxf(mx1, __shfl_xor_sync(0xffffffffu, mx1, 1));
        mx1 = fmaxf(mx1, __shfl_xor_sync(0xffffffffu, mx1, 2));

        float mn0 = fmaxf(m0, mx0), mn1 = fmaxf(m1, mx1);
        float al0 = exp2f(m0 - mn0), al1 = exp2f(m1 - mn1);

        // p = 2^(s - m) in packed half2; packed result is directly the PV A-frag.
        // l kept as per-lane partial sums (reduced once after the loop).
        uint32_t p01[8], p23[8];
        float rs0 = 0.f, rs1 = 0.f;
#pragma unroll
        for (int j = 0; j < 8; j++) {
            uint32_t a01 = h2u(__floats2half2_rn(sf[j][0] - mn0, sf[j][1] - mn0));
            uint32_t a23 = h2u(__floats2half2_rn(sf[j][2] - mn1, sf[j][3] - mn1));
            uint32_t e01 = ex2_h2(a01);
            uint32_t e23 = ex2_h2(a23);
            p01[j] = e01; p23[j] = e23;
            float2 f01 = __half22float2(*reinterpret_cast<__half2*>(&e01));
            float2 f23 = __half22float2(*reinterpret_cast<__half2*>(&e23));
            rs0 += f01.x + f01.y;
            rs1 += f23.x + f23.y;
        }
        l0 = l0 * al0 + rs0;
        l1 = l1 * al1 + rs1;
        m0 = mn0; m1 = mn1;
#pragma unroll
        for (int j = 0; j < 16; j++) {
            of[j][0] *= al0; of[j][1] *= al0; of[j][2] *= al1; of[j][3] *= al1;
        }

        // PV: P (128x64) @ V (64x128); A from registers, B via ldmatrix.x4 on V^T
#pragma unroll
        for (int kb4 = 0; kb4 < 4; kb4++) {
            uint32_t a[4];
            a[0] = p01[2 * kb4];
            a[1] = p23[2 * kb4];
            a[2] = p01[2 * kb4 + 1];
            a[3] = p23[2 * kb4 + 1];
#pragma unroll
            for (int jj = 0; jj < 16; jj += 2) {
                uint32_t addr = vbU + (uint32_t)(jj * 8 * VPITCH * 2 + vroff + kb4 * 32);
                uint32_t b0, b1, b2, b3;
                ldsm4(b0, b1, b2, b3, addr);
                mma_f16(of[jj],     a, b0, b1);
                mma_f16(of[jj + 1], a, b2, b3);
            }
        }
        buf ^= 1;
    }

    // final per-lane l reduction (moved out of the main loop)
    l0 += __shfl_xor_sync(0xffffffffu, l0, 1);
    l0 += __shfl_xor_sync(0xffffffffu, l0, 2);
    l1 += __shfl_xor_sync(0xffffffffu, l1, 1);
    l1 += __shfl_xor_sync(0xffffffffu, l1, 2);

    float inv0 = 1.f / l0, inv1 = 1.f / l1;
#pragma unroll
    for (int j = 0; j < 16; j++) {
        int col = hoff + j * 8 + 2 * t;
        *reinterpret_cast<__half2*>(&g_ctxh[(size_t)row0 * HID + col]) =
            __floats2half2_rn(of[j][0] * inv0, of[j][1] * inv0);
        *reinterpret_cast<__half2*>(&g_ctxh[(size_t)row1 * HID + col]) =
            __floats2half2_rn(of[j][2] * inv1, of[j][3] * inv1);
    }
}

// ---------------- launch ----------------
extern "C" void kernel_launch(void* const* d_in, const int* in_sizes, int n_in,
                              void* d_out, int out_size) {
    const float* X  = (const float*)d_in[0];
    const float* Wq = (const float*)d_in[1];
    const float* Wk = (const float*)d_in[2];
    const float* Wv = (const float*)d_in[3];
    const float* Wo = (const float*)d_in[4];
    float* out = (float*)d_out;

    static int inited = 0;
    if (!inited) {
        cudaFuncSetAttribute(gemm_tn, cudaFuncAttributeMaxDynamicSharedMemorySize, GEMM_SMEM);
        cudaFuncSetAttribute(attn_kernel, cudaFuncAttributeMaxDynamicSharedMemorySize, ATT_SMEM);
        inited = 1;
    }

    tohalf_all<<<(NX + 4 * NW) / 256, 256>>>(X, Wq, Wk, Wv, Wo);
    rope_table<<<(SEQ * 64) / 256, 256>>>();

    // fused Q (pre-scaled), K (rope epilogue) and V^T in one launch
    dim3 gqkv(16, 32, 3);
    gemm_tn<<<gqkv, 256, GEMM_SMEM>>>(0, nullptr);

    attn_kernel<<<dim3(SEQ / ABM, NHEADS), 256, ATT_SMEM>>>();

    dim3 go(HID / GBN, SEQ / GBM, 1);       // output projection
    gemm_tn<<<go, 256, GEMM_SMEM>>>(2, out);
}